// round 1
// baseline (speedup 1.0000x reference)
#include <cuda_runtime.h>

#define S 2048
#define D 64
#define BATCH 16

typedef unsigned long long ull;

// ---------- packed f32x2 helpers (Blackwell FFMA2 path) ----------
__device__ __forceinline__ ull dup2(float a) {
    ull r;
    asm("mov.b64 %0, {%1, %1};" : "=l"(r) : "f"(a));
    return r;
}
__device__ __forceinline__ void ffma2(ull &acc, ull a, ull b) {
    asm("fma.rn.f32x2 %0, %1, %2, %0;" : "+l"(acc) : "l"(a), "l"(b));
}
__device__ __forceinline__ void unpack2(ull v, float &a, float &b) {
    asm("mov.b64 {%0, %1}, %2;" : "=f"(a), "=f"(b) : "l"(v));
}

// ============================================================================
// Kernel 1: masked scaled scores.
//   attn[b,s,t] = (q[b,s,:] . k[b,t,:]) * 0.125   (exact pow2 scale == q/8 first)
//   masked (mask==0) -> -1e9
// Tile 128x128, K=64 done in two 32-slices. 256 threads, 8x8 per thread
// computed as 4 row-pairs x 8 cols of FFMA2.
// ============================================================================
__global__ void __launch_bounds__(256) scores_kernel(
    const float* __restrict__ q, const float* __restrict__ k,
    const int* __restrict__ mask, float* __restrict__ attn)
{
    __shared__ float qs[32][132];   // [d][row], pitch 132 -> conflict-free, 16B aligned
    __shared__ float ks[32][132];   // [d][col]

    const int b    = blockIdx.z;
    const int row0 = blockIdx.y * 128;
    const int col0 = blockIdx.x * 128;

    const float* qb = q + ((size_t)b * S + row0) * D;
    const float* kb = k + ((size_t)b * S + col0) * D;

    const int tid = threadIdx.x;
    const int tx  = tid & 15;      // col group (x8)
    const int ty  = tid >> 4;      // row group (x8)

    ull acc[4][8];
#pragma unroll
    for (int i = 0; i < 4; ++i)
#pragma unroll
        for (int j = 0; j < 8; ++j) acc[i][j] = 0ULL;

#pragma unroll
    for (int h = 0; h < 2; ++h) {
        // cooperative transposed load: 128 rows x 32 d each for q and k
        const int d4    = (tid & 7) * 4;
        const int rbase = tid >> 3;
#pragma unroll
        for (int p = 0; p < 4; ++p) {
            const int r = rbase + p * 32;
            float4 va = *(const float4*)&qb[(size_t)r * D + h * 32 + d4];
            qs[d4 + 0][r] = va.x; qs[d4 + 1][r] = va.y;
            qs[d4 + 2][r] = va.z; qs[d4 + 3][r] = va.w;
            float4 vb = *(const float4*)&kb[(size_t)r * D + h * 32 + d4];
            ks[d4 + 0][r] = vb.x; ks[d4 + 1][r] = vb.y;
            ks[d4 + 2][r] = vb.z; ks[d4 + 3][r] = vb.w;
        }
        __syncthreads();

#pragma unroll 8
        for (int d = 0; d < 32; ++d) {
            float4 a0 = *(const float4*)&qs[d][ty * 8];
            float4 a1 = *(const float4*)&qs[d][ty * 8 + 4];
            float4 b0 = *(const float4*)&ks[d][tx * 8];
            float4 b1 = *(const float4*)&ks[d][tx * 8 + 4];
            ull A[4];
            A[0] = ((const ull*)&a0)[0]; A[1] = ((const ull*)&a0)[1];
            A[2] = ((const ull*)&a1)[0]; A[3] = ((const ull*)&a1)[1];
            ull Bd[8] = { dup2(b0.x), dup2(b0.y), dup2(b0.z), dup2(b0.w),
                          dup2(b1.x), dup2(b1.y), dup2(b1.z), dup2(b1.w) };
#pragma unroll
            for (int i = 0; i < 4; ++i)
#pragma unroll
                for (int j = 0; j < 8; ++j)
                    ffma2(acc[i][j], A[i], Bd[j]);
        }
        __syncthreads();
    }

    // epilogue: scale, mask, store
#pragma unroll
    for (int i = 0; i < 4; ++i) {
        float lov[8], hiv[8];
#pragma unroll
        for (int j = 0; j < 8; ++j) unpack2(acc[i][j], lov[j], hiv[j]);
#pragma unroll
        for (int half = 0; half < 2; ++half) {
            const int r = row0 + ty * 8 + i * 2 + half;
            const float* src = half ? hiv : lov;
            float* dst      = attn + ((size_t)b * S + r) * S + col0 + tx * 8;
            const int* m    = mask + (size_t)r * S + col0 + tx * 8;
            float vals[8];
#pragma unroll
            for (int j = 0; j < 8; ++j) {
                float sv = src[j] * 0.125f;
                vals[j] = (m[j] == 0) ? -1e9f : sv;
            }
            *(float4*)&dst[0] = make_float4(vals[0], vals[1], vals[2], vals[3]);
            *(float4*)&dst[4] = make_float4(vals[4], vals[5], vals[6], vals[7]);
        }
    }
}

// ============================================================================
// Kernel 2: row softmax, in place. One block (256 threads) per row of 2048.
// ============================================================================
__global__ void __launch_bounds__(256) softmax_kernel(float* __restrict__ attn)
{
    const size_t row = (size_t)blockIdx.y * S + blockIdx.x;   // b*S + s
    float* p = attn + row * S;
    const int tid = threadIdx.x;

    __shared__ float red[16];

    float4 v0 = *(const float4*)&p[tid * 4];
    float4 v1 = *(const float4*)&p[1024 + tid * 4];

    float m = fmaxf(fmaxf(fmaxf(v0.x, v0.y), fmaxf(v0.z, v0.w)),
                    fmaxf(fmaxf(v1.x, v1.y), fmaxf(v1.z, v1.w)));
#pragma unroll
    for (int o = 16; o > 0; o >>= 1)
        m = fmaxf(m, __shfl_xor_sync(0xffffffffu, m, o));
    if ((tid & 31) == 0) red[tid >> 5] = m;
    __syncthreads();
    m = red[0];
#pragma unroll
    for (int i = 1; i < 8; ++i) m = fmaxf(m, red[i]);

    float e[8];
    e[0] = __expf(v0.x - m); e[1] = __expf(v0.y - m);
    e[2] = __expf(v0.z - m); e[3] = __expf(v0.w - m);
    e[4] = __expf(v1.x - m); e[5] = __expf(v1.y - m);
    e[6] = __expf(v1.z - m); e[7] = __expf(v1.w - m);

    float s = ((e[0] + e[1]) + (e[2] + e[3])) + ((e[4] + e[5]) + (e[6] + e[7]));
#pragma unroll
    for (int o = 16; o > 0; o >>= 1)
        s += __shfl_xor_sync(0xffffffffu, s, o);
    if ((tid & 31) == 0) red[8 + (tid >> 5)] = s;
    __syncthreads();
    s = red[8];
#pragma unroll
    for (int i = 1; i < 8; ++i) s += red[8 + i];

    const float inv = 1.0f / s;
    *(float4*)&p[tid * 4]        = make_float4(e[0] * inv, e[1] * inv, e[2] * inv, e[3] * inv);
    *(float4*)&p[1024 + tid * 4] = make_float4(e[4] * inv, e[5] * inv, e[6] * inv, e[7] * inv);
}

// ============================================================================
// Kernel 3: out[b,s,d] = sum_t attn[b,s,t] * v[b,t,d].
// Tile M=128 rows x N=64 cols, K-tiles of 32. 128 threads, 8x8 per thread.
// ============================================================================
__global__ void __launch_bounds__(128) pv_kernel(
    const float* __restrict__ attn, const float* __restrict__ v,
    float* __restrict__ out)
{
    __shared__ float ps[32][132];   // [t][row]  (transposed attn tile)
    __shared__ float vs[32][68];    // [t][d]

    const int b    = blockIdx.y;
    const int row0 = blockIdx.x * 128;

    const float* pb = attn + ((size_t)b * S + row0) * S;
    const float* vb = v + (size_t)b * S * D;

    const int tid = threadIdx.x;
    const int tx  = tid & 7;        // d group (x8)
    const int ty  = tid >> 3;       // row group (x8)

    ull acc[4][8];
#pragma unroll
    for (int i = 0; i < 4; ++i)
#pragma unroll
        for (int j = 0; j < 8; ++j) acc[i][j] = 0ULL;

    for (int t0 = 0; t0 < S; t0 += 32) {
        // load attn tile 128x32, transposed into ps[t][row]
        {
            const int t4 = (tid & 7) * 4;
            const int rb = tid >> 3;
#pragma unroll
            for (int pss = 0; pss < 8; ++pss) {
                const int r = rb + pss * 16;
                float4 a = *(const float4*)&pb[(size_t)r * S + t0 + t4];
                ps[t4 + 0][r] = a.x; ps[t4 + 1][r] = a.y;
                ps[t4 + 2][r] = a.z; ps[t4 + 3][r] = a.w;
            }
        }
        // load v tile 32x64
        {
            const int dd = (tid & 15) * 4;
            const int tt = tid >> 4;
#pragma unroll
            for (int pss = 0; pss < 4; ++pss) {
                const int t = tt + pss * 8;
                *(float4*)&vs[t][dd] = *(const float4*)&vb[(size_t)(t0 + t) * D + dd];
            }
        }
        __syncthreads();

#pragma unroll 8
        for (int t = 0; t < 32; ++t) {
            float4 a0 = *(const float4*)&ps[t][ty * 8];
            float4 a1 = *(const float4*)&ps[t][ty * 8 + 4];
            float4 b0 = *(const float4*)&vs[t][tx * 8];
            float4 b1 = *(const float4*)&vs[t][tx * 8 + 4];
            ull A[4];
            A[0] = ((const ull*)&a0)[0]; A[1] = ((const ull*)&a0)[1];
            A[2] = ((const ull*)&a1)[0]; A[3] = ((const ull*)&a1)[1];
            ull Bd[8] = { dup2(b0.x), dup2(b0.y), dup2(b0.z), dup2(b0.w),
                          dup2(b1.x), dup2(b1.y), dup2(b1.z), dup2(b1.w) };
#pragma unroll
            for (int i = 0; i < 4; ++i)
#pragma unroll
                for (int j = 0; j < 8; ++j)
                    ffma2(acc[i][j], A[i], Bd[j]);
        }
        __syncthreads();
    }

#pragma unroll
    for (int i = 0; i < 4; ++i) {
        float lov[8], hiv[8];
#pragma unroll
        for (int j = 0; j < 8; ++j) unpack2(acc[i][j], lov[j], hiv[j]);
#pragma unroll
        for (int half = 0; half < 2; ++half) {
            const int r = row0 + ty * 8 + i * 2 + half;
            const float* src = half ? hiv : lov;
            float* dst = out + ((size_t)b * S + r) * D + tx * 8;
            *(float4*)&dst[0] = make_float4(src[0], src[1], src[2], src[3]);
            *(float4*)&dst[4] = make_float4(src[4], src[5], src[6], src[7]);
        }
    }
}

// ============================================================================
extern "C" void kernel_launch(void* const* d_in, const int* in_sizes, int n_in,
                              void* d_out, int out_size)
{
    const float* q    = (const float*)d_in[0];
    const float* k    = (const float*)d_in[1];
    const float* v    = (const float*)d_in[2];
    const int*   mask = (const int*)d_in[3];

    float* out  = (float*)d_out;                         // [B,S,D]
    float* attn = out + (size_t)BATCH * S * D;           // [B,S,S]

    dim3 g1(S / 128, S / 128, BATCH);
    scores_kernel<<<g1, 256>>>(q, k, mask, attn);

    dim3 g2(S, BATCH);
    softmax_kernel<<<g2, 256>>>(attn);

    dim3 g3(S / 128, BATCH);
    pv_kernel<<<g3, 128>>>(attn, v, out);
}

// round 3
// speedup vs baseline: 1.6889x; 1.6889x over previous
#include <cuda_runtime.h>
#include <cuda_bf16.h>
#include <cstdint>

#define SEQ   2048
#define HD    64
#define BATCH 16

// ---------------------------------------------------------------------------
// device scratch
// ---------------------------------------------------------------------------
__device__ __nv_bfloat16 g_qhi[BATCH * SEQ * HD];
__device__ __nv_bfloat16 g_qlo[BATCH * SEQ * HD];
__device__ __nv_bfloat16 g_khi[BATCH * SEQ * HD];
__device__ __nv_bfloat16 g_klo[BATCH * SEQ * HD];
__device__ __nv_bfloat16 g_vhi[BATCH * HD * SEQ];   // transposed: [b][d][t]
__device__ __nv_bfloat16 g_vlo[BATCH * HD * SEQ];

// ---------------------------------------------------------------------------
// helpers
// ---------------------------------------------------------------------------
__device__ __forceinline__ uint32_t smem_u32(const void* p) {
    uint32_t a;
    asm("{ .reg .u64 t; cvta.to.shared.u64 t, %1; cvt.u32.u64 %0, t; }" : "=r"(a) : "l"(p));
    return a;
}
// pack two floats to bf16x2 (lo = a, hi = b -> memory order [a, b])
__device__ __forceinline__ uint32_t bfpack(float a, float b) {
    uint32_t r;
    asm("cvt.rn.bf16x2.f32 %0, %1, %2;" : "=r"(r) : "f"(b), "f"(a));
    return r;
}
__device__ __forceinline__ void split2(float x0, float x1, uint32_t& h, uint32_t& l) {
    h = bfpack(x0, x1);
    float h0 = __uint_as_float(h << 16);
    float h1 = __uint_as_float(h & 0xffff0000u);
    l = bfpack(x0 - h0, x1 - h1);
}
__device__ __forceinline__ void ldsm_x4(uint32_t& r0, uint32_t& r1, uint32_t& r2,
                                        uint32_t& r3, uint32_t addr) {
    asm volatile("ldmatrix.sync.aligned.m8n8.x4.shared.b16 {%0,%1,%2,%3}, [%4];"
                 : "=r"(r0), "=r"(r1), "=r"(r2), "=r"(r3) : "r"(addr));
}
__device__ __forceinline__ void mma16816(float* c, const uint32_t* a, const uint32_t* b) {
    asm volatile("mma.sync.aligned.m16n8k16.row.col.f32.bf16.bf16.f32 "
                 "{%0,%1,%2,%3}, {%4,%5,%6,%7}, {%8,%9}, {%0,%1,%2,%3};"
                 : "+f"(c[0]), "+f"(c[1]), "+f"(c[2]), "+f"(c[3])
                 : "r"(a[0]), "r"(a[1]), "r"(a[2]), "r"(a[3]), "r"(b[0]), "r"(b[1]));
}

// ===========================================================================
// split q/k into bf16 hi/lo
// ===========================================================================
__global__ void __launch_bounds__(256) split_qk_kernel(const float4* __restrict__ src, int isK)
{
    uint2* hi = (uint2*)(isK ? g_khi : g_qhi);
    uint2* lo = (uint2*)(isK ? g_klo : g_qlo);
    const int n = BATCH * SEQ * HD / 4;
    const int stride = gridDim.x * blockDim.x;
    for (int c = blockIdx.x * blockDim.x + threadIdx.x; c < n; c += stride) {
        float4 x = src[c];
        uint32_t h01, l01, h23, l23;
        split2(x.x, x.y, h01, l01);
        split2(x.z, x.w, h23, l23);
        hi[c] = make_uint2(h01, h23);
        lo[c] = make_uint2(l01, l23);
    }
}

// ===========================================================================
// transpose + split v: vT[b][d][t]
// ===========================================================================
__global__ void __launch_bounds__(256) split_v_kernel(const float* __restrict__ v)
{
    __shared__ float sm[64][129];
    const int tid = threadIdx.x;
    const int b = blockIdx.y, t0 = blockIdx.x * 128;
    const float* vb = v + (size_t)b * SEQ * HD;

#pragma unroll
    for (int i = 0; i < 8; ++i) {
        int chunk = tid + i * 256;
        int t = chunk >> 4, d4 = (chunk & 15) * 4;
        float4 x = *(const float4*)(vb + (size_t)(t0 + t) * HD + d4);
        sm[d4 + 0][t] = x.x; sm[d4 + 1][t] = x.y;
        sm[d4 + 2][t] = x.z; sm[d4 + 3][t] = x.w;
    }
    __syncthreads();

    const int r = tid >> 2, tb = (tid & 3) * 32;
    size_t obase = ((size_t)(b * 64 + r)) * SEQ + t0 + tb;
#pragma unroll
    for (int seg = 0; seg < 4; ++seg) {
        uint32_t h[4], l[4];
#pragma unroll
        for (int j = 0; j < 4; ++j) {
            float x0 = sm[r][tb + seg * 8 + j * 2];
            float x1 = sm[r][tb + seg * 8 + j * 2 + 1];
            split2(x0, x1, h[j], l[j]);
        }
        *(uint4*)(g_vhi + obase + seg * 8) = make_uint4(h[0], h[1], h[2], h[3]);
        *(uint4*)(g_vlo + obase + seg * 8) = make_uint4(l[0], l[1], l[2], l[3]);
    }
}

// ===========================================================================
// scores: C[128x128] = (Qhi+Qlo)(Khi+Klo)^T via 3-term bf16 mma.sync
// smem: 4 tiles of 128 rows x 64 bf16 (128B rows, XOR-swizzled 16B chunks)
// ===========================================================================
__global__ void __launch_bounds__(256) scores_mma_kernel(
    const int* __restrict__ mask, float* __restrict__ attn)
{
    extern __shared__ char smem[];
    constexpr int AHI = 0, ALO = 16384, BHI = 32768, BLO = 49152;
    const uint32_t sb = smem_u32(smem);
    const int tid = threadIdx.x, wid = tid >> 5, l = tid & 31;
    const int b = blockIdx.z, row0 = blockIdx.y * 128, col0 = blockIdx.x * 128;

    // cooperative loads: 4 tiles x 1024 16B-chunks
    {
        const __nv_bfloat16* srcs[4] = {
            g_qhi + ((size_t)(b * SEQ) + row0) * HD,
            g_qlo + ((size_t)(b * SEQ) + row0) * HD,
            g_khi + ((size_t)(b * SEQ) + col0) * HD,
            g_klo + ((size_t)(b * SEQ) + col0) * HD };
        const int offs[4] = { AHI, ALO, BHI, BLO };
#pragma unroll
        for (int t = 0; t < 4; ++t) {
#pragma unroll
            for (int i = 0; i < 4; ++i) {
                int chunk = tid + i * 256;
                int r = chunk >> 3, c = chunk & 7;
                *(uint4*)(smem + offs[t] + r * 128 + ((c ^ (r & 7)) << 4)) =
                    *(const uint4*)(srcs[t] + (size_t)r * HD + c * 8);
            }
        }
    }
    __syncthreads();

    const int wm = wid >> 2, wn = wid & 3;           // 2 x 4 warps, tile 64x32
    float acc[4][4][4];
#pragma unroll
    for (int i = 0; i < 4; ++i)
#pragma unroll
        for (int j = 0; j < 4; ++j)
#pragma unroll
            for (int k = 0; k < 4; ++k) acc[i][j][k] = 0.f;

#pragma unroll
    for (int term = 0; term < 3; ++term) {
        const uint32_t As = sb + (term < 2 ? AHI : ALO);
        const uint32_t Bs = sb + (term == 1 ? BLO : BHI);
#pragma unroll
        for (int ks = 0; ks < 4; ++ks) {
            uint32_t a[4][4];
#pragma unroll
            for (int mt = 0; mt < 4; ++mt) {
                int r = wm * 64 + mt * 16 + (l & 15);
                int c = 2 * ks + (l >> 4);
                ldsm_x4(a[mt][0], a[mt][1], a[mt][2], a[mt][3],
                        As + r * 128 + ((c ^ (r & 7)) << 4));
            }
            uint32_t bf[4][2];
#pragma unroll
            for (int j = 0; j < 2; ++j) {
                int n = wn * 32 + j * 16 + (l & 7) + ((l >> 4) << 3);
                int c = 2 * ks + ((l >> 3) & 1);
                uint32_t t0, t1, t2, t3;
                ldsm_x4(t0, t1, t2, t3, Bs + n * 128 + ((c ^ (n & 7)) << 4));
                bf[j * 2][0] = t0; bf[j * 2][1] = t1;
                bf[j * 2 + 1][0] = t2; bf[j * 2 + 1][1] = t3;
            }
#pragma unroll
            for (int mt = 0; mt < 4; ++mt)
#pragma unroll
                for (int nt = 0; nt < 4; ++nt)
                    mma16816(acc[mt][nt], a[mt], bf[nt]);
        }
    }

    // epilogue: scale, mask, store (float2 per fragment row)
#pragma unroll
    for (int mt = 0; mt < 4; ++mt) {
#pragma unroll
        for (int nt = 0; nt < 4; ++nt) {
            const int gc = col0 + wn * 32 + nt * 8 + 2 * (l & 3);
#pragma unroll
            for (int h = 0; h < 2; ++h) {
                const int s = row0 + wm * 64 + mt * 16 + (l >> 2) + h * 8;
                int2 m = *(const int2*)(mask + (size_t)s * SEQ + gc);
                float v0 = acc[mt][nt][h * 2 + 0] * 0.125f;
                float v1 = acc[mt][nt][h * 2 + 1] * 0.125f;
                *(float2*)(attn + ((size_t)(b * SEQ) + s) * SEQ + gc) =
                    make_float2(m.x == 0 ? -1e9f : v0, m.y == 0 ? -1e9f : v1);
            }
        }
    }
}

// ===========================================================================
// softmax, in place
// ===========================================================================
__global__ void __launch_bounds__(256) softmax_kernel(float* __restrict__ attn)
{
    const size_t row = (size_t)blockIdx.y * SEQ + blockIdx.x;
    float* p = attn + row * SEQ;
    const int tid = threadIdx.x;
    __shared__ float red[16];

    float4 v0 = *(const float4*)&p[tid * 4];
    float4 v1 = *(const float4*)&p[1024 + tid * 4];

    float m = fmaxf(fmaxf(fmaxf(v0.x, v0.y), fmaxf(v0.z, v0.w)),
                    fmaxf(fmaxf(v1.x, v1.y), fmaxf(v1.z, v1.w)));
#pragma unroll
    for (int o = 16; o > 0; o >>= 1) m = fmaxf(m, __shfl_xor_sync(~0u, m, o));
    if ((tid & 31) == 0) red[tid >> 5] = m;
    __syncthreads();
    m = red[0];
#pragma unroll
    for (int i = 1; i < 8; ++i) m = fmaxf(m, red[i]);

    float e[8];
    e[0] = __expf(v0.x - m); e[1] = __expf(v0.y - m);
    e[2] = __expf(v0.z - m); e[3] = __expf(v0.w - m);
    e[4] = __expf(v1.x - m); e[5] = __expf(v1.y - m);
    e[6] = __expf(v1.z - m); e[7] = __expf(v1.w - m);

    float s = ((e[0] + e[1]) + (e[2] + e[3])) + ((e[4] + e[5]) + (e[6] + e[7]));
#pragma unroll
    for (int o = 16; o > 0; o >>= 1) s += __shfl_xor_sync(~0u, s, o);
    if ((tid & 31) == 0) red[8 + (tid >> 5)] = s;
    __syncthreads();
    s = red[8];
#pragma unroll
    for (int i = 1; i < 8; ++i) s += red[8 + i];

    const float inv = 1.0f / s;
    *(float4*)&p[tid * 4]        = make_float4(e[0]*inv, e[1]*inv, e[2]*inv, e[3]*inv);
    *(float4*)&p[1024 + tid * 4] = make_float4(e[4]*inv, e[5]*inv, e[6]*inv, e[7]*inv);
}

// ===========================================================================
// pv: out[128 x 64] = attn[128 x 2048] @ v[2048 x 64]; attn split on the fly
// ===========================================================================
__global__ void __launch_bounds__(256) pv_mma_kernel(
    const float* __restrict__ attn, float* __restrict__ out)
{
    extern __shared__ char smem[];
    constexpr int AHI = 0, ALO = 16384, BHI = 32768, BLO = 40960;
    const uint32_t sb = smem_u32(smem);
    const int tid = threadIdx.x, wid = tid >> 5, l = tid & 31;
    const int b = blockIdx.y, row0 = blockIdx.x * 128;

    const int wm = wid >> 1, wn = wid & 1;           // 4 x 2 warps, tile 32x32
    float acc[2][4][4];
#pragma unroll
    for (int i = 0; i < 2; ++i)
#pragma unroll
        for (int j = 0; j < 4; ++j)
#pragma unroll
            for (int k = 0; k < 4; ++k) acc[i][j][k] = 0.f;

    const __nv_bfloat16* vhi = g_vhi + (size_t)(b * 64) * SEQ;
    const __nv_bfloat16* vlo = g_vlo + (size_t)(b * 64) * SEQ;

    for (int tile = 0; tile < 32; ++tile) {
        const int t0 = tile * 64;

        // A: read attn fp32 128x64, split -> bf16 hi/lo swizzled smem tiles
#pragma unroll
        for (int i = 0; i < 4; ++i) {
            int chunk = tid + i * 256;               // 1024 chunks of 8 k-values
            int r = chunk >> 3, c = chunk & 7;
            const float* src = attn + ((size_t)(b * SEQ + row0 + r)) * SEQ + t0 + c * 8;
            float4 x0 = *(const float4*)src;
            float4 x1 = *(const float4*)(src + 4);
            uint32_t h0, l0, h1, l1, h2, l2, h3, l3;
            split2(x0.x, x0.y, h0, l0);
            split2(x0.z, x0.w, h1, l1);
            split2(x1.x, x1.y, h2, l2);
            split2(x1.z, x1.w, h3, l3);
            uint32_t off = r * 128 + ((c ^ (r & 7)) << 4);
            *(uint4*)(smem + AHI + off) = make_uint4(h0, h1, h2, h3);
            *(uint4*)(smem + ALO + off) = make_uint4(l0, l1, l2, l3);
        }
        // B: v hi/lo tiles 64 d-rows x 64 t
#pragma unroll
        for (int i = 0; i < 2; ++i) {
            int chunk = tid + i * 256;               // 512 chunks
            int r = chunk >> 3, c = chunk & 7;
            uint32_t off = r * 128 + ((c ^ (r & 7)) << 4);
            *(uint4*)(smem + BHI + off) = *(const uint4*)(vhi + (size_t)r * SEQ + t0 + c * 8);
            *(uint4*)(smem + BLO + off) = *(const uint4*)(vlo + (size_t)r * SEQ + t0 + c * 8);
        }
        __syncthreads();

#pragma unroll
        for (int term = 0; term < 3; ++term) {
            const uint32_t As = sb + (term < 2 ? AHI : ALO);
            const uint32_t Bs = sb + (term == 1 ? BLO : BHI);
#pragma unroll
            for (int ks = 0; ks < 4; ++ks) {
                uint32_t a[2][4];
#pragma unroll
                for (int mt = 0; mt < 2; ++mt) {
                    int r = wm * 32 + mt * 16 + (l & 15);
                    int c = 2 * ks + (l >> 4);
                    ldsm_x4(a[mt][0], a[mt][1], a[mt][2], a[mt][3],
                            As + r * 128 + ((c ^ (r & 7)) << 4));
                }
                uint32_t bf[4][2];
#pragma unroll
                for (int j = 0; j < 2; ++j) {
                    int n = wn * 32 + j * 16 + (l & 7) + ((l >> 4) << 3);
                    int c = 2 * ks + ((l >> 3) & 1);
                    uint32_t t0r, t1r, t2r, t3r;
                    ldsm_x4(t0r, t1r, t2r, t3r, Bs + n * 128 + ((c ^ (n & 7)) << 4));
                    bf[j * 2][0] = t0r; bf[j * 2][1] = t1r;
                    bf[j * 2 + 1][0] = t2r; bf[j * 2 + 1][1] = t3r;
                }
#pragma unroll
                for (int mt = 0; mt < 2; ++mt)
#pragma unroll
                    for (int nt = 0; nt < 4; ++nt)
                        mma16816(acc[mt][nt], a[mt], bf[nt]);
            }
        }
        __syncthreads();
    }

    // epilogue
#pragma unroll
    for (int mt = 0; mt < 2; ++mt) {
#pragma unroll
        for (int nt = 0; nt < 4; ++nt) {
            const int gc = wn * 32 + nt * 8 + 2 * (l & 3);
#pragma unroll
            for (int h = 0; h < 2; ++h) {
                const int gr = row0 + wm * 32 + mt * 16 + (l >> 2) + h * 8;
                *(float2*)(out + ((size_t)(b * SEQ) + gr) * HD + gc) =
                    make_float2(acc[mt][nt][h * 2 + 0], acc[mt][nt][h * 2 + 1]);
            }
        }
    }
}

// ===========================================================================
extern "C" void kernel_launch(void* const* d_in, const int* in_sizes, int n_in,
                              void* d_out, int out_size)
{
    const float* q    = (const float*)d_in[0];
    const float* k    = (const float*)d_in[1];
    const float* v    = (const float*)d_in[2];
    const int*   mask = (const int*)d_in[3];

    float* out  = (float*)d_out;
    float* attn = out + (size_t)BATCH * SEQ * HD;

    cudaFuncSetAttribute(scores_mma_kernel,
                         cudaFuncAttributeMaxDynamicSharedMemorySize, 65536);
    cudaFuncSetAttribute(pv_mma_kernel,
                         cudaFuncAttributeMaxDynamicSharedMemorySize, 49152);

    split_qk_kernel<<<512, 256>>>((const float4*)q, 0);
    split_qk_kernel<<<512, 256>>>((const float4*)k, 1);
    split_v_kernel<<<dim3(SEQ / 128, BATCH), 256>>>(v);

    scores_mma_kernel<<<dim3(16, 16, BATCH), 256, 65536>>>(mask, attn);
    softmax_kernel<<<dim3(SEQ, BATCH), 256>>>(attn);
    pv_mma_kernel<<<dim3(16, BATCH), 256, 49152>>>(attn, out);
}

// round 4
// speedup vs baseline: 1.7346x; 1.0270x over previous
#include <cuda_runtime.h>
#include <cuda_bf16.h>
#include <cstdint>

#define SEQ   2048
#define HD    64
#define BATCH 16

// ---------------------------------------------------------------------------
// device scratch
// ---------------------------------------------------------------------------
__device__ __nv_bfloat16 g_qhi[BATCH * SEQ * HD];
__device__ __nv_bfloat16 g_qlo[BATCH * SEQ * HD];
__device__ __nv_bfloat16 g_khi[BATCH * SEQ * HD];
__device__ __nv_bfloat16 g_klo[BATCH * SEQ * HD];
__device__ __nv_bfloat16 g_vhi[BATCH * HD * SEQ];   // transposed: [b][d][t]
__device__ __nv_bfloat16 g_vlo[BATCH * HD * SEQ];
__device__ float         g_part[BATCH * SEQ * 16];  // per-row per-coltile exp sums

// ---------------------------------------------------------------------------
// helpers
// ---------------------------------------------------------------------------
__device__ __forceinline__ uint32_t smem_u32(const void* p) {
    uint32_t a;
    asm("{ .reg .u64 t; cvta.to.shared.u64 t, %1; cvt.u32.u64 %0, t; }" : "=r"(a) : "l"(p));
    return a;
}
__device__ __forceinline__ uint32_t bfpack(float a, float b) {
    uint32_t r;
    asm("cvt.rn.bf16x2.f32 %0, %1, %2;" : "=r"(r) : "f"(b), "f"(a));
    return r;
}
__device__ __forceinline__ void split2(float x0, float x1, uint32_t& h, uint32_t& l) {
    h = bfpack(x0, x1);
    float h0 = __uint_as_float(h << 16);
    float h1 = __uint_as_float(h & 0xffff0000u);
    l = bfpack(x0 - h0, x1 - h1);
}
__device__ __forceinline__ void ldsm_x4(uint32_t& r0, uint32_t& r1, uint32_t& r2,
                                        uint32_t& r3, uint32_t addr) {
    asm volatile("ldmatrix.sync.aligned.m8n8.x4.shared.b16 {%0,%1,%2,%3}, [%4];"
                 : "=r"(r0), "=r"(r1), "=r"(r2), "=r"(r3) : "r"(addr));
}
__device__ __forceinline__ void mma16816(float* c, const uint32_t* a, const uint32_t* b) {
    asm volatile("mma.sync.aligned.m16n8k16.row.col.f32.bf16.bf16.f32 "
                 "{%0,%1,%2,%3}, {%4,%5,%6,%7}, {%8,%9}, {%0,%1,%2,%3};"
                 : "+f"(c[0]), "+f"(c[1]), "+f"(c[2]), "+f"(c[3])
                 : "r"(a[0]), "r"(a[1]), "r"(a[2]), "r"(a[3]), "r"(b[0]), "r"(b[1]));
}

// ===========================================================================
// split q/k into bf16 hi/lo
// ===========================================================================
__global__ void __launch_bounds__(256) split_qk_kernel(const float4* __restrict__ src, int isK)
{
    uint2* hi = (uint2*)(isK ? g_khi : g_qhi);
    uint2* lo = (uint2*)(isK ? g_klo : g_qlo);
    const int n = BATCH * SEQ * HD / 4;
    const int stride = gridDim.x * blockDim.x;
    for (int c = blockIdx.x * blockDim.x + threadIdx.x; c < n; c += stride) {
        float4 x = src[c];
        uint32_t h01, l01, h23, l23;
        split2(x.x, x.y, h01, l01);
        split2(x.z, x.w, h23, l23);
        hi[c] = make_uint2(h01, h23);
        lo[c] = make_uint2(l01, l23);
    }
}

// ===========================================================================
// transpose + split v: vT[b][d][t]
// ===========================================================================
__global__ void __launch_bounds__(256) split_v_kernel(const float* __restrict__ v)
{
    __shared__ float sm[64][129];
    const int tid = threadIdx.x;
    const int b = blockIdx.y, t0 = blockIdx.x * 128;
    const float* vb = v + (size_t)b * SEQ * HD;

#pragma unroll
    for (int i = 0; i < 8; ++i) {
        int chunk = tid + i * 256;
        int t = chunk >> 4, d4 = (chunk & 15) * 4;
        float4 x = *(const float4*)(vb + (size_t)(t0 + t) * HD + d4);
        sm[d4 + 0][t] = x.x; sm[d4 + 1][t] = x.y;
        sm[d4 + 2][t] = x.z; sm[d4 + 3][t] = x.w;
    }
    __syncthreads();

    const int r = tid >> 2, tb = (tid & 3) * 32;
    size_t obase = ((size_t)(b * 64 + r)) * SEQ + t0 + tb;
#pragma unroll
    for (int seg = 0; seg < 4; ++seg) {
        uint32_t h[4], l[4];
#pragma unroll
        for (int j = 0; j < 4; ++j) {
            float x0 = sm[r][tb + seg * 8 + j * 2];
            float x1 = sm[r][tb + seg * 8 + j * 2 + 1];
            split2(x0, x1, h[j], l[j]);
        }
        *(uint4*)(g_vhi + obase + seg * 8) = make_uint4(h[0], h[1], h[2], h[3]);
        *(uint4*)(g_vlo + obase + seg * 8) = make_uint4(l[0], l[1], l[2], l[3]);
    }
}

// ===========================================================================
// scores: e = mask ? exp((QK^T)/8) : 0 written to attn; per-coltile row sums
// -> g_part. 3-term split-bf16 mma, ldsm regrouped to share fragments.
// ===========================================================================
__global__ void __launch_bounds__(256) scores_mma_kernel(
    const int* __restrict__ mask, float* __restrict__ attn)
{
    extern __shared__ char smem[];
    constexpr int AHI = 0, ALO = 16384, BHI = 32768, BLO = 49152;
    const uint32_t sb = smem_u32(smem);
    const int tid = threadIdx.x, wid = tid >> 5, l = tid & 31;
    const int b = blockIdx.z, row0 = blockIdx.y * 128, col0 = blockIdx.x * 128;

    // cooperative loads: 4 tiles x 1024 16B-chunks
    {
        const __nv_bfloat16* srcs[4] = {
            g_qhi + ((size_t)(b * SEQ) + row0) * HD,
            g_qlo + ((size_t)(b * SEQ) + row0) * HD,
            g_khi + ((size_t)(b * SEQ) + col0) * HD,
            g_klo + ((size_t)(b * SEQ) + col0) * HD };
        const int offs[4] = { AHI, ALO, BHI, BLO };
#pragma unroll
        for (int t = 0; t < 4; ++t) {
#pragma unroll
            for (int i = 0; i < 4; ++i) {
                int chunk = tid + i * 256;
                int r = chunk >> 3, c = chunk & 7;
                *(uint4*)(smem + offs[t] + r * 128 + ((c ^ (r & 7)) << 4)) =
                    *(const uint4*)(srcs[t] + (size_t)r * HD + c * 8);
            }
        }
    }
    __syncthreads();

    const int wm = wid >> 2, wn = wid & 3;           // 2 x 4 warps, tile 64x32
    float acc[4][4][4];
#pragma unroll
    for (int i = 0; i < 4; ++i)
#pragma unroll
        for (int j = 0; j < 4; ++j)
#pragma unroll
            for (int k = 0; k < 4; ++k) acc[i][j][k] = 0.f;

    // pass 1: Ahi * (Bhi + Blo)   (Ahi fragments shared across both terms)
#pragma unroll
    for (int ks = 0; ks < 4; ++ks) {
        uint32_t a[4][4];
#pragma unroll
        for (int mt = 0; mt < 4; ++mt) {
            int r = wm * 64 + mt * 16 + (l & 15);
            int c = 2 * ks + (l >> 4);
            ldsm_x4(a[mt][0], a[mt][1], a[mt][2], a[mt][3],
                    sb + AHI + r * 128 + ((c ^ (r & 7)) << 4));
        }
        uint32_t bh[4][2], bl[4][2];
#pragma unroll
        for (int j = 0; j < 2; ++j) {
            int n = wn * 32 + j * 16 + (l & 7) + ((l >> 4) << 3);
            int c = 2 * ks + ((l >> 3) & 1);
            uint32_t t0, t1, t2, t3;
            ldsm_x4(t0, t1, t2, t3, sb + BHI + n * 128 + ((c ^ (n & 7)) << 4));
            bh[j*2][0] = t0; bh[j*2][1] = t1; bh[j*2+1][0] = t2; bh[j*2+1][1] = t3;
            ldsm_x4(t0, t1, t2, t3, sb + BLO + n * 128 + ((c ^ (n & 7)) << 4));
            bl[j*2][0] = t0; bl[j*2][1] = t1; bl[j*2+1][0] = t2; bl[j*2+1][1] = t3;
        }
#pragma unroll
        for (int mt = 0; mt < 4; ++mt)
#pragma unroll
            for (int nt = 0; nt < 4; ++nt) {
                mma16816(acc[mt][nt], a[mt], bh[nt]);
                mma16816(acc[mt][nt], a[mt], bl[nt]);
            }
    }
    // pass 2: Alo * Bhi
#pragma unroll
    for (int ks = 0; ks < 4; ++ks) {
        uint32_t a[4][4];
#pragma unroll
        for (int mt = 0; mt < 4; ++mt) {
            int r = wm * 64 + mt * 16 + (l & 15);
            int c = 2 * ks + (l >> 4);
            ldsm_x4(a[mt][0], a[mt][1], a[mt][2], a[mt][3],
                    sb + ALO + r * 128 + ((c ^ (r & 7)) << 4));
        }
        uint32_t bh[4][2];
#pragma unroll
        for (int j = 0; j < 2; ++j) {
            int n = wn * 32 + j * 16 + (l & 7) + ((l >> 4) << 3);
            int c = 2 * ks + ((l >> 3) & 1);
            uint32_t t0, t1, t2, t3;
            ldsm_x4(t0, t1, t2, t3, sb + BHI + n * 128 + ((c ^ (n & 7)) << 4));
            bh[j*2][0] = t0; bh[j*2][1] = t1; bh[j*2+1][0] = t2; bh[j*2+1][1] = t3;
        }
#pragma unroll
        for (int mt = 0; mt < 4; ++mt)
#pragma unroll
            for (int nt = 0; nt < 4; ++nt)
                mma16816(acc[mt][nt], a[mt], bh[nt]);
    }

    __syncthreads();                 // tiles dead; reuse smem[0..2KB) for row sums
    float* srow = (float*)smem;      // [4][128]

    // epilogue: e = mask ? exp(score/8) : 0 ; store; accumulate row sums
    float rs[4][2];
#pragma unroll
    for (int mt = 0; mt < 4; ++mt) { rs[mt][0] = 0.f; rs[mt][1] = 0.f; }

#pragma unroll
    for (int mt = 0; mt < 4; ++mt) {
#pragma unroll
        for (int nt = 0; nt < 4; ++nt) {
            const int gc = col0 + wn * 32 + nt * 8 + 2 * (l & 3);
#pragma unroll
            for (int h = 0; h < 2; ++h) {
                const int s = row0 + wm * 64 + mt * 16 + (l >> 2) + h * 8;
                int2 m = *(const int2*)(mask + (size_t)s * SEQ + gc);
                float e0 = (m.x == 0) ? 0.f : __expf(acc[mt][nt][h * 2 + 0] * 0.125f);
                float e1 = (m.y == 0) ? 0.f : __expf(acc[mt][nt][h * 2 + 1] * 0.125f);
                *(float2*)(attn + ((size_t)(b * SEQ) + s) * SEQ + gc) =
                    make_float2(e0, e1);
                rs[mt][h] += e0 + e1;
            }
        }
    }
    // quad reduce (lanes sharing a row differ only in l&3)
#pragma unroll
    for (int mt = 0; mt < 4; ++mt)
#pragma unroll
        for (int h = 0; h < 2; ++h) {
            float v = rs[mt][h];
            v += __shfl_xor_sync(~0u, v, 1);
            v += __shfl_xor_sync(~0u, v, 2);
            rs[mt][h] = v;
        }
    if ((l & 3) == 0) {
#pragma unroll
        for (int mt = 0; mt < 4; ++mt)
#pragma unroll
            for (int h = 0; h < 2; ++h)
                srow[wn * 128 + wm * 64 + mt * 16 + (l >> 2) + h * 8] = rs[mt][h];
    }
    __syncthreads();
    if (tid < 128) {
        float s = srow[tid] + srow[128 + tid] + srow[256 + tid] + srow[384 + tid];
        g_part[((size_t)(b * SEQ) + row0 + tid) * 16 + blockIdx.x] = s;
    }
}

// ===========================================================================
// pv: reads e, normalizes (p = e * inv_s), writes p back to attn (final
// output), splits p to bf16 and accumulates out = p @ v.
// ===========================================================================
__global__ void __launch_bounds__(256) pv_mma_kernel(
    float* __restrict__ attn, float* __restrict__ out)
{
    extern __shared__ char smem[];
    constexpr int AHI = 0, ALO = 16384, BHI = 32768, BLO = 40960, SINV = 49152;
    const uint32_t sb = smem_u32(smem);
    const int tid = threadIdx.x, wid = tid >> 5, l = tid & 31;
    const int b = blockIdx.y, row0 = blockIdx.x * 128;

    float* sinv = (float*)(smem + SINV);
    if (tid < 128) {
        const float4* pp = (const float4*)(g_part + ((size_t)(b * SEQ) + row0 + tid) * 16);
        float4 p0 = pp[0], p1 = pp[1], p2 = pp[2], p3 = pp[3];
        float s = ((p0.x + p0.y) + (p0.z + p0.w)) + ((p1.x + p1.y) + (p1.z + p1.w)) +
                  ((p2.x + p2.y) + (p2.z + p2.w)) + ((p3.x + p3.y) + (p3.z + p3.w));
        sinv[tid] = 1.0f / s;
    }
    __syncthreads();

    const int wm = wid >> 1, wn = wid & 1;           // 4 x 2 warps, tile 32x32
    float acc[2][4][4];
#pragma unroll
    for (int i = 0; i < 2; ++i)
#pragma unroll
        for (int j = 0; j < 4; ++j)
#pragma unroll
            for (int k = 0; k < 4; ++k) acc[i][j][k] = 0.f;

    const __nv_bfloat16* vhi = g_vhi + (size_t)(b * 64) * SEQ;
    const __nv_bfloat16* vlo = g_vlo + (size_t)(b * 64) * SEQ;

    for (int tile = 0; tile < 32; ++tile) {
        const int t0 = tile * 64;

        // A: read e, normalize, write back p, split -> bf16 hi/lo smem tiles
#pragma unroll
        for (int i = 0; i < 4; ++i) {
            int chunk = tid + i * 256;               // 1024 chunks of 8 k-values
            int r = chunk >> 3, c = chunk & 7;
            float* src = attn + ((size_t)(b * SEQ + row0 + r)) * SEQ + t0 + c * 8;
            float4 x0 = *(const float4*)src;
            float4 x1 = *(const float4*)(src + 4);
            const float inv = sinv[r];
            x0.x *= inv; x0.y *= inv; x0.z *= inv; x0.w *= inv;
            x1.x *= inv; x1.y *= inv; x1.z *= inv; x1.w *= inv;
            *(float4*)src = x0;
            *(float4*)(src + 4) = x1;
            uint32_t h0, l0, h1, l1, h2, l2, h3, l3;
            split2(x0.x, x0.y, h0, l0);
            split2(x0.z, x0.w, h1, l1);
            split2(x1.x, x1.y, h2, l2);
            split2(x1.z, x1.w, h3, l3);
            uint32_t off = r * 128 + ((c ^ (r & 7)) << 4);
            *(uint4*)(smem + AHI + off) = make_uint4(h0, h1, h2, h3);
            *(uint4*)(smem + ALO + off) = make_uint4(l0, l1, l2, l3);
        }
        // B: v hi/lo tiles 64 d-rows x 64 t
#pragma unroll
        for (int i = 0; i < 2; ++i) {
            int chunk = tid + i * 256;
            int r = chunk >> 3, c = chunk & 7;
            uint32_t off = r * 128 + ((c ^ (r & 7)) << 4);
            *(uint4*)(smem + BHI + off) = *(const uint4*)(vhi + (size_t)r * SEQ + t0 + c * 8);
            *(uint4*)(smem + BLO + off) = *(const uint4*)(vlo + (size_t)r * SEQ + t0 + c * 8);
        }
        __syncthreads();

        // pass 1: Ahi * (Bhi + Blo)
#pragma unroll
        for (int ks = 0; ks < 4; ++ks) {
            uint32_t a[2][4];
#pragma unroll
            for (int mt = 0; mt < 2; ++mt) {
                int r = wm * 32 + mt * 16 + (l & 15);
                int c = 2 * ks + (l >> 4);
                ldsm_x4(a[mt][0], a[mt][1], a[mt][2], a[mt][3],
                        sb + AHI + r * 128 + ((c ^ (r & 7)) << 4));
            }
            uint32_t bh[4][2], bl[4][2];
#pragma unroll
            for (int j = 0; j < 2; ++j) {
                int n = wn * 32 + j * 16 + (l & 7) + ((l >> 4) << 3);
                int c = 2 * ks + ((l >> 3) & 1);
                uint32_t t0r, t1r, t2r, t3r;
                ldsm_x4(t0r, t1r, t2r, t3r, sb + BHI + n * 128 + ((c ^ (n & 7)) << 4));
                bh[j*2][0] = t0r; bh[j*2][1] = t1r; bh[j*2+1][0] = t2r; bh[j*2+1][1] = t3r;
                ldsm_x4(t0r, t1r, t2r, t3r, sb + BLO + n * 128 + ((c ^ (n & 7)) << 4));
                bl[j*2][0] = t0r; bl[j*2][1] = t1r; bl[j*2+1][0] = t2r; bl[j*2+1][1] = t3r;
            }
#pragma unroll
            for (int mt = 0; mt < 2; ++mt)
#pragma unroll
                for (int nt = 0; nt < 4; ++nt) {
                    mma16816(acc[mt][nt], a[mt], bh[nt]);
                    mma16816(acc[mt][nt], a[mt], bl[nt]);
                }
        }
        // pass 2: Alo * Bhi
#pragma unroll
        for (int ks = 0; ks < 4; ++ks) {
            uint32_t a[2][4];
#pragma unroll
            for (int mt = 0; mt < 2; ++mt) {
                int r = wm * 32 + mt * 16 + (l & 15);
                int c = 2 * ks + (l >> 4);
                ldsm_x4(a[mt][0], a[mt][1], a[mt][2], a[mt][3],
                        sb + ALO + r * 128 + ((c ^ (r & 7)) << 4));
            }
            uint32_t bh[4][2];
#pragma unroll
            for (int j = 0; j < 2; ++j) {
                int n = wn * 32 + j * 16 + (l & 7) + ((l >> 4) << 3);
                int c = 2 * ks + ((l >> 3) & 1);
                uint32_t t0r, t1r, t2r, t3r;
                ldsm_x4(t0r, t1r, t2r, t3r, sb + BHI + n * 128 + ((c ^ (n & 7)) << 4));
                bh[j*2][0] = t0r; bh[j*2][1] = t1r; bh[j*2+1][0] = t2r; bh[j*2+1][1] = t3r;
            }
#pragma unroll
            for (int mt = 0; mt < 2; ++mt)
#pragma unroll
                for (int nt = 0; nt < 4; ++nt)
                    mma16816(acc[mt][nt], a[mt], bh[nt]);
        }
        __syncthreads();
    }

    // epilogue
#pragma unroll
    for (int mt = 0; mt < 2; ++mt) {
#pragma unroll
        for (int nt = 0; nt < 4; ++nt) {
            const int gc = wn * 32 + nt * 8 + 2 * (l & 3);
#pragma unroll
            for (int h = 0; h < 2; ++h) {
                const int gr = row0 + wm * 32 + mt * 16 + (l >> 2) + h * 8;
                *(float2*)(out + ((size_t)(b * SEQ) + gr) * HD + gc) =
                    make_float2(acc[mt][nt][h * 2 + 0], acc[mt][nt][h * 2 + 1]);
            }
        }
    }
}

// ===========================================================================
extern "C" void kernel_launch(void* const* d_in, const int* in_sizes, int n_in,
                              void* d_out, int out_size)
{
    const float* q    = (const float*)d_in[0];
    const float* k    = (const float*)d_in[1];
    const float* v    = (const float*)d_in[2];
    const int*   mask = (const int*)d_in[3];

    float* out  = (float*)d_out;
    float* attn = out + (size_t)BATCH * SEQ * HD;

    cudaFuncSetAttribute(scores_mma_kernel,
                         cudaFuncAttributeMaxDynamicSharedMemorySize, 65536);
    cudaFuncSetAttribute(pv_mma_kernel,
                         cudaFuncAttributeMaxDynamicSharedMemorySize, 49152 + 512);

    split_qk_kernel<<<512, 256>>>((const float4*)q, 0);
    split_qk_kernel<<<512, 256>>>((const float4*)k, 1);
    split_v_kernel<<<dim3(SEQ / 128, BATCH), 256>>>(v);

    scores_mma_kernel<<<dim3(16, 16, BATCH), 256, 65536>>>(mask, attn);
    pv_mma_kernel<<<dim3(16, BATCH), 256, 49152 + 512>>>(attn, out);
}

// round 5
// speedup vs baseline: 1.9012x; 1.0961x over previous
#include <cuda_runtime.h>
#include <cuda_bf16.h>
#include <cstdint>

#define SEQ   2048
#define HD    64
#define BATCH 16

// ---------------------------------------------------------------------------
// device scratch
// ---------------------------------------------------------------------------
__device__ __nv_bfloat16 g_qhi[BATCH * SEQ * HD];
__device__ __nv_bfloat16 g_qlo[BATCH * SEQ * HD];
__device__ __nv_bfloat16 g_khi[BATCH * SEQ * HD];
__device__ __nv_bfloat16 g_klo[BATCH * SEQ * HD];
__device__ __nv_bfloat16 g_vhi[BATCH * HD * SEQ];   // transposed: [b][d][t]
__device__ __nv_bfloat16 g_vlo[BATCH * HD * SEQ];
__device__ float         g_part[BATCH * SEQ * 16];  // per-row per-coltile exp sums

// ---------------------------------------------------------------------------
// helpers
// ---------------------------------------------------------------------------
__device__ __forceinline__ uint32_t smem_u32(const void* p) {
    uint32_t a;
    asm("{ .reg .u64 t; cvta.to.shared.u64 t, %1; cvt.u32.u64 %0, t; }" : "=r"(a) : "l"(p));
    return a;
}
__device__ __forceinline__ uint32_t bfpack(float a, float b) {
    uint32_t r;
    asm("cvt.rn.bf16x2.f32 %0, %1, %2;" : "=r"(r) : "f"(b), "f"(a));
    return r;
}
__device__ __forceinline__ void split2(float x0, float x1, uint32_t& h, uint32_t& l) {
    h = bfpack(x0, x1);
    float h0 = __uint_as_float(h << 16);
    float h1 = __uint_as_float(h & 0xffff0000u);
    l = bfpack(x0 - h0, x1 - h1);
}
__device__ __forceinline__ void ldsm_x4(uint32_t& r0, uint32_t& r1, uint32_t& r2,
                                        uint32_t& r3, uint32_t addr) {
    asm volatile("ldmatrix.sync.aligned.m8n8.x4.shared.b16 {%0,%1,%2,%3}, [%4];"
                 : "=r"(r0), "=r"(r1), "=r"(r2), "=r"(r3) : "r"(addr));
}
__device__ __forceinline__ void mma16816(float* c, const uint32_t* a, const uint32_t* b) {
    asm volatile("mma.sync.aligned.m16n8k16.row.col.f32.bf16.bf16.f32 "
                 "{%0,%1,%2,%3}, {%4,%5,%6,%7}, {%8,%9}, {%0,%1,%2,%3};"
                 : "+f"(c[0]), "+f"(c[1]), "+f"(c[2]), "+f"(c[3])
                 : "r"(a[0]), "r"(a[1]), "r"(a[2]), "r"(a[3]), "r"(b[0]), "r"(b[1]));
}
#define CP_ASYNC16(dst, src) \
    asm volatile("cp.async.cg.shared.global [%0], [%1], 16;" :: "r"(dst), "l"(src))
#define CP_COMMIT()  asm volatile("cp.async.commit_group;" ::: "memory")
#define CP_WAIT(n)   asm volatile("cp.async.wait_group %0;" :: "n"(n) : "memory")

// ===========================================================================
// split q/k into bf16 hi/lo
// ===========================================================================
__global__ void __launch_bounds__(256) split_qk_kernel(const float4* __restrict__ src, int isK)
{
    uint2* hi = (uint2*)(isK ? g_khi : g_qhi);
    uint2* lo = (uint2*)(isK ? g_klo : g_qlo);
    const int n = BATCH * SEQ * HD / 4;
    const int stride = gridDim.x * blockDim.x;
    for (int c = blockIdx.x * blockDim.x + threadIdx.x; c < n; c += stride) {
        float4 x = src[c];
        uint32_t h01, l01, h23, l23;
        split2(x.x, x.y, h01, l01);
        split2(x.z, x.w, h23, l23);
        hi[c] = make_uint2(h01, h23);
        lo[c] = make_uint2(l01, l23);
    }
}

// ===========================================================================
// transpose + split v: vT[b][d][t]
// ===========================================================================
__global__ void __launch_bounds__(256) split_v_kernel(const float* __restrict__ v)
{
    __shared__ float sm[64][129];
    const int tid = threadIdx.x;
    const int b = blockIdx.y, t0 = blockIdx.x * 128;
    const float* vb = v + (size_t)b * SEQ * HD;

#pragma unroll
    for (int i = 0; i < 8; ++i) {
        int chunk = tid + i * 256;
        int t = chunk >> 4, d4 = (chunk & 15) * 4;
        float4 x = *(const float4*)(vb + (size_t)(t0 + t) * HD + d4);
        sm[d4 + 0][t] = x.x; sm[d4 + 1][t] = x.y;
        sm[d4 + 2][t] = x.z; sm[d4 + 3][t] = x.w;
    }
    __syncthreads();

    const int r = tid >> 2, tb = (tid & 3) * 32;
    size_t obase = ((size_t)(b * 64 + r)) * SEQ + t0 + tb;
#pragma unroll
    for (int seg = 0; seg < 4; ++seg) {
        uint32_t h[4], l[4];
#pragma unroll
        for (int j = 0; j < 4; ++j) {
            float x0 = sm[r][tb + seg * 8 + j * 2];
            float x1 = sm[r][tb + seg * 8 + j * 2 + 1];
            split2(x0, x1, h[j], l[j]);
        }
        *(uint4*)(g_vhi + obase + seg * 8) = make_uint4(h[0], h[1], h[2], h[3]);
        *(uint4*)(g_vlo + obase + seg * 8) = make_uint4(l[0], l[1], l[2], l[3]);
    }
}

// ===========================================================================
// scores: e = mask ? exp((QK^T)/8) : 0 -> attn; per-coltile row sums -> g_part
// ===========================================================================
__global__ void __launch_bounds__(256, 2) scores_mma_kernel(
    const int* __restrict__ mask, float* __restrict__ attn)
{
    extern __shared__ char smem[];
    constexpr int AHI = 0, ALO = 16384, BHI = 32768, BLO = 49152;
    const uint32_t sb = smem_u32(smem);
    const int tid = threadIdx.x, wid = tid >> 5, l = tid & 31;
    const int b = blockIdx.z, row0 = blockIdx.y * 128, col0 = blockIdx.x * 128;

    {
        const __nv_bfloat16* srcs[4] = {
            g_qhi + ((size_t)(b * SEQ) + row0) * HD,
            g_qlo + ((size_t)(b * SEQ) + row0) * HD,
            g_khi + ((size_t)(b * SEQ) + col0) * HD,
            g_klo + ((size_t)(b * SEQ) + col0) * HD };
        const int offs[4] = { AHI, ALO, BHI, BLO };
#pragma unroll
        for (int t = 0; t < 4; ++t) {
#pragma unroll
            for (int i = 0; i < 4; ++i) {
                int chunk = tid + i * 256;
                int r = chunk >> 3, c = chunk & 7;
                *(uint4*)(smem + offs[t] + r * 128 + ((c ^ (r & 7)) << 4)) =
                    *(const uint4*)(srcs[t] + (size_t)r * HD + c * 8);
            }
        }
    }
    __syncthreads();

    const int wm = wid >> 2, wn = wid & 3;           // 2 x 4 warps, tile 64x32
    float acc[4][4][4];
#pragma unroll
    for (int i = 0; i < 4; ++i)
#pragma unroll
        for (int j = 0; j < 4; ++j)
#pragma unroll
            for (int k = 0; k < 4; ++k) acc[i][j][k] = 0.f;

    // pass 1: Ahi * (Bhi + Blo)
#pragma unroll
    for (int ks = 0; ks < 4; ++ks) {
        uint32_t a[4][4];
#pragma unroll
        for (int mt = 0; mt < 4; ++mt) {
            int r = wm * 64 + mt * 16 + (l & 15);
            int c = 2 * ks + (l >> 4);
            ldsm_x4(a[mt][0], a[mt][1], a[mt][2], a[mt][3],
                    sb + AHI + r * 128 + ((c ^ (r & 7)) << 4));
        }
        uint32_t bh[4][2], bl[4][2];
#pragma unroll
        for (int j = 0; j < 2; ++j) {
            int n = wn * 32 + j * 16 + (l & 7) + ((l >> 4) << 3);
            int c = 2 * ks + ((l >> 3) & 1);
            uint32_t t0, t1, t2, t3;
            ldsm_x4(t0, t1, t2, t3, sb + BHI + n * 128 + ((c ^ (n & 7)) << 4));
            bh[j*2][0] = t0; bh[j*2][1] = t1; bh[j*2+1][0] = t2; bh[j*2+1][1] = t3;
            ldsm_x4(t0, t1, t2, t3, sb + BLO + n * 128 + ((c ^ (n & 7)) << 4));
            bl[j*2][0] = t0; bl[j*2][1] = t1; bl[j*2+1][0] = t2; bl[j*2+1][1] = t3;
        }
#pragma unroll
        for (int mt = 0; mt < 4; ++mt)
#pragma unroll
            for (int nt = 0; nt < 4; ++nt) {
                mma16816(acc[mt][nt], a[mt], bh[nt]);
                mma16816(acc[mt][nt], a[mt], bl[nt]);
            }
    }
    // pass 2: Alo * Bhi
#pragma unroll
    for (int ks = 0; ks < 4; ++ks) {
        uint32_t a[4][4];
#pragma unroll
        for (int mt = 0; mt < 4; ++mt) {
            int r = wm * 64 + mt * 16 + (l & 15);
            int c = 2 * ks + (l >> 4);
            ldsm_x4(a[mt][0], a[mt][1], a[mt][2], a[mt][3],
                    sb + ALO + r * 128 + ((c ^ (r & 7)) << 4));
        }
        uint32_t bh[4][2];
#pragma unroll
        for (int j = 0; j < 2; ++j) {
            int n = wn * 32 + j * 16 + (l & 7) + ((l >> 4) << 3);
            int c = 2 * ks + ((l >> 3) & 1);
            uint32_t t0, t1, t2, t3;
            ldsm_x4(t0, t1, t2, t3, sb + BHI + n * 128 + ((c ^ (n & 7)) << 4));
            bh[j*2][0] = t0; bh[j*2][1] = t1; bh[j*2+1][0] = t2; bh[j*2+1][1] = t3;
        }
#pragma unroll
        for (int mt = 0; mt < 4; ++mt)
#pragma unroll
            for (int nt = 0; nt < 4; ++nt)
                mma16816(acc[mt][nt], a[mt], bh[nt]);
    }

    __syncthreads();
    float* srow = (float*)smem;      // [4][128]

    float rs[4][2];
#pragma unroll
    for (int mt = 0; mt < 4; ++mt) { rs[mt][0] = 0.f; rs[mt][1] = 0.f; }

#pragma unroll
    for (int mt = 0; mt < 4; ++mt) {
#pragma unroll
        for (int nt = 0; nt < 4; ++nt) {
            const int gc = col0 + wn * 32 + nt * 8 + 2 * (l & 3);
#pragma unroll
            for (int h = 0; h < 2; ++h) {
                const int s = row0 + wm * 64 + mt * 16 + (l >> 2) + h * 8;
                int2 m = *(const int2*)(mask + (size_t)s * SEQ + gc);
                float e0 = (m.x == 0) ? 0.f : __expf(acc[mt][nt][h * 2 + 0] * 0.125f);
                float e1 = (m.y == 0) ? 0.f : __expf(acc[mt][nt][h * 2 + 1] * 0.125f);
                *(float2*)(attn + ((size_t)(b * SEQ) + s) * SEQ + gc) =
                    make_float2(e0, e1);
                rs[mt][h] += e0 + e1;
            }
        }
    }
#pragma unroll
    for (int mt = 0; mt < 4; ++mt)
#pragma unroll
        for (int h = 0; h < 2; ++h) {
            float v = rs[mt][h];
            v += __shfl_xor_sync(~0u, v, 1);
            v += __shfl_xor_sync(~0u, v, 2);
            rs[mt][h] = v;
        }
    if ((l & 3) == 0) {
#pragma unroll
        for (int mt = 0; mt < 4; ++mt)
#pragma unroll
            for (int h = 0; h < 2; ++h)
                srow[wn * 128 + wm * 64 + mt * 16 + (l >> 2) + h * 8] = rs[mt][h];
    }
    __syncthreads();
    if (tid < 128) {
        float s = srow[tid] + srow[128 + tid] + srow[256 + tid] + srow[384 + tid];
        g_part[((size_t)(b * SEQ) + row0 + tid) * 16 + blockIdx.x] = s;
    }
}

// ===========================================================================
// pv: 64-row tiles (512 CTAs). Normalize e->p, write p back (final attn),
// split to bf16, MMA vs v. v tiles double-buffered via cp.async.
// smem: AHI 8K | ALO 8K | B 2 x (8K hi + 8K lo) | sinv 256B
// ===========================================================================
__global__ void __launch_bounds__(256) pv_mma_kernel(
    float* __restrict__ attn, float* __restrict__ out)
{
    extern __shared__ char smem[];
    constexpr int AHI = 0, ALO = 8192, BB = 16384, SINV = 49152;
    const uint32_t sb = smem_u32(smem);
    const int tid = threadIdx.x, wid = tid >> 5, l = tid & 31;
    const int b = blockIdx.y, row0 = blockIdx.x * 64;

    float* sinv = (float*)(smem + SINV);
    if (tid < 64) {
        const float4* pp = (const float4*)(g_part + ((size_t)(b * SEQ) + row0 + tid) * 16);
        float4 p0 = pp[0], p1 = pp[1], p2 = pp[2], p3 = pp[3];
        float s = ((p0.x + p0.y) + (p0.z + p0.w)) + ((p1.x + p1.y) + (p1.z + p1.w)) +
                  ((p2.x + p2.y) + (p2.z + p2.w)) + ((p3.x + p3.y) + (p3.z + p3.w));
        sinv[tid] = 1.0f / s;
    }

    const __nv_bfloat16* vhi = g_vhi + (size_t)(b * 64) * SEQ;
    const __nv_bfloat16* vlo = g_vlo + (size_t)(b * 64) * SEQ;

    // issue B tile 0 (hi+lo) via cp.async into buffer 0
    {
#pragma unroll
        for (int i = 0; i < 4; ++i) {
            int chunk = tid + i * 256;               // 1024 chunks
            int tb = chunk >> 9, rem = chunk & 511;
            int r = rem >> 3, c = rem & 7;
            uint32_t dst = sb + BB + tb * 8192 + r * 128 + ((c ^ (r & 7)) << 4);
            const __nv_bfloat16* src = (tb ? vlo : vhi) + (size_t)r * SEQ + c * 8;
            CP_ASYNC16(dst, src);
        }
        CP_COMMIT();
    }
    __syncthreads();                                  // sinv visible

    const int wm = wid >> 1, wn = wid & 1;            // 4 x 2 warps, tile 16x32
    float acc[4][4];
#pragma unroll
    for (int j = 0; j < 4; ++j)
#pragma unroll
        for (int k = 0; k < 4; ++k) acc[j][k] = 0.f;

    for (int tile = 0; tile < 32; ++tile) {
        const int t0 = tile * 64;
        const int buf = tile & 1;

        // A: read e (64x64 fp32), normalize, write back p, split into smem
#pragma unroll
        for (int i = 0; i < 2; ++i) {
            int chunk = tid + i * 256;                // 512 chunks of 8 floats
            int r = chunk >> 3, c = chunk & 7;
            float* src = attn + ((size_t)(b * SEQ + row0 + r)) * SEQ + t0 + c * 8;
            float4 x0 = *(const float4*)src;
            float4 x1 = *(const float4*)(src + 4);
            const float inv = sinv[r];
            x0.x *= inv; x0.y *= inv; x0.z *= inv; x0.w *= inv;
            x1.x *= inv; x1.y *= inv; x1.z *= inv; x1.w *= inv;
            *(float4*)src = x0;
            *(float4*)(src + 4) = x1;
            uint32_t h0, l0, h1, l1, h2, l2, h3, l3;
            split2(x0.x, x0.y, h0, l0);
            split2(x0.z, x0.w, h1, l1);
            split2(x1.x, x1.y, h2, l2);
            split2(x1.z, x1.w, h3, l3);
            uint32_t off = r * 128 + ((c ^ (r & 7)) << 4);
            *(uint4*)(smem + AHI + off) = make_uint4(h0, h1, h2, h3);
            *(uint4*)(smem + ALO + off) = make_uint4(l0, l1, l2, l3);
        }

        // issue next B tile
        if (tile < 31) {
            const int nt0 = t0 + 64;
#pragma unroll
            for (int i = 0; i < 4; ++i) {
                int chunk = tid + i * 256;
                int tb = chunk >> 9, rem = chunk & 511;
                int r = rem >> 3, c = rem & 7;
                uint32_t dst = sb + BB + (buf ^ 1) * 16384 + tb * 8192 +
                               r * 128 + ((c ^ (r & 7)) << 4);
                const __nv_bfloat16* src = (tb ? vlo : vhi) + (size_t)r * SEQ + nt0 + c * 8;
                CP_ASYNC16(dst, src);
            }
            CP_COMMIT();
            CP_WAIT(1);
        } else {
            CP_WAIT(0);
        }
        __syncthreads();

        const uint32_t BHIc = sb + BB + buf * 16384;
        const uint32_t BLOc = BHIc + 8192;

        // pass 1: Ahi * (Bhi + Blo)
#pragma unroll
        for (int ks = 0; ks < 4; ++ks) {
            uint32_t a[4];
            {
                int r = wm * 16 + (l & 15);
                int c = 2 * ks + (l >> 4);
                ldsm_x4(a[0], a[1], a[2], a[3],
                        sb + AHI + r * 128 + ((c ^ (r & 7)) << 4));
            }
            uint32_t bh[4][2], bl[4][2];
#pragma unroll
            for (int j = 0; j < 2; ++j) {
                int n = wn * 32 + j * 16 + (l & 7) + ((l >> 4) << 3);
                int c = 2 * ks + ((l >> 3) & 1);
                uint32_t t0r, t1r, t2r, t3r;
                ldsm_x4(t0r, t1r, t2r, t3r, BHIc + n * 128 + ((c ^ (n & 7)) << 4));
                bh[j*2][0] = t0r; bh[j*2][1] = t1r; bh[j*2+1][0] = t2r; bh[j*2+1][1] = t3r;
                ldsm_x4(t0r, t1r, t2r, t3r, BLOc + n * 128 + ((c ^ (n & 7)) << 4));
                bl[j*2][0] = t0r; bl[j*2][1] = t1r; bl[j*2+1][0] = t2r; bl[j*2+1][1] = t3r;
            }
#pragma unroll
            for (int nt = 0; nt < 4; ++nt) {
                mma16816(acc[nt], a, bh[nt]);
                mma16816(acc[nt], a, bl[nt]);
            }
        }
        // pass 2: Alo * Bhi
#pragma unroll
        for (int ks = 0; ks < 4; ++ks) {
            uint32_t a[4];
            {
                int r = wm * 16 + (l & 15);
                int c = 2 * ks + (l >> 4);
                ldsm_x4(a[0], a[1], a[2], a[3],
                        sb + ALO + r * 128 + ((c ^ (r & 7)) << 4));
            }
            uint32_t bh[4][2];
#pragma unroll
            for (int j = 0; j < 2; ++j) {
                int n = wn * 32 + j * 16 + (l & 7) + ((l >> 4) << 3);
                int c = 2 * ks + ((l >> 3) & 1);
                uint32_t t0r, t1r, t2r, t3r;
                ldsm_x4(t0r, t1r, t2r, t3r, BHIc + n * 128 + ((c ^ (n & 7)) << 4));
                bh[j*2][0] = t0r; bh[j*2][1] = t1r; bh[j*2+1][0] = t2r; bh[j*2+1][1] = t3r;
            }
#pragma unroll
            for (int nt = 0; nt < 4; ++nt)
                mma16816(acc[nt], a, bh[nt]);
        }
        __syncthreads();
    }

    // epilogue
#pragma unroll
    for (int nt = 0; nt < 4; ++nt) {
        const int gc = wn * 32 + nt * 8 + 2 * (l & 3);
#pragma unroll
        for (int h = 0; h < 2; ++h) {
            const int gr = row0 + wm * 16 + (l >> 2) + h * 8;
            *(float2*)(out + ((size_t)(b * SEQ) + gr) * HD + gc) =
                make_float2(acc[nt][h * 2 + 0], acc[nt][h * 2 + 1]);
        }
    }
}

// ===========================================================================
extern "C" void kernel_launch(void* const* d_in, const int* in_sizes, int n_in,
                              void* d_out, int out_size)
{
    const float* q    = (const float*)d_in[0];
    const float* k    = (const float*)d_in[1];
    const float* v    = (const float*)d_in[2];
    const int*   mask = (const int*)d_in[3];

    float* out  = (float*)d_out;
    float* attn = out + (size_t)BATCH * SEQ * HD;

    cudaFuncSetAttribute(scores_mma_kernel,
                         cudaFuncAttributeMaxDynamicSharedMemorySize, 65536);
    cudaFuncSetAttribute(pv_mma_kernel,
                         cudaFuncAttributeMaxDynamicSharedMemorySize, 49152 + 512);

    split_qk_kernel<<<512, 256>>>((const float4*)q, 0);
    split_qk_kernel<<<512, 256>>>((const float4*)k, 1);
    split_v_kernel<<<dim3(SEQ / 128, BATCH), 256>>>(v);

    scores_mma_kernel<<<dim3(16, 16, BATCH), 256, 65536>>>(mask, attn);
    pv_mma_kernel<<<dim3(32, BATCH), 256, 49152 + 512>>>(attn, out);
}

// round 6
// speedup vs baseline: 2.0124x; 1.0585x over previous
#include <cuda_runtime.h>
#include <cuda_bf16.h>
#include <cstdint>

#define SEQ   2048
#define HD    64
#define BATCH 16

// ---------------------------------------------------------------------------
// device scratch
// ---------------------------------------------------------------------------
__device__ __nv_bfloat16 g_qhi[BATCH * SEQ * HD];
__device__ __nv_bfloat16 g_qlo[BATCH * SEQ * HD];
__device__ __nv_bfloat16 g_khi[BATCH * SEQ * HD];
__device__ __nv_bfloat16 g_klo[BATCH * SEQ * HD];
__device__ __nv_bfloat16 g_vhi[BATCH * HD * SEQ];   // transposed: [b][d][t]
__device__ __nv_bfloat16 g_vlo[BATCH * HD * SEQ];
__device__ float         g_part[BATCH * SEQ * 16];  // per-row per-coltile exp sums
__device__ uint32_t      g_maskbits[SEQ * (SEQ / 32)]; // 1 bit per mask element

// ---------------------------------------------------------------------------
// helpers
// ---------------------------------------------------------------------------
__device__ __forceinline__ uint32_t smem_u32(const void* p) {
    uint32_t a;
    asm("{ .reg .u64 t; cvta.to.shared.u64 t, %1; cvt.u32.u64 %0, t; }" : "=r"(a) : "l"(p));
    return a;
}
__device__ __forceinline__ uint32_t bfpack(float a, float b) {
    uint32_t r;
    asm("cvt.rn.bf16x2.f32 %0, %1, %2;" : "=r"(r) : "f"(b), "f"(a));
    return r;
}
__device__ __forceinline__ void split2(float x0, float x1, uint32_t& h, uint32_t& l) {
    h = bfpack(x0, x1);
    float h0 = __uint_as_float(h << 16);
    float h1 = __uint_as_float(h & 0xffff0000u);
    l = bfpack(x0 - h0, x1 - h1);
}
__device__ __forceinline__ void ldsm_x4(uint32_t& r0, uint32_t& r1, uint32_t& r2,
                                        uint32_t& r3, uint32_t addr) {
    asm volatile("ldmatrix.sync.aligned.m8n8.x4.shared.b16 {%0,%1,%2,%3}, [%4];"
                 : "=r"(r0), "=r"(r1), "=r"(r2), "=r"(r3) : "r"(addr));
}
__device__ __forceinline__ void mma16816(float* c, const uint32_t* a, const uint32_t* b) {
    asm volatile("mma.sync.aligned.m16n8k16.row.col.f32.bf16.bf16.f32 "
                 "{%0,%1,%2,%3}, {%4,%5,%6,%7}, {%8,%9}, {%0,%1,%2,%3};"
                 : "+f"(c[0]), "+f"(c[1]), "+f"(c[2]), "+f"(c[3])
                 : "r"(a[0]), "r"(a[1]), "r"(a[2]), "r"(a[3]), "r"(b[0]), "r"(b[1]));
}
#define CP_ASYNC16(dst, src) \
    asm volatile("cp.async.cg.shared.global [%0], [%1], 16;" :: "r"(dst), "l"(src))
#define CP_COMMIT()  asm volatile("cp.async.commit_group;" ::: "memory")
#define CP_WAIT(n)   asm volatile("cp.async.wait_group %0;" :: "n"(n) : "memory")

// ===========================================================================
// pack mask -> bitmask (bit j of word [row][w] = mask[row][w*32+j] != 0)
// ===========================================================================
__global__ void __launch_bounds__(256) mask_pack_kernel(const int* __restrict__ mask)
{
    const int gw = (blockIdx.x * 256 + threadIdx.x) >> 5;   // global warp id
    const int l  = threadIdx.x & 31;
    const int nwarps = gridDim.x * 8;
    const int nwords = SEQ * (SEQ / 32);
    for (int w = gw; w < nwords; w += nwarps) {
        const int row = w >> 6, wc = w & 63;
        int v = mask[(size_t)row * SEQ + wc * 32 + l];
        uint32_t bits = __ballot_sync(~0u, v != 0);
        if (l == 0) g_maskbits[w] = bits;
    }
}

// ===========================================================================
// split q/k into bf16 hi/lo
// ===========================================================================
__global__ void __launch_bounds__(256) split_qk_kernel(const float4* __restrict__ src, int isK)
{
    uint2* hi = (uint2*)(isK ? g_khi : g_qhi);
    uint2* lo = (uint2*)(isK ? g_klo : g_qlo);
    const int n = BATCH * SEQ * HD / 4;
    const int stride = gridDim.x * blockDim.x;
    for (int c = blockIdx.x * blockDim.x + threadIdx.x; c < n; c += stride) {
        float4 x = src[c];
        uint32_t h01, l01, h23, l23;
        split2(x.x, x.y, h01, l01);
        split2(x.z, x.w, h23, l23);
        hi[c] = make_uint2(h01, h23);
        lo[c] = make_uint2(l01, l23);
    }
}

// ===========================================================================
// transpose + split v: vT[b][d][t]
// ===========================================================================
__global__ void __launch_bounds__(256) split_v_kernel(const float* __restrict__ v)
{
    __shared__ float sm[64][129];
    const int tid = threadIdx.x;
    const int b = blockIdx.y, t0 = blockIdx.x * 128;
    const float* vb = v + (size_t)b * SEQ * HD;

#pragma unroll
    for (int i = 0; i < 8; ++i) {
        int chunk = tid + i * 256;
        int t = chunk >> 4, d4 = (chunk & 15) * 4;
        float4 x = *(const float4*)(vb + (size_t)(t0 + t) * HD + d4);
        sm[d4 + 0][t] = x.x; sm[d4 + 1][t] = x.y;
        sm[d4 + 2][t] = x.z; sm[d4 + 3][t] = x.w;
    }
    __syncthreads();

    const int r = tid >> 2, tb = (tid & 3) * 32;
    size_t obase = ((size_t)(b * 64 + r)) * SEQ + t0 + tb;
#pragma unroll
    for (int seg = 0; seg < 4; ++seg) {
        uint32_t h[4], l[4];
#pragma unroll
        for (int j = 0; j < 4; ++j) {
            float x0 = sm[r][tb + seg * 8 + j * 2];
            float x1 = sm[r][tb + seg * 8 + j * 2 + 1];
            split2(x0, x1, h[j], l[j]);
        }
        *(uint4*)(g_vhi + obase + seg * 8) = make_uint4(h[0], h[1], h[2], h[3]);
        *(uint4*)(g_vlo + obase + seg * 8) = make_uint4(l[0], l[1], l[2], l[3]);
    }
}

// ===========================================================================
// scores: e = maskbit ? exp((QK^T)/8) : 0 -> attn; coltile row sums -> g_part
// ===========================================================================
__global__ void __launch_bounds__(256, 2) scores_mma_kernel(float* __restrict__ attn)
{
    extern __shared__ char smem[];
    constexpr int AHI = 0, ALO = 16384, BHI = 32768, BLO = 49152;
    const uint32_t sb = smem_u32(smem);
    const int tid = threadIdx.x, wid = tid >> 5, l = tid & 31;
    const int b = blockIdx.z, row0 = blockIdx.y * 128, col0 = blockIdx.x * 128;

    {
        const __nv_bfloat16* srcs[4] = {
            g_qhi + ((size_t)(b * SEQ) + row0) * HD,
            g_qlo + ((size_t)(b * SEQ) + row0) * HD,
            g_khi + ((size_t)(b * SEQ) + col0) * HD,
            g_klo + ((size_t)(b * SEQ) + col0) * HD };
        const int offs[4] = { AHI, ALO, BHI, BLO };
#pragma unroll
        for (int t = 0; t < 4; ++t) {
#pragma unroll
            for (int i = 0; i < 4; ++i) {
                int chunk = tid + i * 256;
                int r = chunk >> 3, c = chunk & 7;
                *(uint4*)(smem + offs[t] + r * 128 + ((c ^ (r & 7)) << 4)) =
                    *(const uint4*)(srcs[t] + (size_t)r * HD + c * 8);
            }
        }
    }
    __syncthreads();

    const int wm = wid >> 2, wn = wid & 3;           // 2 x 4 warps, tile 64x32
    float acc[4][4][4];
#pragma unroll
    for (int i = 0; i < 4; ++i)
#pragma unroll
        for (int j = 0; j < 4; ++j)
#pragma unroll
            for (int k = 0; k < 4; ++k) acc[i][j][k] = 0.f;

    // pass 1: Ahi * (Bhi + Blo)
#pragma unroll
    for (int ks = 0; ks < 4; ++ks) {
        uint32_t a[4][4];
#pragma unroll
        for (int mt = 0; mt < 4; ++mt) {
            int r = wm * 64 + mt * 16 + (l & 15);
            int c = 2 * ks + (l >> 4);
            ldsm_x4(a[mt][0], a[mt][1], a[mt][2], a[mt][3],
                    sb + AHI + r * 128 + ((c ^ (r & 7)) << 4));
        }
        uint32_t bh[4][2], bl[4][2];
#pragma unroll
        for (int j = 0; j < 2; ++j) {
            int n = wn * 32 + j * 16 + (l & 7) + ((l >> 4) << 3);
            int c = 2 * ks + ((l >> 3) & 1);
            uint32_t t0, t1, t2, t3;
            ldsm_x4(t0, t1, t2, t3, sb + BHI + n * 128 + ((c ^ (n & 7)) << 4));
            bh[j*2][0] = t0; bh[j*2][1] = t1; bh[j*2+1][0] = t2; bh[j*2+1][1] = t3;
            ldsm_x4(t0, t1, t2, t3, sb + BLO + n * 128 + ((c ^ (n & 7)) << 4));
            bl[j*2][0] = t0; bl[j*2][1] = t1; bl[j*2+1][0] = t2; bl[j*2+1][1] = t3;
        }
#pragma unroll
        for (int mt = 0; mt < 4; ++mt)
#pragma unroll
            for (int nt = 0; nt < 4; ++nt) {
                mma16816(acc[mt][nt], a[mt], bh[nt]);
                mma16816(acc[mt][nt], a[mt], bl[nt]);
            }
    }
    // pass 2: Alo * Bhi
#pragma unroll
    for (int ks = 0; ks < 4; ++ks) {
        uint32_t a[4][4];
#pragma unroll
        for (int mt = 0; mt < 4; ++mt) {
            int r = wm * 64 + mt * 16 + (l & 15);
            int c = 2 * ks + (l >> 4);
            ldsm_x4(a[mt][0], a[mt][1], a[mt][2], a[mt][3],
                    sb + ALO + r * 128 + ((c ^ (r & 7)) << 4));
        }
        uint32_t bh[4][2];
#pragma unroll
        for (int j = 0; j < 2; ++j) {
            int n = wn * 32 + j * 16 + (l & 7) + ((l >> 4) << 3);
            int c = 2 * ks + ((l >> 3) & 1);
            uint32_t t0, t1, t2, t3;
            ldsm_x4(t0, t1, t2, t3, sb + BHI + n * 128 + ((c ^ (n & 7)) << 4));
            bh[j*2][0] = t0; bh[j*2][1] = t1; bh[j*2+1][0] = t2; bh[j*2+1][1] = t3;
        }
#pragma unroll
        for (int mt = 0; mt < 4; ++mt)
#pragma unroll
            for (int nt = 0; nt < 4; ++nt)
                mma16816(acc[mt][nt], a[mt], bh[nt]);
    }

    __syncthreads();
    float* srow = (float*)smem;      // [4][128]

    float rs[4][2];
#pragma unroll
    for (int mt = 0; mt < 4; ++mt) { rs[mt][0] = 0.f; rs[mt][1] = 0.f; }

    const int wbase = (col0 >> 5) + wn;              // bitmask word column
#pragma unroll
    for (int mt = 0; mt < 4; ++mt) {
#pragma unroll
        for (int h = 0; h < 2; ++h) {
            const int s = row0 + wm * 64 + mt * 16 + (l >> 2) + h * 8;
            const uint32_t w = g_maskbits[(size_t)s * 64 + wbase];
            float* drow = attn + ((size_t)(b * SEQ) + s) * SEQ + col0 + wn * 32;
            const int sh0 = 2 * (l & 3);
#pragma unroll
            for (int nt = 0; nt < 4; ++nt) {
                const uint32_t bits = w >> (nt * 8 + sh0);
                float e0 = (bits & 1u) ? __expf(acc[mt][nt][h * 2 + 0] * 0.125f) : 0.f;
                float e1 = (bits & 2u) ? __expf(acc[mt][nt][h * 2 + 1] * 0.125f) : 0.f;
                *(float2*)(drow + nt * 8 + sh0) = make_float2(e0, e1);
                rs[mt][h] += e0 + e1;
            }
        }
    }
#pragma unroll
    for (int mt = 0; mt < 4; ++mt)
#pragma unroll
        for (int h = 0; h < 2; ++h) {
            float v = rs[mt][h];
            v += __shfl_xor_sync(~0u, v, 1);
            v += __shfl_xor_sync(~0u, v, 2);
            rs[mt][h] = v;
        }
    if ((l & 3) == 0) {
#pragma unroll
        for (int mt = 0; mt < 4; ++mt)
#pragma unroll
            for (int h = 0; h < 2; ++h)
                srow[wn * 128 + wm * 64 + mt * 16 + (l >> 2) + h * 8] = rs[mt][h];
    }
    __syncthreads();
    if (tid < 128) {
        float s = srow[tid] + srow[128 + tid] + srow[256 + tid] + srow[384 + tid];
        g_part[((size_t)(b * SEQ) + row0 + tid) * 16 + blockIdx.x] = s;
    }
}

// ===========================================================================
// pv: 64-row tiles (512 CTAs). e staged via cp.async (2 stages), transform
// (normalize -> write p -> split bf16) from smem, MMA vs double-buffered v.
// smem: ESTAGE 2x17408 | AHI 8K | ALO 8K | B 2x16K | sinv 256B
// ===========================================================================
__global__ void __launch_bounds__(256) pv_mma_kernel(
    float* __restrict__ attn, float* __restrict__ out)
{
    extern __shared__ char smem[];
    constexpr int EST = 0, ESTRIDE = 17408;                 // 64 rows * 272B
    constexpr int AHI = 34816, ALO = 43008, BB = 51200, SINV = 83968;
    const uint32_t sb = smem_u32(smem);
    const int tid = threadIdx.x, wid = tid >> 5, l = tid & 31;
    const int b = blockIdx.y, row0 = blockIdx.x * 64;

    float* sinv = (float*)(smem + SINV);
    if (tid < 64) {
        const float4* pp = (const float4*)(g_part + ((size_t)(b * SEQ) + row0 + tid) * 16);
        float4 p0 = pp[0], p1 = pp[1], p2 = pp[2], p3 = pp[3];
        float s = ((p0.x + p0.y) + (p0.z + p0.w)) + ((p1.x + p1.y) + (p1.z + p1.w)) +
                  ((p2.x + p2.y) + (p2.z + p2.w)) + ((p3.x + p3.y) + (p3.z + p3.w));
        sinv[tid] = 1.0f / s;
    }

    const __nv_bfloat16* vhi = g_vhi + (size_t)(b * 64) * SEQ;
    const __nv_bfloat16* vlo = g_vlo + (size_t)(b * 64) * SEQ;
    const float* arow = attn + ((size_t)(b * SEQ) + row0) * SEQ;

    // prologue: stage 0 of e-tile and B-tile
    {
#pragma unroll
        for (int i = 0; i < 4; ++i) {
            int chunk = tid + i * 256;                 // 1024 x 16B (e tile)
            int r = chunk >> 4, c = chunk & 15;
            CP_ASYNC16(sb + EST + r * 272 + c * 16, arow + (size_t)r * SEQ + c * 4);
        }
#pragma unroll
        for (int i = 0; i < 4; ++i) {
            int chunk = tid + i * 256;                 // 1024 x 16B (v hi+lo)
            int tb = chunk >> 9, rem = chunk & 511;
            int r = rem >> 3, c = rem & 7;
            uint32_t dst = sb + BB + tb * 8192 + r * 128 + ((c ^ (r & 7)) << 4);
            CP_ASYNC16(dst, (tb ? vlo : vhi) + (size_t)r * SEQ + c * 8);
        }
        CP_COMMIT();
    }

    const int wm = wid >> 1, wn = wid & 1;             // 4 x 2 warps, tile 16x32
    float acc[4][4];
#pragma unroll
    for (int j = 0; j < 4; ++j)
#pragma unroll
        for (int k = 0; k < 4; ++k) acc[j][k] = 0.f;

    for (int tile = 0; tile < 32; ++tile) {
        const int t0 = tile * 64;
        const int buf = tile & 1;

        CP_WAIT(0);
        __syncthreads();        // stage[buf]/B[buf] ready; prev reads done

        // prefetch next tile (overlaps transform + MMA below)
        if (tile < 31) {
            const int nt0 = t0 + 64;
            const int nbuf = buf ^ 1;
#pragma unroll
            for (int i = 0; i < 4; ++i) {
                int chunk = tid + i * 256;
                int r = chunk >> 4, c = chunk & 15;
                CP_ASYNC16(sb + EST + nbuf * ESTRIDE + r * 272 + c * 16,
                           arow + (size_t)r * SEQ + nt0 + c * 4);
            }
#pragma unroll
            for (int i = 0; i < 4; ++i) {
                int chunk = tid + i * 256;
                int tb = chunk >> 9, rem = chunk & 511;
                int r = rem >> 3, c = rem & 7;
                uint32_t dst = sb + BB + nbuf * 16384 + tb * 8192 +
                               r * 128 + ((c ^ (r & 7)) << 4);
                CP_ASYNC16(dst, (tb ? vlo : vhi) + (size_t)r * SEQ + nt0 + c * 8);
            }
            CP_COMMIT();
        }

        // transform: e -> p (write back) + split into AHI/ALO
        const float* est = (const float*)(smem + EST + buf * ESTRIDE);
#pragma unroll
        for (int i = 0; i < 2; ++i) {
            int chunk = tid + i * 256;                 // 512 chunks of 8 floats
            int r = chunk >> 3, c = chunk & 7;
            const float* sp = est + r * 68 + c * 8;
            float4 x0 = *(const float4*)sp;
            float4 x1 = *(const float4*)(sp + 4);
            const float inv = sinv[r];
            x0.x *= inv; x0.y *= inv; x0.z *= inv; x0.w *= inv;
            x1.x *= inv; x1.y *= inv; x1.z *= inv; x1.w *= inv;
            float* gp = (float*)(arow + (size_t)r * SEQ + t0 + c * 8);
            *(float4*)gp = x0;
            *(float4*)(gp + 4) = x1;
            uint32_t h0, l0, h1, l1, h2, l2, h3, l3;
            split2(x0.x, x0.y, h0, l0);
            split2(x0.z, x0.w, h1, l1);
            split2(x1.x, x1.y, h2, l2);
            split2(x1.z, x1.w, h3, l3);
            uint32_t off = r * 128 + ((c ^ (r & 7)) << 4);
            *(uint4*)(smem + AHI + off) = make_uint4(h0, h1, h2, h3);
            *(uint4*)(smem + ALO + off) = make_uint4(l0, l1, l2, l3);
        }
        __syncthreads();

        const uint32_t BHIc = sb + BB + buf * 16384;
        const uint32_t BLOc = BHIc + 8192;

        // pass 1: Ahi * (Bhi + Blo)
#pragma unroll
        for (int ks = 0; ks < 4; ++ks) {
            uint32_t a[4];
            {
                int r = wm * 16 + (l & 15);
                int c = 2 * ks + (l >> 4);
                ldsm_x4(a[0], a[1], a[2], a[3],
                        sb + AHI + r * 128 + ((c ^ (r & 7)) << 4));
            }
            uint32_t bh[4][2], bl[4][2];
#pragma unroll
            for (int j = 0; j < 2; ++j) {
                int n = wn * 32 + j * 16 + (l & 7) + ((l >> 4) << 3);
                int c = 2 * ks + ((l >> 3) & 1);
                uint32_t t0r, t1r, t2r, t3r;
                ldsm_x4(t0r, t1r, t2r, t3r, BHIc + n * 128 + ((c ^ (n & 7)) << 4));
                bh[j*2][0] = t0r; bh[j*2][1] = t1r; bh[j*2+1][0] = t2r; bh[j*2+1][1] = t3r;
                ldsm_x4(t0r, t1r, t2r, t3r, BLOc + n * 128 + ((c ^ (n & 7)) << 4));
                bl[j*2][0] = t0r; bl[j*2][1] = t1r; bl[j*2+1][0] = t2r; bl[j*2+1][1] = t3r;
            }
#pragma unroll
            for (int nt = 0; nt < 4; ++nt) {
                mma16816(acc[nt], a, bh[nt]);
                mma16816(acc[nt], a, bl[nt]);
            }
        }
        // pass 2: Alo * Bhi
#pragma unroll
        for (int ks = 0; ks < 4; ++ks) {
            uint32_t a[4];
            {
                int r = wm * 16 + (l & 15);
                int c = 2 * ks + (l >> 4);
                ldsm_x4(a[0], a[1], a[2], a[3],
                        sb + ALO + r * 128 + ((c ^ (r & 7)) << 4));
            }
            uint32_t bh[4][2];
#pragma unroll
            for (int j = 0; j < 2; ++j) {
                int n = wn * 32 + j * 16 + (l & 7) + ((l >> 4) << 3);
                int c = 2 * ks + ((l >> 3) & 1);
                uint32_t t0r, t1r, t2r, t3r;
                ldsm_x4(t0r, t1r, t2r, t3r, BHIc + n * 128 + ((c ^ (n & 7)) << 4));
                bh[j*2][0] = t0r; bh[j*2][1] = t1r; bh[j*2+1][0] = t2r; bh[j*2+1][1] = t3r;
            }
#pragma unroll
            for (int nt = 0; nt < 4; ++nt)
                mma16816(acc[nt], a, bh[nt]);
        }
    }

    // epilogue
#pragma unroll
    for (int nt = 0; nt < 4; ++nt) {
        const int gc = wn * 32 + nt * 8 + 2 * (l & 3);
#pragma unroll
        for (int h = 0; h < 2; ++h) {
            const int gr = row0 + wm * 16 + (l >> 2) + h * 8;
            *(float2*)(out + ((size_t)(b * SEQ) + gr) * HD + gc) =
                make_float2(acc[nt][h * 2 + 0], acc[nt][h * 2 + 1]);
        }
    }
}

// ===========================================================================
extern "C" void kernel_launch(void* const* d_in, const int* in_sizes, int n_in,
                              void* d_out, int out_size)
{
    const float* q    = (const float*)d_in[0];
    const float* k    = (const float*)d_in[1];
    const float* v    = (const float*)d_in[2];
    const int*   mask = (const int*)d_in[3];

    float* out  = (float*)d_out;
    float* attn = out + (size_t)BATCH * SEQ * HD;

    cudaFuncSetAttribute(scores_mma_kernel,
                         cudaFuncAttributeMaxDynamicSharedMemorySize, 65536);
    cudaFuncSetAttribute(pv_mma_kernel,
                         cudaFuncAttributeMaxDynamicSharedMemorySize, 84224);

    mask_pack_kernel<<<512, 256>>>(mask);
    split_qk_kernel<<<512, 256>>>((const float4*)q, 0);
    split_qk_kernel<<<512, 256>>>((const float4*)k, 1);
    split_v_kernel<<<dim3(SEQ / 128, BATCH), 256>>>(v);

    scores_mma_kernel<<<dim3(16, 16, BATCH), 256, 65536>>>(attn);
    pv_mma_kernel<<<dim3(32, BATCH), 256, 84224>>>(attn, out);
}

// round 7
// speedup vs baseline: 2.1201x; 1.0535x over previous
#include <cuda_runtime.h>
#include <cuda_bf16.h>
#include <cuda_fp16.h>
#include <cstdint>

#define SEQ   2048
#define HD    64
#define BATCH 16

// ---------------------------------------------------------------------------
// device scratch
// ---------------------------------------------------------------------------
__device__ __nv_bfloat16 g_qhi[BATCH * SEQ * HD];
__device__ __nv_bfloat16 g_qlo[BATCH * SEQ * HD];
__device__ __nv_bfloat16 g_khi[BATCH * SEQ * HD];
__device__ __nv_bfloat16 g_klo[BATCH * SEQ * HD];
__device__ __half        g_vhi[BATCH * HD * SEQ];   // transposed: [b][d][t], fp16
__device__ __half        g_vlo[BATCH * HD * SEQ];   // residual, fp16
__device__ float         g_part[BATCH * SEQ * 16];  // per-row per-coltile exp sums
__device__ uint32_t      g_maskbits[SEQ * (SEQ / 32)];

// ---------------------------------------------------------------------------
// helpers
// ---------------------------------------------------------------------------
__device__ __forceinline__ uint32_t smem_u32(const void* p) {
    uint32_t a;
    asm("{ .reg .u64 t; cvta.to.shared.u64 t, %1; cvt.u32.u64 %0, t; }" : "=r"(a) : "l"(p));
    return a;
}
__device__ __forceinline__ uint32_t bfpack(float a, float b) {
    uint32_t r;
    asm("cvt.rn.bf16x2.f32 %0, %1, %2;" : "=r"(r) : "f"(b), "f"(a));
    return r;
}
__device__ __forceinline__ void split2(float x0, float x1, uint32_t& h, uint32_t& l) {
    h = bfpack(x0, x1);
    float h0 = __uint_as_float(h << 16);
    float h1 = __uint_as_float(h & 0xffff0000u);
    l = bfpack(x0 - h0, x1 - h1);
}
// fp16 hi/lo split (for v)
__device__ __forceinline__ void split2h(float x0, float x1, uint32_t& h, uint32_t& l) {
    __half2 hh = __floats2half2_rn(x0, x1);
    float2 hf = __half22float2(hh);
    __half2 ll = __floats2half2_rn(x0 - hf.x, x1 - hf.y);
    h = *(uint32_t*)&hh;
    l = *(uint32_t*)&ll;
}
__device__ __forceinline__ uint32_t hpack(float a, float b) {
    uint32_t r;
    asm("cvt.rn.f16x2.f32 %0, %1, %2;" : "=r"(r) : "f"(b), "f"(a));
    return r;
}
__device__ __forceinline__ void ldsm_x4(uint32_t& r0, uint32_t& r1, uint32_t& r2,
                                        uint32_t& r3, uint32_t addr) {
    asm volatile("ldmatrix.sync.aligned.m8n8.x4.shared.b16 {%0,%1,%2,%3}, [%4];"
                 : "=r"(r0), "=r"(r1), "=r"(r2), "=r"(r3) : "r"(addr));
}
__device__ __forceinline__ void mma16816(float* c, const uint32_t* a, const uint32_t* b) {
    asm volatile("mma.sync.aligned.m16n8k16.row.col.f32.bf16.bf16.f32 "
                 "{%0,%1,%2,%3}, {%4,%5,%6,%7}, {%8,%9}, {%0,%1,%2,%3};"
                 : "+f"(c[0]), "+f"(c[1]), "+f"(c[2]), "+f"(c[3])
                 : "r"(a[0]), "r"(a[1]), "r"(a[2]), "r"(a[3]), "r"(b[0]), "r"(b[1]));
}
__device__ __forceinline__ void mma16816h(float* c, const uint32_t* a, const uint32_t* b) {
    asm volatile("mma.sync.aligned.m16n8k16.row.col.f32.f16.f16.f32 "
                 "{%0,%1,%2,%3}, {%4,%5,%6,%7}, {%8,%9}, {%0,%1,%2,%3};"
                 : "+f"(c[0]), "+f"(c[1]), "+f"(c[2]), "+f"(c[3])
                 : "r"(a[0]), "r"(a[1]), "r"(a[2]), "r"(a[3]), "r"(b[0]), "r"(b[1]));
}
#define CP_ASYNC16(dst, src) \
    asm volatile("cp.async.cg.shared.global [%0], [%1], 16;" :: "r"(dst), "l"(src))
#define CP_COMMIT()  asm volatile("cp.async.commit_group;" ::: "memory")
#define CP_WAIT(n)   asm volatile("cp.async.wait_group %0;" :: "n"(n) : "memory")

// ===========================================================================
// pack mask -> bitmask
// ===========================================================================
__global__ void __launch_bounds__(256) mask_pack_kernel(const int* __restrict__ mask)
{
    const int gw = (blockIdx.x * 256 + threadIdx.x) >> 5;
    const int l  = threadIdx.x & 31;
    const int nwarps = gridDim.x * 8;
    const int nwords = SEQ * (SEQ / 32);
    for (int w = gw; w < nwords; w += nwarps) {
        const int row = w >> 6, wc = w & 63;
        int v = mask[(size_t)row * SEQ + wc * 32 + l];
        uint32_t bits = __ballot_sync(~0u, v != 0);
        if (l == 0) g_maskbits[w] = bits;
    }
}

// ===========================================================================
// split q AND k into bf16 hi/lo (one launch, gridDim.y = 2)
// ===========================================================================
__global__ void __launch_bounds__(256) split_qk_kernel(
    const float4* __restrict__ q, const float4* __restrict__ k)
{
    const int isK = blockIdx.y;
    const float4* src = isK ? k : q;
    uint2* hi = (uint2*)(isK ? g_khi : g_qhi);
    uint2* lo = (uint2*)(isK ? g_klo : g_qlo);
    const int n = BATCH * SEQ * HD / 4;
    const int stride = gridDim.x * blockDim.x;
    for (int c = blockIdx.x * blockDim.x + threadIdx.x; c < n; c += stride) {
        float4 x = src[c];
        uint32_t h01, l01, h23, l23;
        split2(x.x, x.y, h01, l01);
        split2(x.z, x.w, h23, l23);
        hi[c] = make_uint2(h01, h23);
        lo[c] = make_uint2(l01, l23);
    }
}

// ===========================================================================
// transpose + split v -> fp16 hi/lo: vT[b][d][t]
// ===========================================================================
__global__ void __launch_bounds__(256) split_v_kernel(const float* __restrict__ v)
{
    __shared__ float sm[64][129];
    const int tid = threadIdx.x;
    const int b = blockIdx.y, t0 = blockIdx.x * 128;
    const float* vb = v + (size_t)b * SEQ * HD;

#pragma unroll
    for (int i = 0; i < 8; ++i) {
        int chunk = tid + i * 256;
        int t = chunk >> 4, d4 = (chunk & 15) * 4;
        float4 x = *(const float4*)(vb + (size_t)(t0 + t) * HD + d4);
        sm[d4 + 0][t] = x.x; sm[d4 + 1][t] = x.y;
        sm[d4 + 2][t] = x.z; sm[d4 + 3][t] = x.w;
    }
    __syncthreads();

    const int r = tid >> 2, tb = (tid & 3) * 32;
    size_t obase = ((size_t)(b * 64 + r)) * SEQ + t0 + tb;
#pragma unroll
    for (int seg = 0; seg < 4; ++seg) {
        uint32_t h[4], l[4];
#pragma unroll
        for (int j = 0; j < 4; ++j) {
            float x0 = sm[r][tb + seg * 8 + j * 2];
            float x1 = sm[r][tb + seg * 8 + j * 2 + 1];
            split2h(x0, x1, h[j], l[j]);
        }
        *(uint4*)(g_vhi + obase + seg * 8) = make_uint4(h[0], h[1], h[2], h[3]);
        *(uint4*)(g_vlo + obase + seg * 8) = make_uint4(l[0], l[1], l[2], l[3]);
    }
}

// ===========================================================================
// scores: e = maskbit ? exp((QK^T)/8) : 0 -> attn; coltile row sums -> g_part
// ===========================================================================
__global__ void __launch_bounds__(256, 2) scores_mma_kernel(float* __restrict__ attn)
{
    extern __shared__ char smem[];
    constexpr int AHI = 0, ALO = 16384, BHI = 32768, BLO = 49152;
    const uint32_t sb = smem_u32(smem);
    const int tid = threadIdx.x, wid = tid >> 5, l = tid & 31;
    const int b = blockIdx.z, row0 = blockIdx.y * 128, col0 = blockIdx.x * 128;

    {
        const __nv_bfloat16* srcs[4] = {
            g_qhi + ((size_t)(b * SEQ) + row0) * HD,
            g_qlo + ((size_t)(b * SEQ) + row0) * HD,
            g_khi + ((size_t)(b * SEQ) + col0) * HD,
            g_klo + ((size_t)(b * SEQ) + col0) * HD };
        const int offs[4] = { AHI, ALO, BHI, BLO };
#pragma unroll
        for (int t = 0; t < 4; ++t) {
#pragma unroll
            for (int i = 0; i < 4; ++i) {
                int chunk = tid + i * 256;
                int r = chunk >> 3, c = chunk & 7;
                *(uint4*)(smem + offs[t] + r * 128 + ((c ^ (r & 7)) << 4)) =
                    *(const uint4*)(srcs[t] + (size_t)r * HD + c * 8);
            }
        }
    }
    __syncthreads();

    const int wm = wid >> 2, wn = wid & 3;           // 2 x 4 warps, tile 64x32
    float acc[4][4][4];
#pragma unroll
    for (int i = 0; i < 4; ++i)
#pragma unroll
        for (int j = 0; j < 4; ++j)
#pragma unroll
            for (int k = 0; k < 4; ++k) acc[i][j][k] = 0.f;

    // pass 1: Ahi * (Bhi + Blo)
#pragma unroll
    for (int ks = 0; ks < 4; ++ks) {
        uint32_t a[4][4];
#pragma unroll
        for (int mt = 0; mt < 4; ++mt) {
            int r = wm * 64 + mt * 16 + (l & 15);
            int c = 2 * ks + (l >> 4);
            ldsm_x4(a[mt][0], a[mt][1], a[mt][2], a[mt][3],
                    sb + AHI + r * 128 + ((c ^ (r & 7)) << 4));
        }
        uint32_t bh[4][2], bl[4][2];
#pragma unroll
        for (int j = 0; j < 2; ++j) {
            int n = wn * 32 + j * 16 + (l & 7) + ((l >> 4) << 3);
            int c = 2 * ks + ((l >> 3) & 1);
            uint32_t t0, t1, t2, t3;
            ldsm_x4(t0, t1, t2, t3, sb + BHI + n * 128 + ((c ^ (n & 7)) << 4));
            bh[j*2][0] = t0; bh[j*2][1] = t1; bh[j*2+1][0] = t2; bh[j*2+1][1] = t3;
            ldsm_x4(t0, t1, t2, t3, sb + BLO + n * 128 + ((c ^ (n & 7)) << 4));
            bl[j*2][0] = t0; bl[j*2][1] = t1; bl[j*2+1][0] = t2; bl[j*2+1][1] = t3;
        }
#pragma unroll
        for (int mt = 0; mt < 4; ++mt)
#pragma unroll
            for (int nt = 0; nt < 4; ++nt) {
                mma16816(acc[mt][nt], a[mt], bh[nt]);
                mma16816(acc[mt][nt], a[mt], bl[nt]);
            }
    }
    // pass 2: Alo * Bhi
#pragma unroll
    for (int ks = 0; ks < 4; ++ks) {
        uint32_t a[4][4];
#pragma unroll
        for (int mt = 0; mt < 4; ++mt) {
            int r = wm * 64 + mt * 16 + (l & 15);
            int c = 2 * ks + (l >> 4);
            ldsm_x4(a[mt][0], a[mt][1], a[mt][2], a[mt][3],
                    sb + ALO + r * 128 + ((c ^ (r & 7)) << 4));
        }
        uint32_t bh[4][2];
#pragma unroll
        for (int j = 0; j < 2; ++j) {
            int n = wn * 32 + j * 16 + (l & 7) + ((l >> 4) << 3);
            int c = 2 * ks + ((l >> 3) & 1);
            uint32_t t0, t1, t2, t3;
            ldsm_x4(t0, t1, t2, t3, sb + BHI + n * 128 + ((c ^ (n & 7)) << 4));
            bh[j*2][0] = t0; bh[j*2][1] = t1; bh[j*2+1][0] = t2; bh[j*2+1][1] = t3;
        }
#pragma unroll
        for (int mt = 0; mt < 4; ++mt)
#pragma unroll
            for (int nt = 0; nt < 4; ++nt)
                mma16816(acc[mt][nt], a[mt], bh[nt]);
    }

    __syncthreads();
    float* srow = (float*)smem;      // [4][128]

    float rs[4][2];
#pragma unroll
    for (int mt = 0; mt < 4; ++mt) { rs[mt][0] = 0.f; rs[mt][1] = 0.f; }

    const int wbase = (col0 >> 5) + wn;
#pragma unroll
    for (int mt = 0; mt < 4; ++mt) {
#pragma unroll
        for (int h = 0; h < 2; ++h) {
            const int s = row0 + wm * 64 + mt * 16 + (l >> 2) + h * 8;
            const uint32_t w = g_maskbits[(size_t)s * 64 + wbase];
            float* drow = attn + ((size_t)(b * SEQ) + s) * SEQ + col0 + wn * 32;
            const int sh0 = 2 * (l & 3);
#pragma unroll
            for (int nt = 0; nt < 4; ++nt) {
                const uint32_t bits = w >> (nt * 8 + sh0);
                float e0 = (bits & 1u) ? __expf(acc[mt][nt][h * 2 + 0] * 0.125f) : 0.f;
                float e1 = (bits & 2u) ? __expf(acc[mt][nt][h * 2 + 1] * 0.125f) : 0.f;
                *(float2*)(drow + nt * 8 + sh0) = make_float2(e0, e1);
                rs[mt][h] += e0 + e1;
            }
        }
    }
#pragma unroll
    for (int mt = 0; mt < 4; ++mt)
#pragma unroll
        for (int h = 0; h < 2; ++h) {
            float v = rs[mt][h];
            v += __shfl_xor_sync(~0u, v, 1);
            v += __shfl_xor_sync(~0u, v, 2);
            rs[mt][h] = v;
        }
    if ((l & 3) == 0) {
#pragma unroll
        for (int mt = 0; mt < 4; ++mt)
#pragma unroll
            for (int h = 0; h < 2; ++h)
                srow[wn * 128 + wm * 64 + mt * 16 + (l >> 2) + h * 8] = rs[mt][h];
    }
    __syncthreads();
    if (tid < 128) {
        float s = srow[tid] + srow[128 + tid] + srow[256 + tid] + srow[384 + tid];
        g_part[((size_t)(b * SEQ) + row0 + tid) * 16 + blockIdx.x] = s;
    }
}

// ===========================================================================
// pv: 64-row tiles (512 CTAs). e staged via cp.async; transform: p = e*inv,
// write p back (final attn), p -> fp16 single A tile; out = p@vhi + p@vlo
// (fp16 MMA, fp32 accum). smem: EST 2x17408 | A 8K | B 2x16K | sinv
// ===========================================================================
__global__ void __launch_bounds__(256) pv_mma_kernel(
    float* __restrict__ attn, float* __restrict__ out)
{
    extern __shared__ char smem[];
    constexpr int EST = 0, ESTRIDE = 17408;                 // 64 rows * 272B
    constexpr int AP = 34816, BB = 43008, SINV = 75776;
    const uint32_t sb = smem_u32(smem);
    const int tid = threadIdx.x, wid = tid >> 5, l = tid & 31;
    const int b = blockIdx.y, row0 = blockIdx.x * 64;

    float* sinv = (float*)(smem + SINV);
    if (tid < 64) {
        const float4* pp = (const float4*)(g_part + ((size_t)(b * SEQ) + row0 + tid) * 16);
        float4 p0 = pp[0], p1 = pp[1], p2 = pp[2], p3 = pp[3];
        float s = ((p0.x + p0.y) + (p0.z + p0.w)) + ((p1.x + p1.y) + (p1.z + p1.w)) +
                  ((p2.x + p2.y) + (p2.z + p2.w)) + ((p3.x + p3.y) + (p3.z + p3.w));
        sinv[tid] = 1.0f / s;
    }

    const __half* vhi = g_vhi + (size_t)(b * 64) * SEQ;
    const __half* vlo = g_vlo + (size_t)(b * 64) * SEQ;
    const float* arow = attn + ((size_t)(b * SEQ) + row0) * SEQ;

    // prologue: stage 0 of e-tile and B-tile
    {
#pragma unroll
        for (int i = 0; i < 4; ++i) {
            int chunk = tid + i * 256;                 // 1024 x 16B (e tile)
            int r = chunk >> 4, c = chunk & 15;
            CP_ASYNC16(sb + EST + r * 272 + c * 16, arow + (size_t)r * SEQ + c * 4);
        }
#pragma unroll
        for (int i = 0; i < 4; ++i) {
            int chunk = tid + i * 256;                 // 1024 x 16B (v hi+lo)
            int tb = chunk >> 9, rem = chunk & 511;
            int r = rem >> 3, c = rem & 7;
            uint32_t dst = sb + BB + tb * 8192 + r * 128 + ((c ^ (r & 7)) << 4);
            CP_ASYNC16(dst, (tb ? vlo : vhi) + (size_t)r * SEQ + c * 8);
        }
        CP_COMMIT();
    }

    const int wm = wid >> 1, wn = wid & 1;             // 4 x 2 warps, tile 16x32
    float acc[4][4];
#pragma unroll
    for (int j = 0; j < 4; ++j)
#pragma unroll
        for (int k = 0; k < 4; ++k) acc[j][k] = 0.f;

    for (int tile = 0; tile < 32; ++tile) {
        const int t0 = tile * 64;
        const int buf = tile & 1;

        CP_WAIT(0);
        __syncthreads();

        // prefetch next tile
        if (tile < 31) {
            const int nt0 = t0 + 64;
            const int nbuf = buf ^ 1;
#pragma unroll
            for (int i = 0; i < 4; ++i) {
                int chunk = tid + i * 256;
                int r = chunk >> 4, c = chunk & 15;
                CP_ASYNC16(sb + EST + nbuf * ESTRIDE + r * 272 + c * 16,
                           arow + (size_t)r * SEQ + nt0 + c * 4);
            }
#pragma unroll
            for (int i = 0; i < 4; ++i) {
                int chunk = tid + i * 256;
                int tb = chunk >> 9, rem = chunk & 511;
                int r = rem >> 3, c = rem & 7;
                uint32_t dst = sb + BB + nbuf * 16384 + tb * 8192 +
                               r * 128 + ((c ^ (r & 7)) << 4);
                CP_ASYNC16(dst, (tb ? vlo : vhi) + (size_t)r * SEQ + nt0 + c * 8);
            }
            CP_COMMIT();
        }

        // transform: e -> p (write back) + fp16 A tile
        const float* est = (const float*)(smem + EST + buf * ESTRIDE);
#pragma unroll
        for (int i = 0; i < 2; ++i) {
            int chunk = tid + i * 256;                 // 512 chunks of 8 floats
            int r = chunk >> 3, c = chunk & 7;
            const float* sp = est + r * 68 + c * 8;
            float4 x0 = *(const float4*)sp;
            float4 x1 = *(const float4*)(sp + 4);
            const float inv = sinv[r];
            x0.x *= inv; x0.y *= inv; x0.z *= inv; x0.w *= inv;
            x1.x *= inv; x1.y *= inv; x1.z *= inv; x1.w *= inv;
            float* gp = (float*)(arow + (size_t)r * SEQ + t0 + c * 8);
            *(float4*)gp = x0;
            *(float4*)(gp + 4) = x1;
            uint32_t p0 = hpack(x0.x, x0.y), p1 = hpack(x0.z, x0.w);
            uint32_t p2 = hpack(x1.x, x1.y), p3 = hpack(x1.z, x1.w);
            // A tile: 64 rows x 64 fp16 (128B rows); chunk c covers 16B
            uint32_t off = r * 128 + ((c ^ (r & 7)) << 4);
            *(uint4*)(smem + AP + off) = make_uint4(p0, p1, p2, p3);
        }
        __syncthreads();

        const uint32_t BHIc = sb + BB + buf * 16384;
        const uint32_t BLOc = BHIc + 8192;

        // single pass: P * (Vhi + Vlo), fp16 MMA
#pragma unroll
        for (int ks = 0; ks < 4; ++ks) {
            uint32_t a[4];
            {
                int r = wm * 16 + (l & 15);
                int c = 2 * ks + (l >> 4);
                ldsm_x4(a[0], a[1], a[2], a[3],
                        sb + AP + r * 128 + ((c ^ (r & 7)) << 4));
            }
            uint32_t bh[4][2], bl[4][2];
#pragma unroll
            for (int j = 0; j < 2; ++j) {
                int n = wn * 32 + j * 16 + (l & 7) + ((l >> 4) << 3);
                int c = 2 * ks + ((l >> 3) & 1);
                uint32_t t0r, t1r, t2r, t3r;
                ldsm_x4(t0r, t1r, t2r, t3r, BHIc + n * 128 + ((c ^ (n & 7)) << 4));
                bh[j*2][0] = t0r; bh[j*2][1] = t1r; bh[j*2+1][0] = t2r; bh[j*2+1][1] = t3r;
                ldsm_x4(t0r, t1r, t2r, t3r, BLOc + n * 128 + ((c ^ (n & 7)) << 4));
                bl[j*2][0] = t0r; bl[j*2][1] = t1r; bl[j*2+1][0] = t2r; bl[j*2+1][1] = t3r;
            }
#pragma unroll
            for (int nt = 0; nt < 4; ++nt) {
                mma16816h(acc[nt], a, bh[nt]);
                mma16816h(acc[nt], a, bl[nt]);
            }
        }
    }

    // epilogue
#pragma unroll
    for (int nt = 0; nt < 4; ++nt) {
        const int gc = wn * 32 + nt * 8 + 2 * (l & 3);
#pragma unroll
        for (int h = 0; h < 2; ++h) {
            const int gr = row0 + wm * 16 + (l >> 2) + h * 8;
            *(float2*)(out + ((size_t)(b * SEQ) + gr) * HD + gc) =
                make_float2(acc[nt][h * 2 + 0], acc[nt][h * 2 + 1]);
        }
    }
}

// ===========================================================================
extern "C" void kernel_launch(void* const* d_in, const int* in_sizes, int n_in,
                              void* d_out, int out_size)
{
    const float* q    = (const float*)d_in[0];
    const float* k    = (const float*)d_in[1];
    const float* v    = (const float*)d_in[2];
    const int*   mask = (const int*)d_in[3];

    float* out  = (float*)d_out;
    float* attn = out + (size_t)BATCH * SEQ * HD;

    cudaFuncSetAttribute(scores_mma_kernel,
                         cudaFuncAttributeMaxDynamicSharedMemorySize, 65536);
    cudaFuncSetAttribute(pv_mma_kernel,
                         cudaFuncAttributeMaxDynamicSharedMemorySize, 76032);

    mask_pack_kernel<<<512, 256>>>(mask);
    split_qk_kernel<<<dim3(256, 2), 256>>>((const float4*)q, (const float4*)k);
    split_v_kernel<<<dim3(SEQ / 128, BATCH), 256>>>(v);

    scores_mma_kernel<<<dim3(16, 16, BATCH), 256, 65536>>>(attn);
    pv_mma_kernel<<<dim3(32, BATCH), 256, 76032>>>(attn, out);
}

// round 8
// speedup vs baseline: 2.2471x; 1.0599x over previous
#include <cuda_runtime.h>
#include <cuda_bf16.h>
#include <cuda_fp16.h>
#include <cstdint>

#define SEQ   2048
#define HD    64
#define BATCH 16

// ---------------------------------------------------------------------------
// device scratch
// ---------------------------------------------------------------------------
__device__ __nv_bfloat16 g_qhi[BATCH * SEQ * HD];
__device__ __nv_bfloat16 g_qlo[BATCH * SEQ * HD];
__device__ __nv_bfloat16 g_khi[BATCH * SEQ * HD];
__device__ __nv_bfloat16 g_klo[BATCH * SEQ * HD];
__device__ __half        g_vhi[BATCH * HD * SEQ];   // transposed [b][d][t], fp16
__device__ float         g_part[BATCH * SEQ * 16];  // per-row per-coltile exp sums
__device__ uint32_t      g_maskbits[SEQ * (SEQ / 32)];

// ---------------------------------------------------------------------------
// helpers
// ---------------------------------------------------------------------------
__device__ __forceinline__ uint32_t smem_u32(const void* p) {
    uint32_t a;
    asm("{ .reg .u64 t; cvta.to.shared.u64 t, %1; cvt.u32.u64 %0, t; }" : "=r"(a) : "l"(p));
    return a;
}
__device__ __forceinline__ uint32_t bfpack(float a, float b) {
    uint32_t r;
    asm("cvt.rn.bf16x2.f32 %0, %1, %2;" : "=r"(r) : "f"(b), "f"(a));
    return r;
}
__device__ __forceinline__ void split2(float x0, float x1, uint32_t& h, uint32_t& l) {
    h = bfpack(x0, x1);
    float h0 = __uint_as_float(h << 16);
    float h1 = __uint_as_float(h & 0xffff0000u);
    l = bfpack(x0 - h0, x1 - h1);
}
__device__ __forceinline__ uint32_t hpack(float a, float b) {
    uint32_t r;
    asm("cvt.rn.f16x2.f32 %0, %1, %2;" : "=r"(r) : "f"(b), "f"(a));
    return r;
}
__device__ __forceinline__ void ldsm_x4(uint32_t& r0, uint32_t& r1, uint32_t& r2,
                                        uint32_t& r3, uint32_t addr) {
    asm volatile("ldmatrix.sync.aligned.m8n8.x4.shared.b16 {%0,%1,%2,%3}, [%4];"
                 : "=r"(r0), "=r"(r1), "=r"(r2), "=r"(r3) : "r"(addr));
}
__device__ __forceinline__ void mma16816(float* c, const uint32_t* a, const uint32_t* b) {
    asm volatile("mma.sync.aligned.m16n8k16.row.col.f32.bf16.bf16.f32 "
                 "{%0,%1,%2,%3}, {%4,%5,%6,%7}, {%8,%9}, {%0,%1,%2,%3};"
                 : "+f"(c[0]), "+f"(c[1]), "+f"(c[2]), "+f"(c[3])
                 : "r"(a[0]), "r"(a[1]), "r"(a[2]), "r"(a[3]), "r"(b[0]), "r"(b[1]));
}
__device__ __forceinline__ void mma16816h(float* c, const uint32_t* a, const uint32_t* b) {
    asm volatile("mma.sync.aligned.m16n8k16.row.col.f32.f16.f16.f32 "
                 "{%0,%1,%2,%3}, {%4,%5,%6,%7}, {%8,%9}, {%0,%1,%2,%3};"
                 : "+f"(c[0]), "+f"(c[1]), "+f"(c[2]), "+f"(c[3])
                 : "r"(a[0]), "r"(a[1]), "r"(a[2]), "r"(a[3]), "r"(b[0]), "r"(b[1]));
}
#define CP_ASYNC16(dst, src) \
    asm volatile("cp.async.cg.shared.global [%0], [%1], 16;" :: "r"(dst), "l"(src))
#define CP_COMMIT()  asm volatile("cp.async.commit_group;" ::: "memory")
#define CP_WAIT(n)   asm volatile("cp.async.wait_group %0;" :: "n"(n) : "memory")

// ===========================================================================
// fused prep: y=0 mask pack | y=1 q/k bf16 hi-lo split | y=2 v transpose+fp16
// ===========================================================================
__global__ void __launch_bounds__(256) prep_kernel(
    const float4* __restrict__ q, const float4* __restrict__ k,
    const float* __restrict__ v, const int* __restrict__ mask)
{
    __shared__ float sm[64][129];            // used only by y == 2
    const int tid = threadIdx.x;

    if (blockIdx.y == 0) {
        // ---- mask -> bitmask
        const int gw = (blockIdx.x * 256 + tid) >> 5;
        const int l  = tid & 31;
        const int nwarps = gridDim.x * 8;
        const int nwords = SEQ * (SEQ / 32);
        for (int w = gw; w < nwords; w += nwarps) {
            const int row = w >> 6, wc = w & 63;
            int mv = mask[(size_t)row * SEQ + wc * 32 + l];
            uint32_t bits = __ballot_sync(~0u, mv != 0);
            if (l == 0) g_maskbits[w] = bits;
        }
    } else if (blockIdx.y == 1) {
        // ---- split q (x < 256) or k (x >= 256)
        const int isK = blockIdx.x >= 256;
        const float4* src = isK ? k : q;
        uint2* hi = (uint2*)(isK ? g_khi : g_qhi);
        uint2* lo = (uint2*)(isK ? g_klo : g_qlo);
        const int n = BATCH * SEQ * HD / 4;
        const int stride = 256 * 256;
        for (int c = (blockIdx.x & 255) * 256 + tid; c < n; c += stride) {
            float4 x = src[c];
            uint32_t h01, l01, h23, l23;
            split2(x.x, x.y, h01, l01);
            split2(x.z, x.w, h23, l23);
            hi[c] = make_uint2(h01, h23);
            lo[c] = make_uint2(l01, l23);
        }
    } else {
        // ---- v: transpose + fp16 (256 blocks: b = x>>4, t0 = (x&15)*128)
        if (blockIdx.x >= 256) return;
        const int b = blockIdx.x >> 4, t0 = (blockIdx.x & 15) * 128;
        const float* vb = v + (size_t)b * SEQ * HD;
#pragma unroll
        for (int i = 0; i < 8; ++i) {
            int chunk = tid + i * 256;
            int t = chunk >> 4, d4 = (chunk & 15) * 4;
            float4 x = *(const float4*)(vb + (size_t)(t0 + t) * HD + d4);
            sm[d4 + 0][t] = x.x; sm[d4 + 1][t] = x.y;
            sm[d4 + 2][t] = x.z; sm[d4 + 3][t] = x.w;
        }
        __syncthreads();
        const int r = tid >> 2, tb = (tid & 3) * 32;
        size_t obase = ((size_t)(b * 64 + r)) * SEQ + t0 + tb;
#pragma unroll
        for (int seg = 0; seg < 4; ++seg) {
            uint32_t h[4];
#pragma unroll
            for (int j = 0; j < 4; ++j)
                h[j] = hpack(sm[r][tb + seg * 8 + j * 2],
                             sm[r][tb + seg * 8 + j * 2 + 1]);
            *(uint4*)(g_vhi + obase + seg * 8) = make_uint4(h[0], h[1], h[2], h[3]);
        }
    }
}

// ===========================================================================
// scores: e = maskbit ? exp((QK^T)/8) : 0 -> attn; coltile row sums -> g_part
// single merged k-loop: Ahi*(Bhi+Blo) then Alo*Bhi (Bhi kept live)
// ===========================================================================
__global__ void __launch_bounds__(256, 2) scores_mma_kernel(float* __restrict__ attn)
{
    extern __shared__ char smem[];
    constexpr int AHI = 0, ALO = 16384, BHI = 32768, BLO = 49152;
    const uint32_t sb = smem_u32(smem);
    const int tid = threadIdx.x, wid = tid >> 5, l = tid & 31;
    const int b = blockIdx.z, row0 = blockIdx.y * 128, col0 = blockIdx.x * 128;

    {
        const __nv_bfloat16* srcs[4] = {
            g_qhi + ((size_t)(b * SEQ) + row0) * HD,
            g_qlo + ((size_t)(b * SEQ) + row0) * HD,
            g_khi + ((size_t)(b * SEQ) + col0) * HD,
            g_klo + ((size_t)(b * SEQ) + col0) * HD };
        const int offs[4] = { AHI, ALO, BHI, BLO };
#pragma unroll
        for (int t = 0; t < 4; ++t) {
#pragma unroll
            for (int i = 0; i < 4; ++i) {
                int chunk = tid + i * 256;
                int r = chunk >> 3, c = chunk & 7;
                *(uint4*)(smem + offs[t] + r * 128 + ((c ^ (r & 7)) << 4)) =
                    *(const uint4*)(srcs[t] + (size_t)r * HD + c * 8);
            }
        }
    }
    __syncthreads();

    const int wm = wid >> 2, wn = wid & 3;           // 2 x 4 warps, tile 64x32
    float acc[4][4][4];
#pragma unroll
    for (int i = 0; i < 4; ++i)
#pragma unroll
        for (int j = 0; j < 4; ++j)
#pragma unroll
            for (int k = 0; k < 4; ++k) acc[i][j][k] = 0.f;

#pragma unroll
    for (int ks = 0; ks < 4; ++ks) {
        uint32_t a[4][4];
#pragma unroll
        for (int mt = 0; mt < 4; ++mt) {
            int r = wm * 64 + mt * 16 + (l & 15);
            int c = 2 * ks + (l >> 4);
            ldsm_x4(a[mt][0], a[mt][1], a[mt][2], a[mt][3],
                    sb + AHI + r * 128 + ((c ^ (r & 7)) << 4));
        }
        uint32_t bh[4][2], bl[4][2];
#pragma unroll
        for (int j = 0; j < 2; ++j) {
            int n = wn * 32 + j * 16 + (l & 7) + ((l >> 4) << 3);
            int c = 2 * ks + ((l >> 3) & 1);
            uint32_t t0, t1, t2, t3;
            ldsm_x4(t0, t1, t2, t3, sb + BHI + n * 128 + ((c ^ (n & 7)) << 4));
            bh[j*2][0] = t0; bh[j*2][1] = t1; bh[j*2+1][0] = t2; bh[j*2+1][1] = t3;
            ldsm_x4(t0, t1, t2, t3, sb + BLO + n * 128 + ((c ^ (n & 7)) << 4));
            bl[j*2][0] = t0; bl[j*2][1] = t1; bl[j*2+1][0] = t2; bl[j*2+1][1] = t3;
        }
#pragma unroll
        for (int mt = 0; mt < 4; ++mt)
#pragma unroll
            for (int nt = 0; nt < 4; ++nt) {
                mma16816(acc[mt][nt], a[mt], bh[nt]);
                mma16816(acc[mt][nt], a[mt], bl[nt]);
            }
        // reuse a[] for Alo; bh still live
#pragma unroll
        for (int mt = 0; mt < 4; ++mt) {
            int r = wm * 64 + mt * 16 + (l & 15);
            int c = 2 * ks + (l >> 4);
            ldsm_x4(a[mt][0], a[mt][1], a[mt][2], a[mt][3],
                    sb + ALO + r * 128 + ((c ^ (r & 7)) << 4));
        }
#pragma unroll
        for (int mt = 0; mt < 4; ++mt)
#pragma unroll
            for (int nt = 0; nt < 4; ++nt)
                mma16816(acc[mt][nt], a[mt], bh[nt]);
    }

    __syncthreads();
    float* srow = (float*)smem;      // [4][128]

    float rs[4][2];
#pragma unroll
    for (int mt = 0; mt < 4; ++mt) { rs[mt][0] = 0.f; rs[mt][1] = 0.f; }

    const int wbase = (col0 >> 5) + wn;
#pragma unroll
    for (int mt = 0; mt < 4; ++mt) {
#pragma unroll
        for (int h = 0; h < 2; ++h) {
            const int s = row0 + wm * 64 + mt * 16 + (l >> 2) + h * 8;
            const uint32_t w = g_maskbits[(size_t)s * 64 + wbase];
            float* drow = attn + ((size_t)(b * SEQ) + s) * SEQ + col0 + wn * 32;
            const int sh0 = 2 * (l & 3);
#pragma unroll
            for (int nt = 0; nt < 4; ++nt) {
                const uint32_t bits = w >> (nt * 8 + sh0);
                float e0 = (bits & 1u) ? __expf(acc[mt][nt][h * 2 + 0] * 0.125f) : 0.f;
                float e1 = (bits & 2u) ? __expf(acc[mt][nt][h * 2 + 1] * 0.125f) : 0.f;
                __stcs((float2*)(drow + nt * 8 + sh0), make_float2(e0, e1));
                rs[mt][h] += e0 + e1;
            }
        }
    }
#pragma unroll
    for (int mt = 0; mt < 4; ++mt)
#pragma unroll
        for (int h = 0; h < 2; ++h) {
            float v = rs[mt][h];
            v += __shfl_xor_sync(~0u, v, 1);
            v += __shfl_xor_sync(~0u, v, 2);
            rs[mt][h] = v;
        }
    if ((l & 3) == 0) {
#pragma unroll
        for (int mt = 0; mt < 4; ++mt)
#pragma unroll
            for (int h = 0; h < 2; ++h)
                srow[wn * 128 + wm * 64 + mt * 16 + (l >> 2) + h * 8] = rs[mt][h];
    }
    __syncthreads();
    if (tid < 128) {
        float s = srow[tid] + srow[128 + tid] + srow[256 + tid] + srow[384 + tid];
        g_part[((size_t)(b * SEQ) + row0 + tid) * 16 + blockIdx.x] = s;
    }
}

// ===========================================================================
// pv: 64-row tiles (512 CTAs). e staged via cp.async; transform: p = e*inv,
// write p back (final attn), p -> fp16 A tile; out = p @ vhi (fp16 MMA).
// smem: EST 2x17408 | A 8K | B 2x8K | sinv
// ===========================================================================
__global__ void __launch_bounds__(256) pv_mma_kernel(
    float* __restrict__ attn, float* __restrict__ out)
{
    extern __shared__ char smem[];
    constexpr int EST = 0, ESTRIDE = 17408;                 // 64 rows * 272B
    constexpr int AP = 34816, BB = 43008, SINV = 59392;
    const uint32_t sb = smem_u32(smem);
    const int tid = threadIdx.x, wid = tid >> 5, l = tid & 31;
    const int b = blockIdx.y, row0 = blockIdx.x * 64;

    float* sinv = (float*)(smem + SINV);
    if (tid < 64) {
        const float4* pp = (const float4*)(g_part + ((size_t)(b * SEQ) + row0 + tid) * 16);
        float4 p0 = pp[0], p1 = pp[1], p2 = pp[2], p3 = pp[3];
        float s = ((p0.x + p0.y) + (p0.z + p0.w)) + ((p1.x + p1.y) + (p1.z + p1.w)) +
                  ((p2.x + p2.y) + (p2.z + p2.w)) + ((p3.x + p3.y) + (p3.z + p3.w));
        sinv[tid] = 1.0f / s;
    }

    const __half* vhi = g_vhi + (size_t)(b * 64) * SEQ;
    const float* arow = attn + ((size_t)(b * SEQ) + row0) * SEQ;

    // prologue: stage 0 of e-tile and B-tile
    {
#pragma unroll
        for (int i = 0; i < 4; ++i) {
            int chunk = tid + i * 256;                 // 1024 x 16B (e tile)
            int r = chunk >> 4, c = chunk & 15;
            CP_ASYNC16(sb + EST + r * 272 + c * 16, arow + (size_t)r * SEQ + c * 4);
        }
#pragma unroll
        for (int i = 0; i < 2; ++i) {
            int chunk = tid + i * 256;                 // 512 x 16B (v)
            int r = chunk >> 3, c = chunk & 7;
            uint32_t dst = sb + BB + r * 128 + ((c ^ (r & 7)) << 4);
            CP_ASYNC16(dst, vhi + (size_t)r * SEQ + c * 8);
        }
        CP_COMMIT();
    }

    const int wm = wid >> 1, wn = wid & 1;             // 4 x 2 warps, tile 16x32
    float acc[4][4];
#pragma unroll
    for (int j = 0; j < 4; ++j)
#pragma unroll
        for (int k = 0; k < 4; ++k) acc[j][k] = 0.f;

    for (int tile = 0; tile < 32; ++tile) {
        const int t0 = tile * 64;
        const int buf = tile & 1;

        CP_WAIT(0);
        __syncthreads();

        // prefetch next tile
        if (tile < 31) {
            const int nt0 = t0 + 64;
            const int nbuf = buf ^ 1;
#pragma unroll
            for (int i = 0; i < 4; ++i) {
                int chunk = tid + i * 256;
                int r = chunk >> 4, c = chunk & 15;
                CP_ASYNC16(sb + EST + nbuf * ESTRIDE + r * 272 + c * 16,
                           arow + (size_t)r * SEQ + nt0 + c * 4);
            }
#pragma unroll
            for (int i = 0; i < 2; ++i) {
                int chunk = tid + i * 256;
                int r = chunk >> 3, c = chunk & 7;
                uint32_t dst = sb + BB + nbuf * 8192 + r * 128 + ((c ^ (r & 7)) << 4);
                CP_ASYNC16(dst, vhi + (size_t)r * SEQ + nt0 + c * 8);
            }
            CP_COMMIT();
        }

        // transform: e -> p (write back, streaming) + fp16 A tile
        const float* est = (const float*)(smem + EST + buf * ESTRIDE);
#pragma unroll
        for (int i = 0; i < 2; ++i) {
            int chunk = tid + i * 256;                 // 512 chunks of 8 floats
            int r = chunk >> 3, c = chunk & 7;
            const float* sp = est + r * 68 + c * 8;
            float4 x0 = *(const float4*)sp;
            float4 x1 = *(const float4*)(sp + 4);
            const float inv = sinv[r];
            x0.x *= inv; x0.y *= inv; x0.z *= inv; x0.w *= inv;
            x1.x *= inv; x1.y *= inv; x1.z *= inv; x1.w *= inv;
            float* gp = (float*)(arow + (size_t)r * SEQ + t0 + c * 8);
            __stcs((float4*)gp, x0);
            __stcs((float4*)(gp + 4), x1);
            uint32_t p0 = hpack(x0.x, x0.y), p1 = hpack(x0.z, x0.w);
            uint32_t p2 = hpack(x1.x, x1.y), p3 = hpack(x1.z, x1.w);
            uint32_t off = r * 128 + ((c ^ (r & 7)) << 4);
            *(uint4*)(smem + AP + off) = make_uint4(p0, p1, p2, p3);
        }
        __syncthreads();

        const uint32_t Bc = sb + BB + buf * 8192;

        // P * Vhi, fp16 MMA
#pragma unroll
        for (int ks = 0; ks < 4; ++ks) {
            uint32_t a[4];
            {
                int r = wm * 16 + (l & 15);
                int c = 2 * ks + (l >> 4);
                ldsm_x4(a[0], a[1], a[2], a[3],
                        sb + AP + r * 128 + ((c ^ (r & 7)) << 4));
            }
            uint32_t bh[4][2];
#pragma unroll
            for (int j = 0; j < 2; ++j) {
                int n = wn * 32 + j * 16 + (l & 7) + ((l >> 4) << 3);
                int c = 2 * ks + ((l >> 3) & 1);
                uint32_t t0r, t1r, t2r, t3r;
                ldsm_x4(t0r, t1r, t2r, t3r, Bc + n * 128 + ((c ^ (n & 7)) << 4));
                bh[j*2][0] = t0r; bh[j*2][1] = t1r; bh[j*2+1][0] = t2r; bh[j*2+1][1] = t3r;
            }
#pragma unroll
            for (int nt = 0; nt < 4; ++nt)
                mma16816h(acc[nt], a, bh[nt]);
        }
    }

    // epilogue
#pragma unroll
    for (int nt = 0; nt < 4; ++nt) {
        const int gc = wn * 32 + nt * 8 + 2 * (l & 3);
#pragma unroll
        for (int h = 0; h < 2; ++h) {
            const int gr = row0 + wm * 16 + (l >> 2) + h * 8;
            *(float2*)(out + ((size_t)(b * SEQ) + gr) * HD + gc) =
                make_float2(acc[nt][h * 2 + 0], acc[nt][h * 2 + 1]);
        }
    }
}

// ===========================================================================
extern "C" void kernel_launch(void* const* d_in, const int* in_sizes, int n_in,
                              void* d_out, int out_size)
{
    const float* q    = (const float*)d_in[0];
    const float* k    = (const float*)d_in[1];
    const float* v    = (const float*)d_in[2];
    const int*   mask = (const int*)d_in[3];

    float* out  = (float*)d_out;
    float* attn = out + (size_t)BATCH * SEQ * HD;

    cudaFuncSetAttribute(scores_mma_kernel,
                         cudaFuncAttributeMaxDynamicSharedMemorySize, 65536);
    cudaFuncSetAttribute(pv_mma_kernel,
                         cudaFuncAttributeMaxDynamicSharedMemorySize, 59648);

    prep_kernel<<<dim3(512, 3), 256>>>((const float4*)q, (const float4*)k, v, mask);

    scores_mma_kernel<<<dim3(16, 16, BATCH), 256, 65536>>>(attn);
    pv_mma_kernel<<<dim3(32, BATCH), 256, 59648>>>(attn, out);
}

// round 9
// speedup vs baseline: 2.3751x; 1.0570x over previous
#include <cuda_runtime.h>
#include <cuda_fp16.h>
#include <cstdint>

#define SEQ   2048
#define HD    64
#define BATCH 16

// ---------------------------------------------------------------------------
// device scratch
// ---------------------------------------------------------------------------
__device__ __half    g_qh[BATCH * SEQ * HD];        // fp16(q)
__device__ __half    g_kh[BATCH * SEQ * HD];        // fp16(k)
__device__ __half    g_kl[BATCH * SEQ * HD];        // fp16(k - fp16(k))
__device__ __half    g_vh[BATCH * HD * SEQ];        // transposed [b][d][t], fp16
__device__ float     g_part[BATCH * SEQ * 16];      // per-row per-coltile exp sums
__device__ uint32_t  g_maskbits[SEQ * (SEQ / 32)];

// ---------------------------------------------------------------------------
// helpers
// ---------------------------------------------------------------------------
__device__ __forceinline__ uint32_t smem_u32(const void* p) {
    uint32_t a;
    asm("{ .reg .u64 t; cvta.to.shared.u64 t, %1; cvt.u32.u64 %0, t; }" : "=r"(a) : "l"(p));
    return a;
}
__device__ __forceinline__ uint32_t hpack(float a, float b) {
    uint32_t r;
    asm("cvt.rn.f16x2.f32 %0, %1, %2;" : "=r"(r) : "f"(b), "f"(a));
    return r;
}
__device__ __forceinline__ void split2h(float x0, float x1, uint32_t& h, uint32_t& l) {
    __half2 hh = __floats2half2_rn(x0, x1);
    float2 hf = __half22float2(hh);
    __half2 ll = __floats2half2_rn(x0 - hf.x, x1 - hf.y);
    h = *(uint32_t*)&hh;
    l = *(uint32_t*)&ll;
}
__device__ __forceinline__ void ldsm_x4(uint32_t& r0, uint32_t& r1, uint32_t& r2,
                                        uint32_t& r3, uint32_t addr) {
    asm volatile("ldmatrix.sync.aligned.m8n8.x4.shared.b16 {%0,%1,%2,%3}, [%4];"
                 : "=r"(r0), "=r"(r1), "=r"(r2), "=r"(r3) : "r"(addr));
}
__device__ __forceinline__ void mma16816h(float* c, const uint32_t* a, const uint32_t* b) {
    asm volatile("mma.sync.aligned.m16n8k16.row.col.f32.f16.f16.f32 "
                 "{%0,%1,%2,%3}, {%4,%5,%6,%7}, {%8,%9}, {%0,%1,%2,%3};"
                 : "+f"(c[0]), "+f"(c[1]), "+f"(c[2]), "+f"(c[3])
                 : "r"(a[0]), "r"(a[1]), "r"(a[2]), "r"(a[3]), "r"(b[0]), "r"(b[1]));
}
#define CP_ASYNC16(dst, src) \
    asm volatile("cp.async.cg.shared.global [%0], [%1], 16;" :: "r"(dst), "l"(src))
#define CP_COMMIT()  asm volatile("cp.async.commit_group;" ::: "memory")
#define CP_WAIT(n)   asm volatile("cp.async.wait_group %0;" :: "n"(n) : "memory")

// ===========================================================================
// fused prep: y=0 mask pack | y=1 q fp16 / k fp16 hi+lo | y=2 v transpose fp16
// ===========================================================================
__global__ void __launch_bounds__(256) prep_kernel(
    const float4* __restrict__ q, const float4* __restrict__ k,
    const float* __restrict__ v, const int* __restrict__ mask)
{
    __shared__ float sm[64][129];            // used only by y == 2
    const int tid = threadIdx.x;

    if (blockIdx.y == 0) {
        const int gw = (blockIdx.x * 256 + tid) >> 5;
        const int l  = tid & 31;
        const int nwarps = gridDim.x * 8;
        const int nwords = SEQ * (SEQ / 32);
        for (int w = gw; w < nwords; w += nwarps) {
            const int row = w >> 6, wc = w & 63;
            int mv = mask[(size_t)row * SEQ + wc * 32 + l];
            uint32_t bits = __ballot_sync(~0u, mv != 0);
            if (l == 0) g_maskbits[w] = bits;
        }
    } else if (blockIdx.y == 1) {
        const int isK = blockIdx.x >= 256;
        const int n = BATCH * SEQ * HD / 4;
        const int stride = 256 * 256;
        if (!isK) {
            uint2* hi = (uint2*)g_qh;
            for (int c = (blockIdx.x & 255) * 256 + tid; c < n; c += stride) {
                float4 x = q[c];
                hi[c] = make_uint2(hpack(x.x, x.y), hpack(x.z, x.w));
            }
        } else {
            uint2* hi = (uint2*)g_kh;
            uint2* lo = (uint2*)g_kl;
            for (int c = (blockIdx.x & 255) * 256 + tid; c < n; c += stride) {
                float4 x = k[c];
                uint32_t h01, l01, h23, l23;
                split2h(x.x, x.y, h01, l01);
                split2h(x.z, x.w, h23, l23);
                hi[c] = make_uint2(h01, h23);
                lo[c] = make_uint2(l01, l23);
            }
        }
    } else {
        if (blockIdx.x >= 256) return;
        const int b = blockIdx.x >> 4, t0 = (blockIdx.x & 15) * 128;
        const float* vb = v + (size_t)b * SEQ * HD;
#pragma unroll
        for (int i = 0; i < 8; ++i) {
            int chunk = tid + i * 256;
            int t = chunk >> 4, d4 = (chunk & 15) * 4;
            float4 x = *(const float4*)(vb + (size_t)(t0 + t) * HD + d4);
            sm[d4 + 0][t] = x.x; sm[d4 + 1][t] = x.y;
            sm[d4 + 2][t] = x.z; sm[d4 + 3][t] = x.w;
        }
        __syncthreads();
        const int r = tid >> 2, tb = (tid & 3) * 32;
        size_t obase = ((size_t)(b * 64 + r)) * SEQ + t0 + tb;
#pragma unroll
        for (int seg = 0; seg < 4; ++seg) {
            uint32_t h[4];
#pragma unroll
            for (int j = 0; j < 4; ++j)
                h[j] = hpack(sm[r][tb + seg * 8 + j * 2],
                             sm[r][tb + seg * 8 + j * 2 + 1]);
            *(uint4*)(g_vh + obase + seg * 8) = make_uint4(h[0], h[1], h[2], h[3]);
        }
    }
}

// ===========================================================================
// scores: e = maskbit ? exp((QK^T)/8) : 0 -> attn; coltile row sums -> g_part
// 2-term fp16: Qh * (Kh + Kl)
// ===========================================================================
__global__ void __launch_bounds__(256, 2) scores_mma_kernel(float* __restrict__ attn)
{
    extern __shared__ char smem[];
    constexpr int AHI = 0, BHI = 16384, BLO = 32768;
    const uint32_t sb = smem_u32(smem);
    const int tid = threadIdx.x, wid = tid >> 5, l = tid & 31;
    const int b = blockIdx.z, row0 = blockIdx.y * 128, col0 = blockIdx.x * 128;

    {
        const __half* srcs[3] = {
            g_qh + ((size_t)(b * SEQ) + row0) * HD,
            g_kh + ((size_t)(b * SEQ) + col0) * HD,
            g_kl + ((size_t)(b * SEQ) + col0) * HD };
        const int offs[3] = { AHI, BHI, BLO };
#pragma unroll
        for (int t = 0; t < 3; ++t) {
#pragma unroll
            for (int i = 0; i < 4; ++i) {
                int chunk = tid + i * 256;
                int r = chunk >> 3, c = chunk & 7;
                *(uint4*)(smem + offs[t] + r * 128 + ((c ^ (r & 7)) << 4)) =
                    *(const uint4*)(srcs[t] + (size_t)r * HD + c * 8);
            }
        }
    }
    __syncthreads();

    const int wm = wid >> 2, wn = wid & 3;           // 2 x 4 warps, tile 64x32
    float acc[4][4][4];
#pragma unroll
    for (int i = 0; i < 4; ++i)
#pragma unroll
        for (int j = 0; j < 4; ++j)
#pragma unroll
            for (int k = 0; k < 4; ++k) acc[i][j][k] = 0.f;

#pragma unroll
    for (int ks = 0; ks < 4; ++ks) {
        uint32_t a[4][4];
#pragma unroll
        for (int mt = 0; mt < 4; ++mt) {
            int r = wm * 64 + mt * 16 + (l & 15);
            int c = 2 * ks + (l >> 4);
            ldsm_x4(a[mt][0], a[mt][1], a[mt][2], a[mt][3],
                    sb + AHI + r * 128 + ((c ^ (r & 7)) << 4));
        }
        uint32_t bh[4][2], bl[4][2];
#pragma unroll
        for (int j = 0; j < 2; ++j) {
            int n = wn * 32 + j * 16 + (l & 7) + ((l >> 4) << 3);
            int c = 2 * ks + ((l >> 3) & 1);
            uint32_t t0, t1, t2, t3;
            ldsm_x4(t0, t1, t2, t3, sb + BHI + n * 128 + ((c ^ (n & 7)) << 4));
            bh[j*2][0] = t0; bh[j*2][1] = t1; bh[j*2+1][0] = t2; bh[j*2+1][1] = t3;
            ldsm_x4(t0, t1, t2, t3, sb + BLO + n * 128 + ((c ^ (n & 7)) << 4));
            bl[j*2][0] = t0; bl[j*2][1] = t1; bl[j*2+1][0] = t2; bl[j*2+1][1] = t3;
        }
#pragma unroll
        for (int mt = 0; mt < 4; ++mt)
#pragma unroll
            for (int nt = 0; nt < 4; ++nt) {
                mma16816h(acc[mt][nt], a[mt], bh[nt]);
                mma16816h(acc[mt][nt], a[mt], bl[nt]);
            }
    }

    __syncthreads();
    float* srow = (float*)smem;      // [4][128]

    float rs[4][2];
#pragma unroll
    for (int mt = 0; mt < 4; ++mt) { rs[mt][0] = 0.f; rs[mt][1] = 0.f; }

    const int wbase = (col0 >> 5) + wn;
#pragma unroll
    for (int mt = 0; mt < 4; ++mt) {
#pragma unroll
        for (int h = 0; h < 2; ++h) {
            const int s = row0 + wm * 64 + mt * 16 + (l >> 2) + h * 8;
            const uint32_t w = g_maskbits[(size_t)s * 64 + wbase];
            float* drow = attn + ((size_t)(b * SEQ) + s) * SEQ + col0 + wn * 32;
            const int sh0 = 2 * (l & 3);
#pragma unroll
            for (int nt = 0; nt < 4; ++nt) {
                const uint32_t bits = w >> (nt * 8 + sh0);
                float e0 = (bits & 1u) ? __expf(acc[mt][nt][h * 2 + 0] * 0.125f) : 0.f;
                float e1 = (bits & 2u) ? __expf(acc[mt][nt][h * 2 + 1] * 0.125f) : 0.f;
                __stcs((float2*)(drow + nt * 8 + sh0), make_float2(e0, e1));
                rs[mt][h] += e0 + e1;
            }
        }
    }
#pragma unroll
    for (int mt = 0; mt < 4; ++mt)
#pragma unroll
        for (int h = 0; h < 2; ++h) {
            float v = rs[mt][h];
            v += __shfl_xor_sync(~0u, v, 1);
            v += __shfl_xor_sync(~0u, v, 2);
            rs[mt][h] = v;
        }
    if ((l & 3) == 0) {
#pragma unroll
        for (int mt = 0; mt < 4; ++mt)
#pragma unroll
            for (int h = 0; h < 2; ++h)
                srow[wn * 128 + wm * 64 + mt * 16 + (l >> 2) + h * 8] = rs[mt][h];
    }
    __syncthreads();
    if (tid < 128) {
        float s = srow[tid] + srow[128 + tid] + srow[256 + tid] + srow[384 + tid];
        g_part[((size_t)(b * SEQ) + row0 + tid) * 16 + blockIdx.x] = s;
    }
}

// ===========================================================================
// pv: 64-row tiles (512 CTAs). e staged via cp.async; transform: p = e*inv,
// write p back (final attn), p -> fp16 A tile; out = p @ v (fp16 MMA).
// ===========================================================================
__global__ void __launch_bounds__(256) pv_mma_kernel(
    float* __restrict__ attn, float* __restrict__ out)
{
    extern __shared__ char smem[];
    constexpr int EST = 0, ESTRIDE = 17408;                 // 64 rows * 272B
    constexpr int AP = 34816, BB = 43008, SINV = 59392;
    const uint32_t sb = smem_u32(smem);
    const int tid = threadIdx.x, wid = tid >> 5, l = tid & 31;
    const int b = blockIdx.y, row0 = blockIdx.x * 64;

    float* sinv = (float*)(smem + SINV);
    if (tid < 64) {
        const float4* pp = (const float4*)(g_part + ((size_t)(b * SEQ) + row0 + tid) * 16);
        float4 p0 = pp[0], p1 = pp[1], p2 = pp[2], p3 = pp[3];
        float s = ((p0.x + p0.y) + (p0.z + p0.w)) + ((p1.x + p1.y) + (p1.z + p1.w)) +
                  ((p2.x + p2.y) + (p2.z + p2.w)) + ((p3.x + p3.y) + (p3.z + p3.w));
        sinv[tid] = 1.0f / s;
    }

    const __half* vh = g_vh + (size_t)(b * 64) * SEQ;
    const float* arow = attn + ((size_t)(b * SEQ) + row0) * SEQ;

    {
#pragma unroll
        for (int i = 0; i < 4; ++i) {
            int chunk = tid + i * 256;                 // 1024 x 16B (e tile)
            int r = chunk >> 4, c = chunk & 15;
            CP_ASYNC16(sb + EST + r * 272 + c * 16, arow + (size_t)r * SEQ + c * 4);
        }
#pragma unroll
        for (int i = 0; i < 2; ++i) {
            int chunk = tid + i * 256;                 // 512 x 16B (v)
            int r = chunk >> 3, c = chunk & 7;
            uint32_t dst = sb + BB + r * 128 + ((c ^ (r & 7)) << 4);
            CP_ASYNC16(dst, vh + (size_t)r * SEQ + c * 8);
        }
        CP_COMMIT();
    }

    const int wm = wid >> 1, wn = wid & 1;             // 4 x 2 warps, tile 16x32
    float acc[4][4];
#pragma unroll
    for (int j = 0; j < 4; ++j)
#pragma unroll
        for (int k = 0; k < 4; ++k) acc[j][k] = 0.f;

    for (int tile = 0; tile < 32; ++tile) {
        const int t0 = tile * 64;
        const int buf = tile & 1;

        CP_WAIT(0);
        __syncthreads();

        if (tile < 31) {
            const int nt0 = t0 + 64;
            const int nbuf = buf ^ 1;
#pragma unroll
            for (int i = 0; i < 4; ++i) {
                int chunk = tid + i * 256;
                int r = chunk >> 4, c = chunk & 15;
                CP_ASYNC16(sb + EST + nbuf * ESTRIDE + r * 272 + c * 16,
                           arow + (size_t)r * SEQ + nt0 + c * 4);
            }
#pragma unroll
            for (int i = 0; i < 2; ++i) {
                int chunk = tid + i * 256;
                int r = chunk >> 3, c = chunk & 7;
                uint32_t dst = sb + BB + nbuf * 8192 + r * 128 + ((c ^ (r & 7)) << 4);
                CP_ASYNC16(dst, vh + (size_t)r * SEQ + nt0 + c * 8);
            }
            CP_COMMIT();
        }

        const float* est = (const float*)(smem + EST + buf * ESTRIDE);
#pragma unroll
        for (int i = 0; i < 2; ++i) {
            int chunk = tid + i * 256;                 // 512 chunks of 8 floats
            int r = chunk >> 3, c = chunk & 7;
            const float* sp = est + r * 68 + c * 8;
            float4 x0 = *(const float4*)sp;
            float4 x1 = *(const float4*)(sp + 4);
            const float inv = sinv[r];
            x0.x *= inv; x0.y *= inv; x0.z *= inv; x0.w *= inv;
            x1.x *= inv; x1.y *= inv; x1.z *= inv; x1.w *= inv;
            float* gp = (float*)(arow + (size_t)r * SEQ + t0 + c * 8);
            __stcs((float4*)gp, x0);
            __stcs((float4*)(gp + 4), x1);
            uint32_t p0 = hpack(x0.x, x0.y), p1 = hpack(x0.z, x0.w);
            uint32_t p2 = hpack(x1.x, x1.y), p3 = hpack(x1.z, x1.w);
            uint32_t off = r * 128 + ((c ^ (r & 7)) << 4);
            *(uint4*)(smem + AP + off) = make_uint4(p0, p1, p2, p3);
        }
        __syncthreads();

        const uint32_t Bc = sb + BB + buf * 8192;

#pragma unroll
        for (int ks = 0; ks < 4; ++ks) {
            uint32_t a[4];
            {
                int r = wm * 16 + (l & 15);
                int c = 2 * ks + (l >> 4);
                ldsm_x4(a[0], a[1], a[2], a[3],
                        sb + AP + r * 128 + ((c ^ (r & 7)) << 4));
            }
            uint32_t bh[4][2];
#pragma unroll
            for (int j = 0; j < 2; ++j) {
                int n = wn * 32 + j * 16 + (l & 7) + ((l >> 4) << 3);
                int c = 2 * ks + ((l >> 3) & 1);
                uint32_t t0r, t1r, t2r, t3r;
                ldsm_x4(t0r, t1r, t2r, t3r, Bc + n * 128 + ((c ^ (n & 7)) << 4));
                bh[j*2][0] = t0r; bh[j*2][1] = t1r; bh[j*2+1][0] = t2r; bh[j*2+1][1] = t3r;
            }
#pragma unroll
            for (int nt = 0; nt < 4; ++nt)
                mma16816h(acc[nt], a, bh[nt]);
        }
    }

    // epilogue
#pragma unroll
    for (int nt = 0; nt < 4; ++nt) {
        const int gc = wn * 32 + nt * 8 + 2 * (l & 3);
#pragma unroll
        for (int h = 0; h < 2; ++h) {
            const int gr = row0 + wm * 16 + (l >> 2) + h * 8;
            *(float2*)(out + ((size_t)(b * SEQ) + gr) * HD + gc) =
                make_float2(acc[nt][h * 2 + 0], acc[nt][h * 2 + 1]);
        }
    }
}

// ===========================================================================
extern "C" void kernel_launch(void* const* d_in, const int* in_sizes, int n_in,
                              void* d_out, int out_size)
{
    const float* q    = (const float*)d_in[0];
    const float* k    = (const float*)d_in[1];
    const float* v    = (const float*)d_in[2];
    const int*   mask = (const int*)d_in[3];

    float* out  = (float*)d_out;
    float* attn = out + (size_t)BATCH * SEQ * HD;

    cudaFuncSetAttribute(scores_mma_kernel,
                         cudaFuncAttributeMaxDynamicSharedMemorySize, 49152);
    cudaFuncSetAttribute(pv_mma_kernel,
                         cudaFuncAttributeMaxDynamicSharedMemorySize, 59648);

    prep_kernel<<<dim3(512, 3), 256>>>((const float4*)q, (const float4*)k, v, mask);

    scores_mma_kernel<<<dim3(16, 16, BATCH), 256, 49152>>>(attn);
    pv_mma_kernel<<<dim3(32, BATCH), 256, 59648>>>(attn, out);
}

// round 10
// speedup vs baseline: 2.7876x; 1.1737x over previous
#include <cuda_runtime.h>
#include <cuda_fp16.h>
#include <cstdint>

#define SEQ   2048
#define HD    64
#define BATCH 16

// ---------------------------------------------------------------------------
// device scratch
// ---------------------------------------------------------------------------
__device__ __half    g_qh[BATCH * SEQ * HD];        // fp16(q)
__device__ __half    g_kh[BATCH * SEQ * HD];        // fp16(k)
__device__ __half    g_kl[BATCH * SEQ * HD];        // fp16(k - fp16(k))
__device__ __half    g_vh[BATCH * HD * SEQ];        // transposed [b][d][t], fp16
__device__ __half    g_e[(size_t)BATCH * SEQ * SEQ]; // unnormalized exp, fp16
__device__ float     g_part[BATCH * SEQ * 16];      // per-row per-coltile exp sums
__device__ uint32_t  g_maskbits[SEQ * (SEQ / 32)];

// ---------------------------------------------------------------------------
// helpers
// ---------------------------------------------------------------------------
__device__ __forceinline__ uint32_t smem_u32(const void* p) {
    uint32_t a;
    asm("{ .reg .u64 t; cvta.to.shared.u64 t, %1; cvt.u32.u64 %0, t; }" : "=r"(a) : "l"(p));
    return a;
}
__device__ __forceinline__ uint32_t hpack(float a, float b) {
    uint32_t r;
    asm("cvt.rn.f16x2.f32 %0, %1, %2;" : "=r"(r) : "f"(b), "f"(a));
    return r;
}
__device__ __forceinline__ void split2h(float x0, float x1, uint32_t& h, uint32_t& l) {
    __half2 hh = __floats2half2_rn(x0, x1);
    float2 hf = __half22float2(hh);
    __half2 ll = __floats2half2_rn(x0 - hf.x, x1 - hf.y);
    h = *(uint32_t*)&hh;
    l = *(uint32_t*)&ll;
}
__device__ __forceinline__ void ldsm_x4(uint32_t& r0, uint32_t& r1, uint32_t& r2,
                                        uint32_t& r3, uint32_t addr) {
    asm volatile("ldmatrix.sync.aligned.m8n8.x4.shared.b16 {%0,%1,%2,%3}, [%4];"
                 : "=r"(r0), "=r"(r1), "=r"(r2), "=r"(r3) : "r"(addr));
}
__device__ __forceinline__ void mma16816h(float* c, const uint32_t* a, const uint32_t* b) {
    asm volatile("mma.sync.aligned.m16n8k16.row.col.f32.f16.f16.f32 "
                 "{%0,%1,%2,%3}, {%4,%5,%6,%7}, {%8,%9}, {%0,%1,%2,%3};"
                 : "+f"(c[0]), "+f"(c[1]), "+f"(c[2]), "+f"(c[3])
                 : "r"(a[0]), "r"(a[1]), "r"(a[2]), "r"(a[3]), "r"(b[0]), "r"(b[1]));
}
#define CP_ASYNC16(dst, src) \
    asm volatile("cp.async.cg.shared.global [%0], [%1], 16;" :: "r"(dst), "l"(src))
#define CP_COMMIT()  asm volatile("cp.async.commit_group;" ::: "memory")
#define CP_WAIT(n)   asm volatile("cp.async.wait_group %0;" :: "n"(n) : "memory")

// ===========================================================================
// fused prep: y=0 mask pack | y=1 q fp16 / k fp16 hi+lo | y=2 v transpose fp16
// ===========================================================================
__global__ void __launch_bounds__(256) prep_kernel(
    const float4* __restrict__ q, const float4* __restrict__ k,
    const float* __restrict__ v, const int* __restrict__ mask)
{
    __shared__ float sm[64][129];            // used only by y == 2
    const int tid = threadIdx.x;

    if (blockIdx.y == 0) {
        const int gw = (blockIdx.x * 256 + tid) >> 5;
        const int l  = tid & 31;
        const int nwarps = gridDim.x * 8;
        const int nwords = SEQ * (SEQ / 32);
        for (int w = gw; w < nwords; w += nwarps) {
            const int row = w >> 6, wc = w & 63;
            int mv = mask[(size_t)row * SEQ + wc * 32 + l];
            uint32_t bits = __ballot_sync(~0u, mv != 0);
            if (l == 0) g_maskbits[w] = bits;
        }
    } else if (blockIdx.y == 1) {
        const int isK = blockIdx.x >= 256;
        const int n = BATCH * SEQ * HD / 4;
        const int stride = 256 * 256;
        if (!isK) {
            uint2* hi = (uint2*)g_qh;
            for (int c = (blockIdx.x & 255) * 256 + tid; c < n; c += stride) {
                float4 x = q[c];
                hi[c] = make_uint2(hpack(x.x, x.y), hpack(x.z, x.w));
            }
        } else {
            uint2* hi = (uint2*)g_kh;
            uint2* lo = (uint2*)g_kl;
            for (int c = (blockIdx.x & 255) * 256 + tid; c < n; c += stride) {
                float4 x = k[c];
                uint32_t h01, l01, h23, l23;
                split2h(x.x, x.y, h01, l01);
                split2h(x.z, x.w, h23, l23);
                hi[c] = make_uint2(h01, h23);
                lo[c] = make_uint2(l01, l23);
            }
        }
    } else {
        if (blockIdx.x >= 256) return;
        const int b = blockIdx.x >> 4, t0 = (blockIdx.x & 15) * 128;
        const float* vb = v + (size_t)b * SEQ * HD;
#pragma unroll
        for (int i = 0; i < 8; ++i) {
            int chunk = tid + i * 256;
            int t = chunk >> 4, d4 = (chunk & 15) * 4;
            float4 x = *(const float4*)(vb + (size_t)(t0 + t) * HD + d4);
            sm[d4 + 0][t] = x.x; sm[d4 + 1][t] = x.y;
            sm[d4 + 2][t] = x.z; sm[d4 + 3][t] = x.w;
        }
        __syncthreads();
        const int r = tid >> 2, tb = (tid & 3) * 32;
        size_t obase = ((size_t)(b * 64 + r)) * SEQ + t0 + tb;
#pragma unroll
        for (int seg = 0; seg < 4; ++seg) {
            uint32_t h[4];
#pragma unroll
            for (int j = 0; j < 4; ++j)
                h[j] = hpack(sm[r][tb + seg * 8 + j * 2],
                             sm[r][tb + seg * 8 + j * 2 + 1]);
            *(uint4*)(g_vh + obase + seg * 8) = make_uint4(h[0], h[1], h[2], h[3]);
        }
    }
}

// ===========================================================================
// scores: e = maskbit ? exp((QK^T)/8) : 0 -> g_e (fp16); row sums -> g_part
// 2-term fp16: Qh * (Kh + Kl)
// ===========================================================================
__global__ void __launch_bounds__(256, 2) scores_mma_kernel()
{
    extern __shared__ char smem[];
    constexpr int AHI = 0, BHI = 16384, BLO = 32768;
    const uint32_t sb = smem_u32(smem);
    const int tid = threadIdx.x, wid = tid >> 5, l = tid & 31;
    const int b = blockIdx.z, row0 = blockIdx.y * 128, col0 = blockIdx.x * 128;

    {
        const __half* srcs[3] = {
            g_qh + ((size_t)(b * SEQ) + row0) * HD,
            g_kh + ((size_t)(b * SEQ) + col0) * HD,
            g_kl + ((size_t)(b * SEQ) + col0) * HD };
        const int offs[3] = { AHI, BHI, BLO };
#pragma unroll
        for (int t = 0; t < 3; ++t) {
#pragma unroll
            for (int i = 0; i < 4; ++i) {
                int chunk = tid + i * 256;
                int r = chunk >> 3, c = chunk & 7;
                *(uint4*)(smem + offs[t] + r * 128 + ((c ^ (r & 7)) << 4)) =
                    *(const uint4*)(srcs[t] + (size_t)r * HD + c * 8);
            }
        }
    }
    __syncthreads();

    const int wm = wid >> 2, wn = wid & 3;           // 2 x 4 warps, tile 64x32
    float acc[4][4][4];
#pragma unroll
    for (int i = 0; i < 4; ++i)
#pragma unroll
        for (int j = 0; j < 4; ++j)
#pragma unroll
            for (int k = 0; k < 4; ++k) acc[i][j][k] = 0.f;

#pragma unroll
    for (int ks = 0; ks < 4; ++ks) {
        uint32_t a[4][4];
#pragma unroll
        for (int mt = 0; mt < 4; ++mt) {
            int r = wm * 64 + mt * 16 + (l & 15);
            int c = 2 * ks + (l >> 4);
            ldsm_x4(a[mt][0], a[mt][1], a[mt][2], a[mt][3],
                    sb + AHI + r * 128 + ((c ^ (r & 7)) << 4));
        }
        uint32_t bh[4][2], bl[4][2];
#pragma unroll
        for (int j = 0; j < 2; ++j) {
            int n = wn * 32 + j * 16 + (l & 7) + ((l >> 4) << 3);
            int c = 2 * ks + ((l >> 3) & 1);
            uint32_t t0, t1, t2, t3;
            ldsm_x4(t0, t1, t2, t3, sb + BHI + n * 128 + ((c ^ (n & 7)) << 4));
            bh[j*2][0] = t0; bh[j*2][1] = t1; bh[j*2+1][0] = t2; bh[j*2+1][1] = t3;
            ldsm_x4(t0, t1, t2, t3, sb + BLO + n * 128 + ((c ^ (n & 7)) << 4));
            bl[j*2][0] = t0; bl[j*2][1] = t1; bl[j*2+1][0] = t2; bl[j*2+1][1] = t3;
        }
#pragma unroll
        for (int mt = 0; mt < 4; ++mt)
#pragma unroll
            for (int nt = 0; nt < 4; ++nt) {
                mma16816h(acc[mt][nt], a[mt], bh[nt]);
                mma16816h(acc[mt][nt], a[mt], bl[nt]);
            }
    }

    __syncthreads();
    float* srow = (float*)smem;      // [4][128]

    float rs[4][2];
#pragma unroll
    for (int mt = 0; mt < 4; ++mt) { rs[mt][0] = 0.f; rs[mt][1] = 0.f; }

    const int wbase = (col0 >> 5) + wn;
#pragma unroll
    for (int mt = 0; mt < 4; ++mt) {
#pragma unroll
        for (int h = 0; h < 2; ++h) {
            const int s = row0 + wm * 64 + mt * 16 + (l >> 2) + h * 8;
            const uint32_t w = g_maskbits[(size_t)s * 64 + wbase];
            __half* drow = g_e + ((size_t)(b * SEQ) + s) * SEQ + col0 + wn * 32;
            const int sh0 = 2 * (l & 3);
#pragma unroll
            for (int nt = 0; nt < 4; ++nt) {
                const uint32_t bits = w >> (nt * 8 + sh0);
                float e0 = (bits & 1u) ? __expf(acc[mt][nt][h * 2 + 0] * 0.125f) : 0.f;
                float e1 = (bits & 2u) ? __expf(acc[mt][nt][h * 2 + 1] * 0.125f) : 0.f;
                __stcs((uint32_t*)(drow + nt * 8 + sh0), hpack(e0, e1));
                rs[mt][h] += e0 + e1;
            }
        }
    }
#pragma unroll
    for (int mt = 0; mt < 4; ++mt)
#pragma unroll
        for (int h = 0; h < 2; ++h) {
            float v = rs[mt][h];
            v += __shfl_xor_sync(~0u, v, 1);
            v += __shfl_xor_sync(~0u, v, 2);
            rs[mt][h] = v;
        }
    if ((l & 3) == 0) {
#pragma unroll
        for (int mt = 0; mt < 4; ++mt)
#pragma unroll
            for (int h = 0; h < 2; ++h)
                srow[wn * 128 + wm * 64 + mt * 16 + (l >> 2) + h * 8] = rs[mt][h];
    }
    __syncthreads();
    if (tid < 128) {
        float s = srow[tid] + srow[128 + tid] + srow[256 + tid] + srow[384 + tid];
        g_part[((size_t)(b * SEQ) + row0 + tid) * 16 + blockIdx.x] = s;
    }
}

// ===========================================================================
// pv: 64-row tiles (512 CTAs). fp16 e staged via cp.async; transform:
// p = e*inv -> write fp32 p to attn (final output) + fp16 A tile;
// out = p @ v (fp16 MMA). smem: EST 2x9216 | AP 8K | B 2x8K | sinv
// ===========================================================================
__global__ void __launch_bounds__(256) pv_mma_kernel(
    float* __restrict__ attn, float* __restrict__ out)
{
    extern __shared__ char smem[];
    constexpr int EST = 0, ESTRIDE = 9216;                  // 64 rows * 144B
    constexpr int AP = 18432, BB = 26624, SINV = 43008;
    const uint32_t sb = smem_u32(smem);
    const int tid = threadIdx.x, wid = tid >> 5, l = tid & 31;
    const int b = blockIdx.y, row0 = blockIdx.x * 64;

    float* sinv = (float*)(smem + SINV);
    if (tid < 64) {
        const float4* pp = (const float4*)(g_part + ((size_t)(b * SEQ) + row0 + tid) * 16);
        float4 p0 = pp[0], p1 = pp[1], p2 = pp[2], p3 = pp[3];
        float s = ((p0.x + p0.y) + (p0.z + p0.w)) + ((p1.x + p1.y) + (p1.z + p1.w)) +
                  ((p2.x + p2.y) + (p2.z + p2.w)) + ((p3.x + p3.y) + (p3.z + p3.w));
        sinv[tid] = 1.0f / s;
    }

    const __half* vh = g_vh + (size_t)(b * 64) * SEQ;
    const __half* erow = g_e + ((size_t)(b * SEQ) + row0) * SEQ;
    float* arow = attn + ((size_t)(b * SEQ) + row0) * SEQ;

    // prologue: stage 0 of e-tile (fp16, 8KB) and v-tile
    {
#pragma unroll
        for (int i = 0; i < 2; ++i) {
            int chunk = tid + i * 256;                 // 512 x 16B (e tile)
            int r = chunk >> 3, c = chunk & 7;
            CP_ASYNC16(sb + EST + r * 144 + c * 16, erow + (size_t)r * SEQ + c * 8);
        }
#pragma unroll
        for (int i = 0; i < 2; ++i) {
            int chunk = tid + i * 256;                 // 512 x 16B (v)
            int r = chunk >> 3, c = chunk & 7;
            uint32_t dst = sb + BB + r * 128 + ((c ^ (r & 7)) << 4);
            CP_ASYNC16(dst, vh + (size_t)r * SEQ + c * 8);
        }
        CP_COMMIT();
    }

    const int wm = wid >> 1, wn = wid & 1;             // 4 x 2 warps, tile 16x32
    float acc[4][4];
#pragma unroll
    for (int j = 0; j < 4; ++j)
#pragma unroll
        for (int k = 0; k < 4; ++k) acc[j][k] = 0.f;

    for (int tile = 0; tile < 32; ++tile) {
        const int t0 = tile * 64;
        const int buf = tile & 1;

        CP_WAIT(0);
        __syncthreads();

        // prefetch next tile (overlaps transform + MMA)
        if (tile < 31) {
            const int nt0 = t0 + 64;
            const int nbuf = buf ^ 1;
#pragma unroll
            for (int i = 0; i < 2; ++i) {
                int chunk = tid + i * 256;
                int r = chunk >> 3, c = chunk & 7;
                CP_ASYNC16(sb + EST + nbuf * ESTRIDE + r * 144 + c * 16,
                           erow + (size_t)r * SEQ + nt0 + c * 8);
            }
#pragma unroll
            for (int i = 0; i < 2; ++i) {
                int chunk = tid + i * 256;
                int r = chunk >> 3, c = chunk & 7;
                uint32_t dst = sb + BB + nbuf * 8192 + r * 128 + ((c ^ (r & 7)) << 4);
                CP_ASYNC16(dst, vh + (size_t)r * SEQ + nt0 + c * 8);
            }
            CP_COMMIT();
        }

        // transform: fp16 e -> fp32 p (write, streaming) + fp16 A tile
        const char* est = smem + EST + buf * ESTRIDE;
#pragma unroll
        for (int i = 0; i < 2; ++i) {
            int chunk = tid + i * 256;                 // 512 chunks of 8 halfs
            int r = chunk >> 3, c = chunk & 7;
            uint4 raw = *(const uint4*)(est + r * 144 + c * 16);
            float2 f0 = __half22float2(*(__half2*)&raw.x);
            float2 f1 = __half22float2(*(__half2*)&raw.y);
            float2 f2 = __half22float2(*(__half2*)&raw.z);
            float2 f3 = __half22float2(*(__half2*)&raw.w);
            const float inv = sinv[r];
            float p0 = f0.x * inv, p1 = f0.y * inv, p2 = f1.x * inv, p3 = f1.y * inv;
            float p4 = f2.x * inv, p5 = f2.y * inv, p6 = f3.x * inv, p7 = f3.y * inv;
            float* gp = arow + (size_t)r * SEQ + t0 + c * 8;
            __stcs((float4*)gp,       make_float4(p0, p1, p2, p3));
            __stcs((float4*)(gp + 4), make_float4(p4, p5, p6, p7));
            uint32_t off = r * 128 + ((c ^ (r & 7)) << 4);
            *(uint4*)(smem + AP + off) =
                make_uint4(hpack(p0, p1), hpack(p2, p3), hpack(p4, p5), hpack(p6, p7));
        }
        __syncthreads();

        const uint32_t Bc = sb + BB + buf * 8192;

#pragma unroll
        for (int ks = 0; ks < 4; ++ks) {
            uint32_t a[4];
            {
                int r = wm * 16 + (l & 15);
                int c = 2 * ks + (l >> 4);
                ldsm_x4(a[0], a[1], a[2], a[3],
                        sb + AP + r * 128 + ((c ^ (r & 7)) << 4));
            }
            uint32_t bh[4][2];
#pragma unroll
            for (int j = 0; j < 2; ++j) {
                int n = wn * 32 + j * 16 + (l & 7) + ((l >> 4) << 3);
                int c = 2 * ks + ((l >> 3) & 1);
                uint32_t t0r, t1r, t2r, t3r;
                ldsm_x4(t0r, t1r, t2r, t3r, Bc + n * 128 + ((c ^ (n & 7)) << 4));
                bh[j*2][0] = t0r; bh[j*2][1] = t1r; bh[j*2+1][0] = t2r; bh[j*2+1][1] = t3r;
            }
#pragma unroll
            for (int nt = 0; nt < 4; ++nt)
                mma16816h(acc[nt], a, bh[nt]);
        }
    }

    // epilogue
#pragma unroll
    for (int nt = 0; nt < 4; ++nt) {
        const int gc = wn * 32 + nt * 8 + 2 * (l & 3);
#pragma unroll
        for (int h = 0; h < 2; ++h) {
            const int gr = row0 + wm * 16 + (l >> 2) + h * 8;
            *(float2*)(out + ((size_t)(b * SEQ) + gr) * HD + gc) =
                make_float2(acc[nt][h * 2 + 0], acc[nt][h * 2 + 1]);
        }
    }
}

// ===========================================================================
extern "C" void kernel_launch(void* const* d_in, const int* in_sizes, int n_in,
                              void* d_out, int out_size)
{
    const float* q    = (const float*)d_in[0];
    const float* k    = (const float*)d_in[1];
    const float* v    = (const float*)d_in[2];
    const int*   mask = (const int*)d_in[3];

    float* out  = (float*)d_out;
    float* attn = out + (size_t)BATCH * SEQ * HD;

    cudaFuncSetAttribute(scores_mma_kernel,
                         cudaFuncAttributeMaxDynamicSharedMemorySize, 49152);
    cudaFuncSetAttribute(pv_mma_kernel,
                         cudaFuncAttributeMaxDynamicSharedMemorySize, 43264);

    prep_kernel<<<dim3(512, 3), 256>>>((const float4*)q, (const float4*)k, v, mask);

    scores_mma_kernel<<<dim3(16, 16, BATCH), 256, 49152>>>();
    pv_mma_kernel<<<dim3(32, BATCH), 256, 43264>>>(attn, out);
}

// round 11
// speedup vs baseline: 2.9832x; 1.0702x over previous
#include <cuda_runtime.h>
#include <cuda_fp16.h>
#include <cstdint>

#define SEQ   2048
#define HD    64
#define BATCH 16

// ---------------------------------------------------------------------------
// device scratch
// ---------------------------------------------------------------------------
__device__ __half    g_qh[BATCH * SEQ * HD];        // fp16(q)
__device__ __half    g_kh[BATCH * SEQ * HD];        // fp16(k)
__device__ __half    g_vh[BATCH * HD * SEQ];        // transposed [b][d][t], fp16
__device__ __half    g_e[(size_t)BATCH * SEQ * SEQ]; // unnormalized exp, fp16
__device__ float     g_part[BATCH * SEQ * 16];      // per-row per-coltile exp sums
__device__ uint32_t  g_maskbits[SEQ * (SEQ / 32)];

// ---------------------------------------------------------------------------
// helpers
// ---------------------------------------------------------------------------
__device__ __forceinline__ uint32_t smem_u32(const void* p) {
    uint32_t a;
    asm("{ .reg .u64 t; cvta.to.shared.u64 t, %1; cvt.u32.u64 %0, t; }" : "=r"(a) : "l"(p));
    return a;
}
__device__ __forceinline__ uint32_t hpack(float a, float b) {
    uint32_t r;
    asm("cvt.rn.f16x2.f32 %0, %1, %2;" : "=r"(r) : "f"(b), "f"(a));
    return r;
}
__device__ __forceinline__ void ldsm_x4(uint32_t& r0, uint32_t& r1, uint32_t& r2,
                                        uint32_t& r3, uint32_t addr) {
    asm volatile("ldmatrix.sync.aligned.m8n8.x4.shared.b16 {%0,%1,%2,%3}, [%4];"
                 : "=r"(r0), "=r"(r1), "=r"(r2), "=r"(r3) : "r"(addr));
}
__device__ __forceinline__ void mma16816h(float* c, const uint32_t* a, const uint32_t* b) {
    asm volatile("mma.sync.aligned.m16n8k16.row.col.f32.f16.f16.f32 "
                 "{%0,%1,%2,%3}, {%4,%5,%6,%7}, {%8,%9}, {%0,%1,%2,%3};"
                 : "+f"(c[0]), "+f"(c[1]), "+f"(c[2]), "+f"(c[3])
                 : "r"(a[0]), "r"(a[1]), "r"(a[2]), "r"(a[3]), "r"(b[0]), "r"(b[1]));
}
#define CP_ASYNC16(dst, src) \
    asm volatile("cp.async.cg.shared.global [%0], [%1], 16;" :: "r"(dst), "l"(src))
#define CP_COMMIT()  asm volatile("cp.async.commit_group;" ::: "memory")
#define CP_WAIT(n)   asm volatile("cp.async.wait_group %0;" :: "n"(n) : "memory")

// ===========================================================================
// fused prep: y=0 mask pack | y=1 q/k fp16 convert | y=2 v transpose fp16
// ===========================================================================
__global__ void __launch_bounds__(256) prep_kernel(
    const float4* __restrict__ q, const float4* __restrict__ k,
    const float* __restrict__ v, const int* __restrict__ mask)
{
    __shared__ float sm[64][129];            // used only by y == 2
    const int tid = threadIdx.x;

    if (blockIdx.y == 0) {
        const int gw = (blockIdx.x * 256 + tid) >> 5;
        const int l  = tid & 31;
        const int nwarps = gridDim.x * 8;
        const int nwords = SEQ * (SEQ / 32);
        for (int w = gw; w < nwords; w += nwarps) {
            const int row = w >> 6, wc = w & 63;
            int mv = mask[(size_t)row * SEQ + wc * 32 + l];
            uint32_t bits = __ballot_sync(~0u, mv != 0);
            if (l == 0) g_maskbits[w] = bits;
        }
    } else if (blockIdx.y == 1) {
        const int isK = blockIdx.x >= 256;
        const float4* src = isK ? k : q;
        uint2* hi = (uint2*)(isK ? g_kh : g_qh);
        const int n = BATCH * SEQ * HD / 4;
        const int stride = 256 * 256;
        for (int c = (blockIdx.x & 255) * 256 + tid; c < n; c += stride) {
            float4 x = src[c];
            hi[c] = make_uint2(hpack(x.x, x.y), hpack(x.z, x.w));
        }
    } else {
        if (blockIdx.x >= 256) return;
        const int b = blockIdx.x >> 4, t0 = (blockIdx.x & 15) * 128;
        const float* vb = v + (size_t)b * SEQ * HD;
#pragma unroll
        for (int i = 0; i < 8; ++i) {
            int chunk = tid + i * 256;
            int t = chunk >> 4, d4 = (chunk & 15) * 4;
            float4 x = *(const float4*)(vb + (size_t)(t0 + t) * HD + d4);
            sm[d4 + 0][t] = x.x; sm[d4 + 1][t] = x.y;
            sm[d4 + 2][t] = x.z; sm[d4 + 3][t] = x.w;
        }
        __syncthreads();
        const int r = tid >> 2, tb = (tid & 3) * 32;
        size_t obase = ((size_t)(b * 64 + r)) * SEQ + t0 + tb;
#pragma unroll
        for (int seg = 0; seg < 4; ++seg) {
            uint32_t h[4];
#pragma unroll
            for (int j = 0; j < 4; ++j)
                h[j] = hpack(sm[r][tb + seg * 8 + j * 2],
                             sm[r][tb + seg * 8 + j * 2 + 1]);
            *(uint4*)(g_vh + obase + seg * 8) = make_uint4(h[0], h[1], h[2], h[3]);
        }
    }
}

// ===========================================================================
// scores: e = maskbit ? exp((Qh Kh^T)/8) : 0 -> g_e (fp16); sums -> g_part
// single-term fp16 MMA
// ===========================================================================
__global__ void __launch_bounds__(256, 2) scores_mma_kernel()
{
    extern __shared__ char smem[];
    constexpr int AHI = 0, BHI = 16384;
    const uint32_t sb = smem_u32(smem);
    const int tid = threadIdx.x, wid = tid >> 5, l = tid & 31;
    const int b = blockIdx.z, row0 = blockIdx.y * 128, col0 = blockIdx.x * 128;

    {
        const __half* srcs[2] = {
            g_qh + ((size_t)(b * SEQ) + row0) * HD,
            g_kh + ((size_t)(b * SEQ) + col0) * HD };
        const int offs[2] = { AHI, BHI };
#pragma unroll
        for (int t = 0; t < 2; ++t) {
#pragma unroll
            for (int i = 0; i < 4; ++i) {
                int chunk = tid + i * 256;
                int r = chunk >> 3, c = chunk & 7;
                *(uint4*)(smem + offs[t] + r * 128 + ((c ^ (r & 7)) << 4)) =
                    *(const uint4*)(srcs[t] + (size_t)r * HD + c * 8);
            }
        }
    }
    __syncthreads();

    const int wm = wid >> 2, wn = wid & 3;           // 2 x 4 warps, tile 64x32
    float acc[4][4][4];
#pragma unroll
    for (int i = 0; i < 4; ++i)
#pragma unroll
        for (int j = 0; j < 4; ++j)
#pragma unroll
            for (int k = 0; k < 4; ++k) acc[i][j][k] = 0.f;

#pragma unroll
    for (int ks = 0; ks < 4; ++ks) {
        uint32_t a[4][4];
#pragma unroll
        for (int mt = 0; mt < 4; ++mt) {
            int r = wm * 64 + mt * 16 + (l & 15);
            int c = 2 * ks + (l >> 4);
            ldsm_x4(a[mt][0], a[mt][1], a[mt][2], a[mt][3],
                    sb + AHI + r * 128 + ((c ^ (r & 7)) << 4));
        }
        uint32_t bh[4][2];
#pragma unroll
        for (int j = 0; j < 2; ++j) {
            int n = wn * 32 + j * 16 + (l & 7) + ((l >> 4) << 3);
            int c = 2 * ks + ((l >> 3) & 1);
            uint32_t t0, t1, t2, t3;
            ldsm_x4(t0, t1, t2, t3, sb + BHI + n * 128 + ((c ^ (n & 7)) << 4));
            bh[j*2][0] = t0; bh[j*2][1] = t1; bh[j*2+1][0] = t2; bh[j*2+1][1] = t3;
        }
#pragma unroll
        for (int mt = 0; mt < 4; ++mt)
#pragma unroll
            for (int nt = 0; nt < 4; ++nt)
                mma16816h(acc[mt][nt], a[mt], bh[nt]);
    }

    __syncthreads();
    float* srow = (float*)smem;      // [4][128]

    float rs[4][2];
#pragma unroll
    for (int mt = 0; mt < 4; ++mt) { rs[mt][0] = 0.f; rs[mt][1] = 0.f; }

    const int wbase = (col0 >> 5) + wn;
#pragma unroll
    for (int mt = 0; mt < 4; ++mt) {
#pragma unroll
        for (int h = 0; h < 2; ++h) {
            const int s = row0 + wm * 64 + mt * 16 + (l >> 2) + h * 8;
            const uint32_t w = g_maskbits[(size_t)s * 64 + wbase];
            __half* drow = g_e + ((size_t)(b * SEQ) + s) * SEQ + col0 + wn * 32;
            const int sh0 = 2 * (l & 3);
#pragma unroll
            for (int nt = 0; nt < 4; ++nt) {
                const uint32_t bits = w >> (nt * 8 + sh0);
                float e0 = (bits & 1u) ? __expf(acc[mt][nt][h * 2 + 0] * 0.125f) : 0.f;
                float e1 = (bits & 2u) ? __expf(acc[mt][nt][h * 2 + 1] * 0.125f) : 0.f;
                __stcs((uint32_t*)(drow + nt * 8 + sh0), hpack(e0, e1));
                rs[mt][h] += e0 + e1;
            }
        }
    }
#pragma unroll
    for (int mt = 0; mt < 4; ++mt)
#pragma unroll
        for (int h = 0; h < 2; ++h) {
            float v = rs[mt][h];
            v += __shfl_xor_sync(~0u, v, 1);
            v += __shfl_xor_sync(~0u, v, 2);
            rs[mt][h] = v;
        }
    if ((l & 3) == 0) {
#pragma unroll
        for (int mt = 0; mt < 4; ++mt)
#pragma unroll
            for (int h = 0; h < 2; ++h)
                srow[wn * 128 + wm * 64 + mt * 16 + (l >> 2) + h * 8] = rs[mt][h];
    }
    __syncthreads();
    if (tid < 128) {
        float s = srow[tid] + srow[128 + tid] + srow[256 + tid] + srow[384 + tid];
        g_part[((size_t)(b * SEQ) + row0 + tid) * 16 + blockIdx.x] = s;
    }
}

// ===========================================================================
// pv: 64-row tiles (512 CTAs), 3-stage cp.async pipeline on e+v tiles.
// transform: p = e*inv -> fp32 p to attn (final output) + fp16 A tile;
// out = p @ v. smem: EST 3x9216 | AP 8K | B 3x8K | sinv
// ===========================================================================
__global__ void __launch_bounds__(256) pv_mma_kernel(
    float* __restrict__ attn, float* __restrict__ out)
{
    extern __shared__ char smem[];
    constexpr int EST = 0, ESTRIDE = 9216;                  // 64 rows * 144B
    constexpr int AP = 27648, BB = 35840, SINV = 60416;
    const uint32_t sb = smem_u32(smem);
    const int tid = threadIdx.x, wid = tid >> 5, l = tid & 31;
    const int b = blockIdx.y, row0 = blockIdx.x * 64;

    float* sinv = (float*)(smem + SINV);
    if (tid < 64) {
        const float4* pp = (const float4*)(g_part + ((size_t)(b * SEQ) + row0 + tid) * 16);
        float4 p0 = pp[0], p1 = pp[1], p2 = pp[2], p3 = pp[3];
        float s = ((p0.x + p0.y) + (p0.z + p0.w)) + ((p1.x + p1.y) + (p1.z + p1.w)) +
                  ((p2.x + p2.y) + (p2.z + p2.w)) + ((p3.x + p3.y) + (p3.z + p3.w));
        sinv[tid] = 1.0f / s;
    }

    const __half* vh = g_vh + (size_t)(b * 64) * SEQ;
    const __half* erow = g_e + ((size_t)(b * SEQ) + row0) * SEQ;
    float* arow = attn + ((size_t)(b * SEQ) + row0) * SEQ;

    // prologue: stage tiles 0 and 1
#pragma unroll
    for (int st = 0; st < 2; ++st) {
        const int t0 = st * 64;
#pragma unroll
        for (int i = 0; i < 2; ++i) {
            int chunk = tid + i * 256;                 // 512 x 16B (e tile)
            int r = chunk >> 3, c = chunk & 7;
            CP_ASYNC16(sb + EST + st * ESTRIDE + r * 144 + c * 16,
                       erow + (size_t)r * SEQ + t0 + c * 8);
        }
#pragma unroll
        for (int i = 0; i < 2; ++i) {
            int chunk = tid + i * 256;                 // 512 x 16B (v)
            int r = chunk >> 3, c = chunk & 7;
            uint32_t dst = sb + BB + st * 8192 + r * 128 + ((c ^ (r & 7)) << 4);
            CP_ASYNC16(dst, vh + (size_t)r * SEQ + t0 + c * 8);
        }
        CP_COMMIT();
    }

    const int wm = wid >> 1, wn = wid & 1;             // 4 x 2 warps, tile 16x32
    float acc[4][4];
#pragma unroll
    for (int j = 0; j < 4; ++j)
#pragma unroll
        for (int k = 0; k < 4; ++k) acc[j][k] = 0.f;

    for (int tile = 0; tile < 32; ++tile) {
        const int t0 = tile * 64;
        const int buf = tile % 3;

        if (tile < 31) { CP_WAIT(1); } else { CP_WAIT(0); }
        __syncthreads();

        // prefetch tile+2 (two iterations of latency hiding)
        if (tile < 30) {
            const int nt0 = t0 + 128;
            const int nbuf = (tile + 2) % 3;
#pragma unroll
            for (int i = 0; i < 2; ++i) {
                int chunk = tid + i * 256;
                int r = chunk >> 3, c = chunk & 7;
                CP_ASYNC16(sb + EST + nbuf * ESTRIDE + r * 144 + c * 16,
                           erow + (size_t)r * SEQ + nt0 + c * 8);
            }
#pragma unroll
            for (int i = 0; i < 2; ++i) {
                int chunk = tid + i * 256;
                int r = chunk >> 3, c = chunk & 7;
                uint32_t dst = sb + BB + nbuf * 8192 + r * 128 + ((c ^ (r & 7)) << 4);
                CP_ASYNC16(dst, vh + (size_t)r * SEQ + nt0 + c * 8);
            }
            CP_COMMIT();
        }

        // transform: fp16 e -> fp32 p (write, streaming) + fp16 A tile
        const char* est = smem + EST + buf * ESTRIDE;
#pragma unroll
        for (int i = 0; i < 2; ++i) {
            int chunk = tid + i * 256;                 // 512 chunks of 8 halfs
            int r = chunk >> 3, c = chunk & 7;
            uint4 raw = *(const uint4*)(est + r * 144 + c * 16);
            float2 f0 = __half22float2(*(__half2*)&raw.x);
            float2 f1 = __half22float2(*(__half2*)&raw.y);
            float2 f2 = __half22float2(*(__half2*)&raw.z);
            float2 f3 = __half22float2(*(__half2*)&raw.w);
            const float inv = sinv[r];
            float p0 = f0.x * inv, p1 = f0.y * inv, p2 = f1.x * inv, p3 = f1.y * inv;
            float p4 = f2.x * inv, p5 = f2.y * inv, p6 = f3.x * inv, p7 = f3.y * inv;
            float* gp = arow + (size_t)r * SEQ + t0 + c * 8;
            __stcs((float4*)gp,       make_float4(p0, p1, p2, p3));
            __stcs((float4*)(gp + 4), make_float4(p4, p5, p6, p7));
            uint32_t off = r * 128 + ((c ^ (r & 7)) << 4);
            *(uint4*)(smem + AP + off) =
                make_uint4(hpack(p0, p1), hpack(p2, p3), hpack(p4, p5), hpack(p6, p7));
        }
        __syncthreads();

        const uint32_t Bc = sb + BB + buf * 8192;

#pragma unroll
        for (int ks = 0; ks < 4; ++ks) {
            uint32_t a[4];
            {
                int r = wm * 16 + (l & 15);
                int c = 2 * ks + (l >> 4);
                ldsm_x4(a[0], a[1], a[2], a[3],
                        sb + AP + r * 128 + ((c ^ (r & 7)) << 4));
            }
            uint32_t bh[4][2];
#pragma unroll
            for (int j = 0; j < 2; ++j) {
                int n = wn * 32 + j * 16 + (l & 7) + ((l >> 4) << 3);
                int c = 2 * ks + ((l >> 3) & 1);
                uint32_t t0r, t1r, t2r, t3r;
                ldsm_x4(t0r, t1r, t2r, t3r, Bc + n * 128 + ((c ^ (n & 7)) << 4));
                bh[j*2][0] = t0r; bh[j*2][1] = t1r; bh[j*2+1][0] = t2r; bh[j*2+1][1] = t3r;
            }
#pragma unroll
            for (int nt = 0; nt < 4; ++nt)
                mma16816h(acc[nt], a, bh[nt]);
        }
    }

    // epilogue
#pragma unroll
    for (int nt = 0; nt < 4; ++nt) {
        const int gc = wn * 32 + nt * 8 + 2 * (l & 3);
#pragma unroll
        for (int h = 0; h < 2; ++h) {
            const int gr = row0 + wm * 16 + (l >> 2) + h * 8;
            *(float2*)(out + ((size_t)(b * SEQ) + gr) * HD + gc) =
                make_float2(acc[nt][h * 2 + 0], acc[nt][h * 2 + 1]);
        }
    }
}

// ===========================================================================
extern "C" void kernel_launch(void* const* d_in, const int* in_sizes, int n_in,
                              void* d_out, int out_size)
{
    const float* q    = (const float*)d_in[0];
    const float* k    = (const float*)d_in[1];
    const float* v    = (const float*)d_in[2];
    const int*   mask = (const int*)d_in[3];

    float* out  = (float*)d_out;
    float* attn = out + (size_t)BATCH * SEQ * HD;

    cudaFuncSetAttribute(scores_mma_kernel,
                         cudaFuncAttributeMaxDynamicSharedMemorySize, 32768);
    cudaFuncSetAttribute(pv_mma_kernel,
                         cudaFuncAttributeMaxDynamicSharedMemorySize, 60672);

    prep_kernel<<<dim3(512, 3), 256>>>((const float4*)q, (const float4*)k, v, mask);

    scores_mma_kernel<<<dim3(16, 16, BATCH), 256, 32768>>>();
    pv_mma_kernel<<<dim3(32, BATCH), 256, 60672>>>(attn, out);
}

// round 12
// speedup vs baseline: 2.9953x; 1.0041x over previous
#include <cuda_runtime.h>
#include <cuda_fp16.h>
#include <cstdint>

#define SEQ   2048
#define HD    64
#define BATCH 16

// ---------------------------------------------------------------------------
// device scratch
// ---------------------------------------------------------------------------
__device__ __half    g_qh[BATCH * SEQ * HD];        // fp16(q)
__device__ __half    g_kh[BATCH * SEQ * HD];        // fp16(k)
__device__ __half    g_vh[BATCH * HD * SEQ];        // transposed [b][d][t], fp16
__device__ __half    g_e[(size_t)BATCH * SEQ * SEQ]; // unnormalized exp, fp16
__device__ float     g_part[BATCH * SEQ * 32];      // per-row per-coltile exp sums
__device__ uint32_t  g_maskbits[SEQ * (SEQ / 32)];

// ---------------------------------------------------------------------------
// helpers
// ---------------------------------------------------------------------------
__device__ __forceinline__ uint32_t smem_u32(const void* p) {
    uint32_t a;
    asm("{ .reg .u64 t; cvta.to.shared.u64 t, %1; cvt.u32.u64 %0, t; }" : "=r"(a) : "l"(p));
    return a;
}
__device__ __forceinline__ uint32_t hpack(float a, float b) {
    uint32_t r;
    asm("cvt.rn.f16x2.f32 %0, %1, %2;" : "=r"(r) : "f"(b), "f"(a));
    return r;
}
__device__ __forceinline__ void ldsm_x4(uint32_t& r0, uint32_t& r1, uint32_t& r2,
                                        uint32_t& r3, uint32_t addr) {
    asm volatile("ldmatrix.sync.aligned.m8n8.x4.shared.b16 {%0,%1,%2,%3}, [%4];"
                 : "=r"(r0), "=r"(r1), "=r"(r2), "=r"(r3) : "r"(addr));
}
__device__ __forceinline__ void mma16816h(float* c, const uint32_t* a, const uint32_t* b) {
    asm volatile("mma.sync.aligned.m16n8k16.row.col.f32.f16.f16.f32 "
                 "{%0,%1,%2,%3}, {%4,%5,%6,%7}, {%8,%9}, {%0,%1,%2,%3};"
                 : "+f"(c[0]), "+f"(c[1]), "+f"(c[2]), "+f"(c[3])
                 : "r"(a[0]), "r"(a[1]), "r"(a[2]), "r"(a[3]), "r"(b[0]), "r"(b[1]));
}
#define CP_ASYNC16(dst, src) \
    asm volatile("cp.async.cg.shared.global [%0], [%1], 16;" :: "r"(dst), "l"(src))
#define CP_COMMIT()  asm volatile("cp.async.commit_group;" ::: "memory")
#define CP_WAIT(n)   asm volatile("cp.async.wait_group %0;" :: "n"(n) : "memory")

// ===========================================================================
// fused prep: y=0 mask pack | y=1 q/k fp16 convert | y=2 v transpose fp16
// ===========================================================================
__global__ void __launch_bounds__(256) prep_kernel(
    const float4* __restrict__ q, const float4* __restrict__ k,
    const float* __restrict__ v, const int* __restrict__ mask)
{
    __shared__ float sm[64][129];            // used only by y == 2
    const int tid = threadIdx.x;

    if (blockIdx.y == 0) {
        const int gw = (blockIdx.x * 256 + tid) >> 5;
        const int l  = tid & 31;
        const int nwarps = gridDim.x * 8;
        const int nwords = SEQ * (SEQ / 32);
        for (int w = gw; w < nwords; w += nwarps) {
            const int row = w >> 6, wc = w & 63;
            int mv = mask[(size_t)row * SEQ + wc * 32 + l];
            uint32_t bits = __ballot_sync(~0u, mv != 0);
            if (l == 0) g_maskbits[w] = bits;
        }
    } else if (blockIdx.y == 1) {
        const int isK = blockIdx.x >= 256;
        const float4* src = isK ? k : q;
        uint2* hi = (uint2*)(isK ? g_kh : g_qh);
        const int n = BATCH * SEQ * HD / 4;
        const int stride = 256 * 256;
        for (int c = (blockIdx.x & 255) * 256 + tid; c < n; c += stride) {
            float4 x = src[c];
            hi[c] = make_uint2(hpack(x.x, x.y), hpack(x.z, x.w));
        }
    } else {
        if (blockIdx.x >= 256) return;
        const int b = blockIdx.x >> 4, t0 = (blockIdx.x & 15) * 128;
        const float* vb = v + (size_t)b * SEQ * HD;
#pragma unroll
        for (int i = 0; i < 8; ++i) {
            int chunk = tid + i * 256;
            int t = chunk >> 4, d4 = (chunk & 15) * 4;
            float4 x = *(const float4*)(vb + (size_t)(t0 + t) * HD + d4);
            sm[d4 + 0][t] = x.x; sm[d4 + 1][t] = x.y;
            sm[d4 + 2][t] = x.z; sm[d4 + 3][t] = x.w;
        }
        __syncthreads();
        const int r = tid >> 2, tb = (tid & 3) * 32;
        size_t obase = ((size_t)(b * 64 + r)) * SEQ + t0 + tb;
#pragma unroll
        for (int seg = 0; seg < 4; ++seg) {
            uint32_t h[4];
#pragma unroll
            for (int j = 0; j < 4; ++j)
                h[j] = hpack(sm[r][tb + seg * 8 + j * 2],
                             sm[r][tb + seg * 8 + j * 2 + 1]);
            *(uint4*)(g_vh + obase + seg * 8) = make_uint4(h[0], h[1], h[2], h[3]);
        }
    }
}

// ===========================================================================
// scores: CTA tile 128 rows x 64 cols (grid 32x16x16), warps 4x2, tile 32x32.
// e = maskbit ? exp((Qh Kh^T)/8) : 0 -> g_e (fp16); sums -> g_part[..][32]
// ===========================================================================
__global__ void __launch_bounds__(256, 3) scores_mma_kernel()
{
    extern __shared__ char smem[];
    constexpr int AHI = 0, BHI = 16384;
    const uint32_t sb = smem_u32(smem);
    const int tid = threadIdx.x, wid = tid >> 5, l = tid & 31;
    const int b = blockIdx.z, row0 = blockIdx.y * 128, col0 = blockIdx.x * 64;

    // loads: A 128x64 fp16 (1024 chunks), B 64x64 fp16 (512 chunks)
    {
        const __half* asrc = g_qh + ((size_t)(b * SEQ) + row0) * HD;
#pragma unroll
        for (int i = 0; i < 4; ++i) {
            int chunk = tid + i * 256;
            int r = chunk >> 3, c = chunk & 7;
            *(uint4*)(smem + AHI + r * 128 + ((c ^ (r & 7)) << 4)) =
                *(const uint4*)(asrc + (size_t)r * HD + c * 8);
        }
        const __half* bsrc = g_kh + ((size_t)(b * SEQ) + col0) * HD;
#pragma unroll
        for (int i = 0; i < 2; ++i) {
            int chunk = tid + i * 256;
            int r = chunk >> 3, c = chunk & 7;
            *(uint4*)(smem + BHI + r * 128 + ((c ^ (r & 7)) << 4)) =
                *(const uint4*)(bsrc + (size_t)r * HD + c * 8);
        }
    }
    __syncthreads();

    const int wm = wid >> 1, wn = wid & 1;           // 4 x 2 warps, tile 32x32
    float acc[2][4][4];
#pragma unroll
    for (int i = 0; i < 2; ++i)
#pragma unroll
        for (int j = 0; j < 4; ++j)
#pragma unroll
            for (int k = 0; k < 4; ++k) acc[i][j][k] = 0.f;

#pragma unroll
    for (int ks = 0; ks < 4; ++ks) {
        uint32_t a[2][4];
#pragma unroll
        for (int mt = 0; mt < 2; ++mt) {
            int r = wm * 32 + mt * 16 + (l & 15);
            int c = 2 * ks + (l >> 4);
            ldsm_x4(a[mt][0], a[mt][1], a[mt][2], a[mt][3],
                    sb + AHI + r * 128 + ((c ^ (r & 7)) << 4));
        }
        uint32_t bh[4][2];
#pragma unroll
        for (int j = 0; j < 2; ++j) {
            int n = wn * 32 + j * 16 + (l & 7) + ((l >> 4) << 3);
            int c = 2 * ks + ((l >> 3) & 1);
            uint32_t t0, t1, t2, t3;
            ldsm_x4(t0, t1, t2, t3, sb + BHI + n * 128 + ((c ^ (n & 7)) << 4));
            bh[j*2][0] = t0; bh[j*2][1] = t1; bh[j*2+1][0] = t2; bh[j*2+1][1] = t3;
        }
#pragma unroll
        for (int mt = 0; mt < 2; ++mt)
#pragma unroll
            for (int nt = 0; nt < 4; ++nt)
                mma16816h(acc[mt][nt], a[mt], bh[nt]);
    }

    __syncthreads();
    float* srow = (float*)smem;      // [2][128]

    float rs[2][2];
    rs[0][0] = rs[0][1] = rs[1][0] = rs[1][1] = 0.f;

    const int wbase = (col0 >> 5) + wn;
#pragma unroll
    for (int mt = 0; mt < 2; ++mt) {
#pragma unroll
        for (int h = 0; h < 2; ++h) {
            const int s = row0 + wm * 32 + mt * 16 + (l >> 2) + h * 8;
            const uint32_t w = g_maskbits[(size_t)s * 64 + wbase];
            __half* drow = g_e + ((size_t)(b * SEQ) + s) * SEQ + col0 + wn * 32;
            const int sh0 = 2 * (l & 3);
#pragma unroll
            for (int nt = 0; nt < 4; ++nt) {
                const uint32_t bits = w >> (nt * 8 + sh0);
                float e0 = (bits & 1u) ? __expf(acc[mt][nt][h * 2 + 0] * 0.125f) : 0.f;
                float e1 = (bits & 2u) ? __expf(acc[mt][nt][h * 2 + 1] * 0.125f) : 0.f;
                __stcs((uint32_t*)(drow + nt * 8 + sh0), hpack(e0, e1));
                rs[mt][h] += e0 + e1;
            }
        }
    }
#pragma unroll
    for (int mt = 0; mt < 2; ++mt)
#pragma unroll
        for (int h = 0; h < 2; ++h) {
            float v = rs[mt][h];
            v += __shfl_xor_sync(~0u, v, 1);
            v += __shfl_xor_sync(~0u, v, 2);
            rs[mt][h] = v;
        }
    if ((l & 3) == 0) {
#pragma unroll
        for (int mt = 0; mt < 2; ++mt)
#pragma unroll
            for (int h = 0; h < 2; ++h)
                srow[wn * 128 + wm * 32 + mt * 16 + (l >> 2) + h * 8] = rs[mt][h];
    }
    __syncthreads();
    if (tid < 128) {
        float s = srow[tid] + srow[128 + tid];
        g_part[((size_t)(b * SEQ) + row0 + tid) * 32 + blockIdx.x] = s;
    }
}

// ===========================================================================
// pv: 64-row tiles (512 CTAs), 3-stage cp.async pipeline on e+v tiles.
// transform: p = e*inv -> fp32 p to attn (final output) + fp16 A tile;
// out = p @ v. smem: EST 3x9216 | AP 8K | B 3x8K | sinv. 3 CTAs/SM.
// ===========================================================================
__global__ void __launch_bounds__(256, 3) pv_mma_kernel(
    float* __restrict__ attn, float* __restrict__ out)
{
    extern __shared__ char smem[];
    constexpr int EST = 0, ESTRIDE = 9216;                  // 64 rows * 144B
    constexpr int AP = 27648, BB = 35840, SINV = 60416;
    const uint32_t sb = smem_u32(smem);
    const int tid = threadIdx.x, wid = tid >> 5, l = tid & 31;
    const int b = blockIdx.y, row0 = blockIdx.x * 64;

    float* sinv = (float*)(smem + SINV);
    if (tid < 64) {
        const float4* pp = (const float4*)(g_part + ((size_t)(b * SEQ) + row0 + tid) * 32);
        float s = 0.f;
#pragma unroll
        for (int i = 0; i < 8; ++i) {
            float4 t = pp[i];
            s += (t.x + t.y) + (t.z + t.w);
        }
        sinv[tid] = 1.0f / s;
    }

    const __half* vh = g_vh + (size_t)(b * 64) * SEQ;
    const __half* erow = g_e + ((size_t)(b * SEQ) + row0) * SEQ;
    float* arow = attn + ((size_t)(b * SEQ) + row0) * SEQ;

    // prologue: stage tiles 0 and 1
#pragma unroll
    for (int st = 0; st < 2; ++st) {
        const int t0 = st * 64;
#pragma unroll
        for (int i = 0; i < 2; ++i) {
            int chunk = tid + i * 256;                 // 512 x 16B (e tile)
            int r = chunk >> 3, c = chunk & 7;
            CP_ASYNC16(sb + EST + st * ESTRIDE + r * 144 + c * 16,
                       erow + (size_t)r * SEQ + t0 + c * 8);
        }
#pragma unroll
        for (int i = 0; i < 2; ++i) {
            int chunk = tid + i * 256;                 // 512 x 16B (v)
            int r = chunk >> 3, c = chunk & 7;
            uint32_t dst = sb + BB + st * 8192 + r * 128 + ((c ^ (r & 7)) << 4);
            CP_ASYNC16(dst, vh + (size_t)r * SEQ + t0 + c * 8);
        }
        CP_COMMIT();
    }

    const int wm = wid >> 1, wn = wid & 1;             // 4 x 2 warps, tile 16x32
    float acc[4][4];
#pragma unroll
    for (int j = 0; j < 4; ++j)
#pragma unroll
        for (int k = 0; k < 4; ++k) acc[j][k] = 0.f;

    for (int tile = 0; tile < 32; ++tile) {
        const int t0 = tile * 64;
        const int buf = tile % 3;

        if (tile < 31) { CP_WAIT(1); } else { CP_WAIT(0); }
        __syncthreads();

        // prefetch tile+2 (two iterations of latency hiding)
        if (tile < 30) {
            const int nt0 = t0 + 128;
            const int nbuf = (tile + 2) % 3;
#pragma unroll
            for (int i = 0; i < 2; ++i) {
                int chunk = tid + i * 256;
                int r = chunk >> 3, c = chunk & 7;
                CP_ASYNC16(sb + EST + nbuf * ESTRIDE + r * 144 + c * 16,
                           erow + (size_t)r * SEQ + nt0 + c * 8);
            }
#pragma unroll
            for (int i = 0; i < 2; ++i) {
                int chunk = tid + i * 256;
                int r = chunk >> 3, c = chunk & 7;
                uint32_t dst = sb + BB + nbuf * 8192 + r * 128 + ((c ^ (r & 7)) << 4);
                CP_ASYNC16(dst, vh + (size_t)r * SEQ + nt0 + c * 8);
            }
            CP_COMMIT();
        }

        // transform: fp16 e -> fp32 p (write, streaming) + fp16 A tile
        const char* est = smem + EST + buf * ESTRIDE;
#pragma unroll
        for (int i = 0; i < 2; ++i) {
            int chunk = tid + i * 256;                 // 512 chunks of 8 halfs
            int r = chunk >> 3, c = chunk & 7;
            uint4 raw = *(const uint4*)(est + r * 144 + c * 16);
            float2 f0 = __half22float2(*(__half2*)&raw.x);
            float2 f1 = __half22float2(*(__half2*)&raw.y);
            float2 f2 = __half22float2(*(__half2*)&raw.z);
            float2 f3 = __half22float2(*(__half2*)&raw.w);
            const float inv = sinv[r];
            float p0 = f0.x * inv, p1 = f0.y * inv, p2 = f1.x * inv, p3 = f1.y * inv;
            float p4 = f2.x * inv, p5 = f2.y * inv, p6 = f3.x * inv, p7 = f3.y * inv;
            float* gp = arow + (size_t)r * SEQ + t0 + c * 8;
            __stcs((float4*)gp,       make_float4(p0, p1, p2, p3));
            __stcs((float4*)(gp + 4), make_float4(p4, p5, p6, p7));
            uint32_t off = r * 128 + ((c ^ (r & 7)) << 4);
            *(uint4*)(smem + AP + off) =
                make_uint4(hpack(p0, p1), hpack(p2, p3), hpack(p4, p5), hpack(p6, p7));
        }
        __syncthreads();

        const uint32_t Bc = sb + BB + buf * 8192;

#pragma unroll
        for (int ks = 0; ks < 4; ++ks) {
            uint32_t a[4];
            {
                int r = wm * 16 + (l & 15);
                int c = 2 * ks + (l >> 4);
                ldsm_x4(a[0], a[1], a[2], a[3],
                        sb + AP + r * 128 + ((c ^ (r & 7)) << 4));
            }
            uint32_t bh[4][2];
#pragma unroll
            for (int j = 0; j < 2; ++j) {
                int n = wn * 32 + j * 16 + (l & 7) + ((l >> 4) << 3);
                int c = 2 * ks + ((l >> 3) & 1);
                uint32_t t0r, t1r, t2r, t3r;
                ldsm_x4(t0r, t1r, t2r, t3r, Bc + n * 128 + ((c ^ (n & 7)) << 4));
                bh[j*2][0] = t0r; bh[j*2][1] = t1r; bh[j*2+1][0] = t2r; bh[j*2+1][1] = t3r;
            }
#pragma unroll
            for (int nt = 0; nt < 4; ++nt)
                mma16816h(acc[nt], a, bh[nt]);
        }
    }

    // epilogue
#pragma unroll
    for (int nt = 0; nt < 4; ++nt) {
        const int gc = wn * 32 + nt * 8 + 2 * (l & 3);
#pragma unroll
        for (int h = 0; h < 2; ++h) {
            const int gr = row0 + wm * 16 + (l >> 2) + h * 8;
            *(float2*)(out + ((size_t)(b * SEQ) + gr) * HD + gc) =
                make_float2(acc[nt][h * 2 + 0], acc[nt][h * 2 + 1]);
        }
    }
}

// ===========================================================================
extern "C" void kernel_launch(void* const* d_in, const int* in_sizes, int n_in,
                              void* d_out, int out_size)
{
    const float* q    = (const float*)d_in[0];
    const float* k    = (const float*)d_in[1];
    const float* v    = (const float*)d_in[2];
    const int*   mask = (const int*)d_in[3];

    float* out  = (float*)d_out;
    float* attn = out + (size_t)BATCH * SEQ * HD;

    cudaFuncSetAttribute(scores_mma_kernel,
                         cudaFuncAttributeMaxDynamicSharedMemorySize, 24576);
    cudaFuncSetAttribute(pv_mma_kernel,
                         cudaFuncAttributeMaxDynamicSharedMemorySize, 60672);

    prep_kernel<<<dim3(512, 3), 256>>>((const float4*)q, (const float4*)k, v, mask);

    scores_mma_kernel<<<dim3(32, 16, BATCH), 256, 24576>>>();
    pv_mma_kernel<<<dim3(32, BATCH), 256, 60672>>>(attn, out);
}

// round 13
// speedup vs baseline: 3.1067x; 1.0372x over previous
#include <cuda_runtime.h>
#include <cuda_fp16.h>
#include <cstdint>

#define SEQ   2048
#define HD    64
#define BATCH 16

// ---------------------------------------------------------------------------
// device scratch
// ---------------------------------------------------------------------------
__device__ __half    g_qh[BATCH * SEQ * HD];        // fp16(q)
__device__ __half    g_kh[BATCH * SEQ * HD];        // fp16(k)
__device__ __half    g_vh[BATCH * HD * SEQ];        // transposed [b][d][t], fp16
__device__ float     g_part[BATCH * SEQ * 32];      // per-row per-coltile exp sums
__device__ uint32_t  g_maskbits[SEQ * (SEQ / 32)];

// ---------------------------------------------------------------------------
// helpers
// ---------------------------------------------------------------------------
__device__ __forceinline__ uint32_t smem_u32(const void* p) {
    uint32_t a;
    asm("{ .reg .u64 t; cvta.to.shared.u64 t, %1; cvt.u32.u64 %0, t; }" : "=r"(a) : "l"(p));
    return a;
}
__device__ __forceinline__ uint32_t hpack(float a, float b) {
    uint32_t r;
    asm("cvt.rn.f16x2.f32 %0, %1, %2;" : "=r"(r) : "f"(b), "f"(a));
    return r;
}
__device__ __forceinline__ void ldsm_x4(uint32_t& r0, uint32_t& r1, uint32_t& r2,
                                        uint32_t& r3, uint32_t addr) {
    asm volatile("ldmatrix.sync.aligned.m8n8.x4.shared.b16 {%0,%1,%2,%3}, [%4];"
                 : "=r"(r0), "=r"(r1), "=r"(r2), "=r"(r3) : "r"(addr));
}
__device__ __forceinline__ void mma16816h(float* c, const uint32_t* a, const uint32_t* b) {
    asm volatile("mma.sync.aligned.m16n8k16.row.col.f32.f16.f16.f32 "
                 "{%0,%1,%2,%3}, {%4,%5,%6,%7}, {%8,%9}, {%0,%1,%2,%3};"
                 : "+f"(c[0]), "+f"(c[1]), "+f"(c[2]), "+f"(c[3])
                 : "r"(a[0]), "r"(a[1]), "r"(a[2]), "r"(a[3]), "r"(b[0]), "r"(b[1]));
}
#define CP_ASYNC16(dst, src) \
    asm volatile("cp.async.cg.shared.global [%0], [%1], 16;" :: "r"(dst), "l"(src))
#define CP_COMMIT()  asm volatile("cp.async.commit_group;" ::: "memory")
#define CP_WAIT(n)   asm volatile("cp.async.wait_group %0;" :: "n"(n) : "memory")

// ===========================================================================
// fused prep: y=0 mask pack | y=1 q/k fp16 convert | y=2 v transpose fp16
// ===========================================================================
__global__ void __launch_bounds__(256) prep_kernel(
    const float4* __restrict__ q, const float4* __restrict__ k,
    const float* __restrict__ v, const int* __restrict__ mask)
{
    __shared__ float sm[64][129];            // used only by y == 2
    const int tid = threadIdx.x;

    if (blockIdx.y == 0) {
        const int gw = (blockIdx.x * 256 + tid) >> 5;
        const int l  = tid & 31;
        const int nwarps = gridDim.x * 8;
        const int nwords = SEQ * (SEQ / 32);
        for (int w = gw; w < nwords; w += nwarps) {
            const int row = w >> 6, wc = w & 63;
            int mv = mask[(size_t)row * SEQ + wc * 32 + l];
            uint32_t bits = __ballot_sync(~0u, mv != 0);
            if (l == 0) g_maskbits[w] = bits;
        }
    } else if (blockIdx.y == 1) {
        const int isK = blockIdx.x >= 256;
        const float4* src = isK ? k : q;
        uint2* hi = (uint2*)(isK ? g_kh : g_qh);
        const int n = BATCH * SEQ * HD / 4;
        const int stride = 256 * 256;
        for (int c = (blockIdx.x & 255) * 256 + tid; c < n; c += stride) {
            float4 x = src[c];
            hi[c] = make_uint2(hpack(x.x, x.y), hpack(x.z, x.w));
        }
    } else {
        if (blockIdx.x >= 256) return;
        const int b = blockIdx.x >> 4, t0 = (blockIdx.x & 15) * 128;
        const float* vb = v + (size_t)b * SEQ * HD;
#pragma unroll
        for (int i = 0; i < 8; ++i) {
            int chunk = tid + i * 256;
            int t = chunk >> 4, d4 = (chunk & 15) * 4;
            float4 x = *(const float4*)(vb + (size_t)(t0 + t) * HD + d4);
            sm[d4 + 0][t] = x.x; sm[d4 + 1][t] = x.y;
            sm[d4 + 2][t] = x.z; sm[d4 + 3][t] = x.w;
        }
        __syncthreads();
        const int r = tid >> 2, tb = (tid & 3) * 32;
        size_t obase = ((size_t)(b * 64 + r)) * SEQ + t0 + tb;
#pragma unroll
        for (int seg = 0; seg < 4; ++seg) {
            uint32_t h[4];
#pragma unroll
            for (int j = 0; j < 4; ++j)
                h[j] = hpack(sm[r][tb + seg * 8 + j * 2],
                             sm[r][tb + seg * 8 + j * 2 + 1]);
            *(uint4*)(g_vh + obase + seg * 8) = make_uint4(h[0], h[1], h[2], h[3]);
        }
    }
}

// ===========================================================================
// scores: row-sum-only pass. sum_t( maskbit ? exp((Qh Kh^T)/8) : 0 )
// CTA tile 128 rows x 64 cols (grid 32x16x16) -> g_part[row][32]
// ===========================================================================
__global__ void __launch_bounds__(256, 3) scores_mma_kernel()
{
    extern __shared__ char smem[];
    constexpr int AHI = 0, BHI = 16384;
    const uint32_t sb = smem_u32(smem);
    const int tid = threadIdx.x, wid = tid >> 5, l = tid & 31;
    const int b = blockIdx.z, row0 = blockIdx.y * 128, col0 = blockIdx.x * 64;

    {
        const __half* asrc = g_qh + ((size_t)(b * SEQ) + row0) * HD;
#pragma unroll
        for (int i = 0; i < 4; ++i) {
            int chunk = tid + i * 256;
            int r = chunk >> 3, c = chunk & 7;
            *(uint4*)(smem + AHI + r * 128 + ((c ^ (r & 7)) << 4)) =
                *(const uint4*)(asrc + (size_t)r * HD + c * 8);
        }
        const __half* bsrc = g_kh + ((size_t)(b * SEQ) + col0) * HD;
#pragma unroll
        for (int i = 0; i < 2; ++i) {
            int chunk = tid + i * 256;
            int r = chunk >> 3, c = chunk & 7;
            *(uint4*)(smem + BHI + r * 128 + ((c ^ (r & 7)) << 4)) =
                *(const uint4*)(bsrc + (size_t)r * HD + c * 8);
        }
    }
    __syncthreads();

    const int wm = wid >> 1, wn = wid & 1;           // 4 x 2 warps, tile 32x32
    float acc[2][4][4];
#pragma unroll
    for (int i = 0; i < 2; ++i)
#pragma unroll
        for (int j = 0; j < 4; ++j)
#pragma unroll
            for (int k = 0; k < 4; ++k) acc[i][j][k] = 0.f;

#pragma unroll
    for (int ks = 0; ks < 4; ++ks) {
        uint32_t a[2][4];
#pragma unroll
        for (int mt = 0; mt < 2; ++mt) {
            int r = wm * 32 + mt * 16 + (l & 15);
            int c = 2 * ks + (l >> 4);
            ldsm_x4(a[mt][0], a[mt][1], a[mt][2], a[mt][3],
                    sb + AHI + r * 128 + ((c ^ (r & 7)) << 4));
        }
        uint32_t bh[4][2];
#pragma unroll
        for (int j = 0; j < 2; ++j) {
            int n = wn * 32 + j * 16 + (l & 7) + ((l >> 4) << 3);
            int c = 2 * ks + ((l >> 3) & 1);
            uint32_t t0, t1, t2, t3;
            ldsm_x4(t0, t1, t2, t3, sb + BHI + n * 128 + ((c ^ (n & 7)) << 4));
            bh[j*2][0] = t0; bh[j*2][1] = t1; bh[j*2+1][0] = t2; bh[j*2+1][1] = t3;
        }
#pragma unroll
        for (int mt = 0; mt < 2; ++mt)
#pragma unroll
            for (int nt = 0; nt < 4; ++nt)
                mma16816h(acc[mt][nt], a[mt], bh[nt]);
    }

    __syncthreads();
    float* srow = (float*)smem;      // [2][128]

    float rs[2][2];
    rs[0][0] = rs[0][1] = rs[1][0] = rs[1][1] = 0.f;

    const int wbase = (col0 >> 5) + wn;
#pragma unroll
    for (int mt = 0; mt < 2; ++mt) {
#pragma unroll
        for (int h = 0; h < 2; ++h) {
            const int s = row0 + wm * 32 + mt * 16 + (l >> 2) + h * 8;
            const uint32_t w = g_maskbits[(size_t)s * 64 + wbase];
            const int sh0 = 2 * (l & 3);
#pragma unroll
            for (int nt = 0; nt < 4; ++nt) {
                const uint32_t bits = w >> (nt * 8 + sh0);
                float e0 = (bits & 1u) ? __expf(acc[mt][nt][h * 2 + 0] * 0.125f) : 0.f;
                float e1 = (bits & 2u) ? __expf(acc[mt][nt][h * 2 + 1] * 0.125f) : 0.f;
                rs[mt][h] += e0 + e1;
            }
        }
    }
#pragma unroll
    for (int mt = 0; mt < 2; ++mt)
#pragma unroll
        for (int h = 0; h < 2; ++h) {
            float v = rs[mt][h];
            v += __shfl_xor_sync(~0u, v, 1);
            v += __shfl_xor_sync(~0u, v, 2);
            rs[mt][h] = v;
        }
    if ((l & 3) == 0) {
#pragma unroll
        for (int mt = 0; mt < 2; ++mt)
#pragma unroll
            for (int h = 0; h < 2; ++h)
                srow[wn * 128 + wm * 32 + mt * 16 + (l >> 2) + h * 8] = rs[mt][h];
    }
    __syncthreads();
    if (tid < 128) {
        float s = srow[tid] + srow[128 + tid];
        g_part[((size_t)(b * SEQ) + row0 + tid) * 32 + blockIdx.x] = s;
    }
}

// ===========================================================================
// pv (fused): per 64-row CTA, per 64-col k-tile:
//   QK mma (q tile resident, k tile streamed) -> scores in frags
//   frag epilogue: p = mask ? exp(s/8)*inv : 0 -> fp32 attn write + fp16 AP
//   PV mma: out += p @ v-tile
// k,v tiles double-buffered via cp.async (L2-resident per batch).
// smem: QT 8K | KT 2x8K | VT 2x8K | AP 8K | SINV
// ===========================================================================
__global__ void __launch_bounds__(256, 2) pv_mma_kernel(
    float* __restrict__ attn, float* __restrict__ out)
{
    extern __shared__ char smem[];
    constexpr int QT = 0, KT = 8192, VT = 24576, AP = 40960, SINV = 49152;
    const uint32_t sb = smem_u32(smem);
    const int tid = threadIdx.x, wid = tid >> 5, l = tid & 31;
    const int b = blockIdx.y, row0 = blockIdx.x * 64;

    float* sinv = (float*)(smem + SINV);
    if (tid < 64) {
        const float4* pp = (const float4*)(g_part + ((size_t)(b * SEQ) + row0 + tid) * 32);
        float s = 0.f;
#pragma unroll
        for (int i = 0; i < 8; ++i) {
            float4 t = pp[i];
            s += (t.x + t.y) + (t.z + t.w);
        }
        sinv[tid] = 1.0f / s;
    }

    const __half* qrow  = g_qh + ((size_t)(b * SEQ) + row0) * HD;
    const __half* kbase = g_kh + (size_t)b * SEQ * HD;
    const __half* vh    = g_vh + (size_t)(b * 64) * SEQ;
    float* arow = attn + ((size_t)(b * SEQ) + row0) * SEQ;

    // prologue: q tile + k/v tile 0 (group 0)
    {
#pragma unroll
        for (int i = 0; i < 2; ++i) {
            int chunk = tid + i * 256;                 // 512 x 16B (q)
            int r = chunk >> 3, c = chunk & 7;
            CP_ASYNC16(sb + QT + r * 128 + ((c ^ (r & 7)) << 4),
                       qrow + (size_t)r * HD + c * 8);
        }
#pragma unroll
        for (int i = 0; i < 2; ++i) {
            int chunk = tid + i * 256;                 // 512 x 16B (k tile 0)
            int r = chunk >> 3, c = chunk & 7;
            CP_ASYNC16(sb + KT + r * 128 + ((c ^ (r & 7)) << 4),
                       kbase + (size_t)r * HD + c * 8);
        }
#pragma unroll
        for (int i = 0; i < 2; ++i) {
            int chunk = tid + i * 256;                 // 512 x 16B (v tile 0)
            int r = chunk >> 3, c = chunk & 7;
            CP_ASYNC16(sb + VT + r * 128 + ((c ^ (r & 7)) << 4),
                       vh + (size_t)r * SEQ + c * 8);
        }
        CP_COMMIT();
    }

    const int wm = wid >> 1, wn = wid & 1;             // 4 x 2 warps
    float oacc[4][4];
#pragma unroll
    for (int j = 0; j < 4; ++j)
#pragma unroll
        for (int k = 0; k < 4; ++k) oacc[j][k] = 0.f;

    const int rl0 = wm * 16 + (l >> 2);                // local row, h=0
    const float inv0 = 0.f;                            // (loaded per-iteration from smem)

    for (int tile = 0; tile < 32; ++tile) {
        const int t0 = tile * 64;
        const int buf = tile & 1;

        CP_WAIT(0);
        __syncthreads();                                // tiles ready; AP reads of prev tile done

        // prefetch k/v of tile+1 into other buffer (hidden by compute below)
        if (tile < 31) {
            const int nt0 = t0 + 64;
            const int nbuf = buf ^ 1;
#pragma unroll
            for (int i = 0; i < 2; ++i) {
                int chunk = tid + i * 256;
                int r = chunk >> 3, c = chunk & 7;
                CP_ASYNC16(sb + KT + nbuf * 8192 + r * 128 + ((c ^ (r & 7)) << 4),
                           kbase + (size_t)(nt0 + r) * HD + c * 8);
            }
#pragma unroll
            for (int i = 0; i < 2; ++i) {
                int chunk = tid + i * 256;
                int r = chunk >> 3, c = chunk & 7;
                CP_ASYNC16(sb + VT + nbuf * 8192 + r * 128 + ((c ^ (r & 7)) << 4),
                           vh + (size_t)r * SEQ + nt0 + c * 8);
            }
            CP_COMMIT();
        }

        // ---- QK mma: scores for this 64x64 tile
        float sacc[4][4];
#pragma unroll
        for (int j = 0; j < 4; ++j)
#pragma unroll
            for (int k = 0; k < 4; ++k) sacc[j][k] = 0.f;

        const uint32_t Kc = sb + KT + buf * 8192;
#pragma unroll
        for (int ks = 0; ks < 4; ++ks) {
            uint32_t a[4];
            {
                int r = wm * 16 + (l & 15);
                int c = 2 * ks + (l >> 4);
                ldsm_x4(a[0], a[1], a[2], a[3],
                        sb + QT + r * 128 + ((c ^ (r & 7)) << 4));
            }
            uint32_t bh[4][2];
#pragma unroll
            for (int j = 0; j < 2; ++j) {
                int n = wn * 32 + j * 16 + (l & 7) + ((l >> 4) << 3);
                int c = 2 * ks + ((l >> 3) & 1);
                uint32_t t0r, t1r, t2r, t3r;
                ldsm_x4(t0r, t1r, t2r, t3r, Kc + n * 128 + ((c ^ (n & 7)) << 4));
                bh[j*2][0] = t0r; bh[j*2][1] = t1r; bh[j*2+1][0] = t2r; bh[j*2+1][1] = t3r;
            }
#pragma unroll
            for (int nt = 0; nt < 4; ++nt)
                mma16816h(sacc[nt], a, bh[nt]);
        }

        // ---- fragment epilogue: p = mask ? exp(s/8)*inv : 0
        const int sh0 = 2 * (l & 3);
#pragma unroll
        for (int h = 0; h < 2; ++h) {
            const int rl = rl0 + h * 8;
            const uint32_t w = g_maskbits[(size_t)(row0 + rl) * 64 + (t0 >> 5) + wn];
            const float inv = sinv[rl];
            float* gp = arow + (size_t)rl * SEQ + t0 + wn * 32 + sh0;
#pragma unroll
            for (int nt = 0; nt < 4; ++nt) {
                const uint32_t bits = w >> (nt * 8 + sh0);
                float p0 = (bits & 1u) ? __expf(sacc[nt][h * 2 + 0] * 0.125f) * inv : 0.f;
                float p1 = (bits & 2u) ? __expf(sacc[nt][h * 2 + 1] * 0.125f) * inv : 0.f;
                __stcs((float2*)(gp + nt * 8), make_float2(p0, p1));
                // fp16 p into AP (swizzled, chunk = 4*wn + nt)
                uint32_t chunk = (uint32_t)((4 * wn + nt) ^ (rl & 7));
                *(uint32_t*)(smem + AP + rl * 128 + chunk * 16 + 4 * (l & 3)) =
                    hpack(p0, p1);
            }
        }
        __syncthreads();                                // AP complete

        // ---- PV mma: out += p @ v
        const uint32_t Vc = sb + VT + buf * 8192;
#pragma unroll
        for (int ks = 0; ks < 4; ++ks) {
            uint32_t a[4];
            {
                int r = wm * 16 + (l & 15);
                int c = 2 * ks + (l >> 4);
                ldsm_x4(a[0], a[1], a[2], a[3],
                        sb + AP + r * 128 + ((c ^ (r & 7)) << 4));
            }
            uint32_t bh[4][2];
#pragma unroll
            for (int j = 0; j < 2; ++j) {
                int n = wn * 32 + j * 16 + (l & 7) + ((l >> 4) << 3);
                int c = 2 * ks + ((l >> 3) & 1);
                uint32_t t0r, t1r, t2r, t3r;
                ldsm_x4(t0r, t1r, t2r, t3r, Vc + n * 128 + ((c ^ (n & 7)) << 4));
                bh[j*2][0] = t0r; bh[j*2][1] = t1r; bh[j*2+1][0] = t2r; bh[j*2+1][1] = t3r;
            }
#pragma unroll
            for (int nt = 0; nt < 4; ++nt)
                mma16816h(oacc[nt], a, bh[nt]);
        }
    }

    // epilogue
#pragma unroll
    for (int nt = 0; nt < 4; ++nt) {
        const int gc = wn * 32 + nt * 8 + 2 * (l & 3);
#pragma unroll
        for (int h = 0; h < 2; ++h) {
            const int gr = row0 + wm * 16 + (l >> 2) + h * 8;
            *(float2*)(out + ((size_t)(b * SEQ) + gr) * HD + gc) =
                make_float2(oacc[nt][h * 2 + 0], oacc[nt][h * 2 + 1]);
        }
    }
}

// ===========================================================================
extern "C" void kernel_launch(void* const* d_in, const int* in_sizes, int n_in,
                              void* d_out, int out_size)
{
    const float* q    = (const float*)d_in[0];
    const float* k    = (const float*)d_in[1];
    const float* v    = (const float*)d_in[2];
    const int*   mask = (const int*)d_in[3];

    float* out  = (float*)d_out;
    float* attn = out + (size_t)BATCH * SEQ * HD;

    cudaFuncSetAttribute(scores_mma_kernel,
                         cudaFuncAttributeMaxDynamicSharedMemorySize, 24576);
    cudaFuncSetAttribute(pv_mma_kernel,
                         cudaFuncAttributeMaxDynamicSharedMemorySize, 49408);

    prep_kernel<<<dim3(512, 3), 256>>>((const float4*)q, (const float4*)k, v, mask);

    scores_mma_kernel<<<dim3(32, 16, BATCH), 256, 24576>>>();
    pv_mma_kernel<<<dim3(32, BATCH), 256, 49408>>>(attn, out);
}

// round 14
// speedup vs baseline: 3.3486x; 1.0779x over previous
#include <cuda_runtime.h>
#include <cuda_fp16.h>
#include <cstdint>

#define SEQ   2048
#define HD    64
#define BATCH 16

// ---------------------------------------------------------------------------
// device scratch
// ---------------------------------------------------------------------------
__device__ __half    g_qh[BATCH * SEQ * HD];        // fp16(q / 8)
__device__ __half    g_kh[BATCH * SEQ * HD];        // fp16(k)
__device__ __half    g_vh[BATCH * HD * SEQ];        // transposed [b][d][t], fp16
__device__ float     g_part[BATCH * SEQ * 32];      // per-row per-coltile exp sums
__device__ uint32_t  g_maskbits[SEQ * (SEQ / 32)];

#define LOG2E 1.4426950408889634f

// ---------------------------------------------------------------------------
// helpers
// ---------------------------------------------------------------------------
__device__ __forceinline__ uint32_t smem_u32(const void* p) {
    uint32_t a;
    asm("{ .reg .u64 t; cvta.to.shared.u64 t, %1; cvt.u32.u64 %0, t; }" : "=r"(a) : "l"(p));
    return a;
}
__device__ __forceinline__ uint32_t hpack(float a, float b) {
    uint32_t r;
    asm("cvt.rn.f16x2.f32 %0, %1, %2;" : "=r"(r) : "f"(b), "f"(a));
    return r;
}
__device__ __forceinline__ float ex2f(float x) {
    float r;
    asm("ex2.approx.ftz.f32 %0, %1;" : "=f"(r) : "f"(x));
    return r;
}
__device__ __forceinline__ void ldsm_x4(uint32_t& r0, uint32_t& r1, uint32_t& r2,
                                        uint32_t& r3, uint32_t addr) {
    asm volatile("ldmatrix.sync.aligned.m8n8.x4.shared.b16 {%0,%1,%2,%3}, [%4];"
                 : "=r"(r0), "=r"(r1), "=r"(r2), "=r"(r3) : "r"(addr));
}
__device__ __forceinline__ void mma16816h(float* c, const uint32_t* a, const uint32_t* b) {
    asm volatile("mma.sync.aligned.m16n8k16.row.col.f32.f16.f16.f32 "
                 "{%0,%1,%2,%3}, {%4,%5,%6,%7}, {%8,%9}, {%0,%1,%2,%3};"
                 : "+f"(c[0]), "+f"(c[1]), "+f"(c[2]), "+f"(c[3])
                 : "r"(a[0]), "r"(a[1]), "r"(a[2]), "r"(a[3]), "r"(b[0]), "r"(b[1]));
}
#define CP_ASYNC16(dst, src) \
    asm volatile("cp.async.cg.shared.global [%0], [%1], 16;" :: "r"(dst), "l"(src))
#define CP_COMMIT()  asm volatile("cp.async.commit_group;" ::: "memory")
#define CP_WAIT(n)   asm volatile("cp.async.wait_group %0;" :: "n"(n) : "memory")
#define PAIR_BAR(id) asm volatile("bar.sync %0, 64;" :: "r"(id) : "memory")

// ===========================================================================
// fused prep: y=0 mask pack | y=1 q/8, k fp16 convert | y=2 v transpose fp16
// ===========================================================================
__global__ void __launch_bounds__(256) prep_kernel(
    const float4* __restrict__ q, const float4* __restrict__ k,
    const float* __restrict__ v, const int* __restrict__ mask)
{
    __shared__ float sm[64][129];            // used only by y == 2
    const int tid = threadIdx.x;

    if (blockIdx.y == 0) {
        // mask -> bitmask; 4 words per warp per iteration (int4 + shfl OR-tree)
        const int gw = (blockIdx.x * 256 + tid) >> 5;
        const int l  = tid & 31;
        const int nwarps = gridDim.x * 8;
        const int ngroups = SEQ * (SEQ / 32) / 4;      // 32768
        for (int g = gw; g < ngroups; g += nwarps) {
            int4 mv = *(const int4*)(mask + (size_t)128 * g + 4 * l);
            uint32_t nib = (uint32_t)(mv.x != 0) | ((uint32_t)(mv.y != 0) << 1) |
                           ((uint32_t)(mv.z != 0) << 2) | ((uint32_t)(mv.w != 0) << 3);
            uint32_t bits = nib << (4 * (l & 7));
            bits |= __shfl_xor_sync(~0u, bits, 1);
            bits |= __shfl_xor_sync(~0u, bits, 2);
            bits |= __shfl_xor_sync(~0u, bits, 4);
            if ((l & 7) == 0) g_maskbits[4 * g + (l >> 3)] = bits;
        }
    } else if (blockIdx.y == 1) {
        const int isK = blockIdx.x >= 256;
        const float4* src = isK ? k : q;
        uint2* hi = (uint2*)(isK ? g_kh : g_qh);
        const float scale = isK ? 1.0f : 0.125f;
        const int n = BATCH * SEQ * HD / 4;
        const int stride = 256 * 256;
        for (int c = (blockIdx.x & 255) * 256 + tid; c < n; c += stride) {
            float4 x = src[c];
            hi[c] = make_uint2(hpack(x.x * scale, x.y * scale),
                               hpack(x.z * scale, x.w * scale));
        }
    } else {
        if (blockIdx.x >= 256) return;
        const int b = blockIdx.x >> 4, t0 = (blockIdx.x & 15) * 128;
        const float* vb = v + (size_t)b * SEQ * HD;
#pragma unroll
        for (int i = 0; i < 8; ++i) {
            int chunk = tid + i * 256;
            int t = chunk >> 4, d4 = (chunk & 15) * 4;
            float4 x = *(const float4*)(vb + (size_t)(t0 + t) * HD + d4);
            sm[d4 + 0][t] = x.x; sm[d4 + 1][t] = x.y;
            sm[d4 + 2][t] = x.z; sm[d4 + 3][t] = x.w;
        }
        __syncthreads();
        const int r = tid >> 2, tb = (tid & 3) * 32;
        size_t obase = ((size_t)(b * 64 + r)) * SEQ + t0 + tb;
#pragma unroll
        for (int seg = 0; seg < 4; ++seg) {
            uint32_t h[4];
#pragma unroll
            for (int j = 0; j < 4; ++j)
                h[j] = hpack(sm[r][tb + seg * 8 + j * 2],
                             sm[r][tb + seg * 8 + j * 2 + 1]);
            *(uint4*)(g_vh + obase + seg * 8) = make_uint4(h[0], h[1], h[2], h[3]);
        }
    }
}

// ===========================================================================
// scores: row-sum-only pass. sum_t( maskbit ? exp2(s*log2e) : 0 ), s=(q/8)k
// CTA tile 128 rows x 64 cols (grid 32x16x16) -> g_part[row][32]
// ===========================================================================
__global__ void __launch_bounds__(256, 3) scores_mma_kernel()
{
    extern __shared__ char smem[];
    constexpr int AHI = 0, BHI = 16384;
    const uint32_t sb = smem_u32(smem);
    const int tid = threadIdx.x, wid = tid >> 5, l = tid & 31;
    const int b = blockIdx.z, row0 = blockIdx.y * 128, col0 = blockIdx.x * 64;

    {
        const __half* asrc = g_qh + ((size_t)(b * SEQ) + row0) * HD;
#pragma unroll
        for (int i = 0; i < 4; ++i) {
            int chunk = tid + i * 256;
            int r = chunk >> 3, c = chunk & 7;
            *(uint4*)(smem + AHI + r * 128 + ((c ^ (r & 7)) << 4)) =
                *(const uint4*)(asrc + (size_t)r * HD + c * 8);
        }
        const __half* bsrc = g_kh + ((size_t)(b * SEQ) + col0) * HD;
#pragma unroll
        for (int i = 0; i < 2; ++i) {
            int chunk = tid + i * 256;
            int r = chunk >> 3, c = chunk & 7;
            *(uint4*)(smem + BHI + r * 128 + ((c ^ (r & 7)) << 4)) =
                *(const uint4*)(bsrc + (size_t)r * HD + c * 8);
        }
    }
    __syncthreads();

    const int wm = wid >> 1, wn = wid & 1;           // 4 x 2 warps, tile 32x32
    float acc[2][4][4];
#pragma unroll
    for (int i = 0; i < 2; ++i)
#pragma unroll
        for (int j = 0; j < 4; ++j)
#pragma unroll
            for (int k = 0; k < 4; ++k) acc[i][j][k] = 0.f;

#pragma unroll
    for (int ks = 0; ks < 4; ++ks) {
        uint32_t a[2][4];
#pragma unroll
        for (int mt = 0; mt < 2; ++mt) {
            int r = wm * 32 + mt * 16 + (l & 15);
            int c = 2 * ks + (l >> 4);
            ldsm_x4(a[mt][0], a[mt][1], a[mt][2], a[mt][3],
                    sb + AHI + r * 128 + ((c ^ (r & 7)) << 4));
        }
        uint32_t bh[4][2];
#pragma unroll
        for (int j = 0; j < 2; ++j) {
            int n = wn * 32 + j * 16 + (l & 7) + ((l >> 4) << 3);
            int c = 2 * ks + ((l >> 3) & 1);
            uint32_t t0, t1, t2, t3;
            ldsm_x4(t0, t1, t2, t3, sb + BHI + n * 128 + ((c ^ (n & 7)) << 4));
            bh[j*2][0] = t0; bh[j*2][1] = t1; bh[j*2+1][0] = t2; bh[j*2+1][1] = t3;
        }
#pragma unroll
        for (int mt = 0; mt < 2; ++mt)
#pragma unroll
            for (int nt = 0; nt < 4; ++nt)
                mma16816h(acc[mt][nt], a[mt], bh[nt]);
    }

    __syncthreads();
    float* srow = (float*)smem;      // [2][128]

    float rs[2][2];
    rs[0][0] = rs[0][1] = rs[1][0] = rs[1][1] = 0.f;

    const int wbase = (col0 >> 5) + wn;
#pragma unroll
    for (int mt = 0; mt < 2; ++mt) {
#pragma unroll
        for (int h = 0; h < 2; ++h) {
            const int s = row0 + wm * 32 + mt * 16 + (l >> 2) + h * 8;
            const uint32_t w = g_maskbits[(size_t)s * 64 + wbase];
            const int sh0 = 2 * (l & 3);
#pragma unroll
            for (int nt = 0; nt < 4; ++nt) {
                const uint32_t bits = w >> (nt * 8 + sh0);
                float e0 = (bits & 1u) ? ex2f(acc[mt][nt][h * 2 + 0] * LOG2E) : 0.f;
                float e1 = (bits & 2u) ? ex2f(acc[mt][nt][h * 2 + 1] * LOG2E) : 0.f;
                rs[mt][h] += e0 + e1;
            }
        }
    }
#pragma unroll
    for (int mt = 0; mt < 2; ++mt)
#pragma unroll
        for (int h = 0; h < 2; ++h) {
            float v = rs[mt][h];
            v += __shfl_xor_sync(~0u, v, 1);
            v += __shfl_xor_sync(~0u, v, 2);
            rs[mt][h] = v;
        }
    if ((l & 3) == 0) {
#pragma unroll
        for (int mt = 0; mt < 2; ++mt)
#pragma unroll
            for (int h = 0; h < 2; ++h)
                srow[wn * 128 + wm * 32 + mt * 16 + (l >> 2) + h * 8] = rs[mt][h];
    }
    __syncthreads();
    if (tid < 128) {
        float s = srow[tid] + srow[128 + tid];
        g_part[((size_t)(b * SEQ) + row0 + tid) * 32 + blockIdx.x] = s;
    }
}

// ===========================================================================
// pv (fused): per 64-row CTA, per 64-col k-tile:
//   QK mma -> frag epilogue (p = mask ? exp*inv : 0 -> attn + fp16 AP)
//   pair-barrier -> PV mma (out += p @ v-tile)
// ===========================================================================
__global__ void __launch_bounds__(256, 2) pv_mma_kernel(
    float* __restrict__ attn, float* __restrict__ out)
{
    extern __shared__ char smem[];
    constexpr int QT = 0, KT = 8192, VT = 24576, AP = 40960, SINV = 49152;
    const uint32_t sb = smem_u32(smem);
    const int tid = threadIdx.x, wid = tid >> 5, l = tid & 31;
    const int b = blockIdx.y, row0 = blockIdx.x * 64;

    float* sinv = (float*)(smem + SINV);
    if (tid < 64) {
        const float4* pp = (const float4*)(g_part + ((size_t)(b * SEQ) + row0 + tid) * 32);
        float s = 0.f;
#pragma unroll
        for (int i = 0; i < 8; ++i) {
            float4 t = pp[i];
            s += (t.x + t.y) + (t.z + t.w);
        }
        sinv[tid] = 1.0f / s;
    }

    const __half* qrow  = g_qh + ((size_t)(b * SEQ) + row0) * HD;
    const __half* kbase = g_kh + (size_t)b * SEQ * HD;
    const __half* vh    = g_vh + (size_t)(b * 64) * SEQ;
    float* arow = attn + ((size_t)(b * SEQ) + row0) * SEQ;

    // prologue: q tile + k/v tile 0
    {
#pragma unroll
        for (int i = 0; i < 2; ++i) {
            int chunk = tid + i * 256;
            int r = chunk >> 3, c = chunk & 7;
            CP_ASYNC16(sb + QT + r * 128 + ((c ^ (r & 7)) << 4),
                       qrow + (size_t)r * HD + c * 8);
        }
#pragma unroll
        for (int i = 0; i < 2; ++i) {
            int chunk = tid + i * 256;
            int r = chunk >> 3, c = chunk & 7;
            CP_ASYNC16(sb + KT + r * 128 + ((c ^ (r & 7)) << 4),
                       kbase + (size_t)r * HD + c * 8);
        }
#pragma unroll
        for (int i = 0; i < 2; ++i) {
            int chunk = tid + i * 256;
            int r = chunk >> 3, c = chunk & 7;
            CP_ASYNC16(sb + VT + r * 128 + ((c ^ (r & 7)) << 4),
                       vh + (size_t)r * SEQ + c * 8);
        }
        CP_COMMIT();
    }

    const int wm = wid >> 1, wn = wid & 1;             // 4 x 2 warps
    float oacc[4][4];
#pragma unroll
    for (int j = 0; j < 4; ++j)
#pragma unroll
        for (int k = 0; k < 4; ++k) oacc[j][k] = 0.f;

    const int rl0 = wm * 16 + (l >> 2);

    for (int tile = 0; tile < 32; ++tile) {
        const int t0 = tile * 64;
        const int buf = tile & 1;

        CP_WAIT(0);
        __syncthreads();                                // tiles ready

        if (tile < 31) {
            const int nt0 = t0 + 64;
            const int nbuf = buf ^ 1;
#pragma unroll
            for (int i = 0; i < 2; ++i) {
                int chunk = tid + i * 256;
                int r = chunk >> 3, c = chunk & 7;
                CP_ASYNC16(sb + KT + nbuf * 8192 + r * 128 + ((c ^ (r & 7)) << 4),
                           kbase + (size_t)(nt0 + r) * HD + c * 8);
            }
#pragma unroll
            for (int i = 0; i < 2; ++i) {
                int chunk = tid + i * 256;
                int r = chunk >> 3, c = chunk & 7;
                CP_ASYNC16(sb + VT + nbuf * 8192 + r * 128 + ((c ^ (r & 7)) << 4),
                           vh + (size_t)r * SEQ + nt0 + c * 8);
            }
            CP_COMMIT();
        }

        // ---- QK mma
        float sacc[4][4];
#pragma unroll
        for (int j = 0; j < 4; ++j)
#pragma unroll
            for (int k = 0; k < 4; ++k) sacc[j][k] = 0.f;

        const uint32_t Kc = sb + KT + buf * 8192;
#pragma unroll
        for (int ks = 0; ks < 4; ++ks) {
            uint32_t a[4];
            {
                int r = wm * 16 + (l & 15);
                int c = 2 * ks + (l >> 4);
                ldsm_x4(a[0], a[1], a[2], a[3],
                        sb + QT + r * 128 + ((c ^ (r & 7)) << 4));
            }
            uint32_t bh[4][2];
#pragma unroll
            for (int j = 0; j < 2; ++j) {
                int n = wn * 32 + j * 16 + (l & 7) + ((l >> 4) << 3);
                int c = 2 * ks + ((l >> 3) & 1);
                uint32_t t0r, t1r, t2r, t3r;
                ldsm_x4(t0r, t1r, t2r, t3r, Kc + n * 128 + ((c ^ (n & 7)) << 4));
                bh[j*2][0] = t0r; bh[j*2][1] = t1r; bh[j*2+1][0] = t2r; bh[j*2+1][1] = t3r;
            }
#pragma unroll
            for (int nt = 0; nt < 4; ++nt)
                mma16816h(sacc[nt], a, bh[nt]);
        }

        // ---- fragment epilogue
        const int sh0 = 2 * (l & 3);
#pragma unroll
        for (int h = 0; h < 2; ++h) {
            const int rl = rl0 + h * 8;
            const uint32_t w = g_maskbits[(size_t)(row0 + rl) * 64 + (t0 >> 5) + wn];
            const float inv = sinv[rl];
            float* gp = arow + (size_t)rl * SEQ + t0 + wn * 32 + sh0;
#pragma unroll
            for (int nt = 0; nt < 4; ++nt) {
                const uint32_t bits = w >> (nt * 8 + sh0);
                float p0 = (bits & 1u) ? ex2f(sacc[nt][h * 2 + 0] * LOG2E) * inv : 0.f;
                float p1 = (bits & 2u) ? ex2f(sacc[nt][h * 2 + 1] * LOG2E) * inv : 0.f;
                __stcs((float2*)(gp + nt * 8), make_float2(p0, p1));
                uint32_t chunk = (uint32_t)((4 * wn + nt) ^ (rl & 7));
                *(uint32_t*)(smem + AP + rl * 128 + chunk * 16 + 4 * (l & 3)) =
                    hpack(p0, p1);
            }
        }
        PAIR_BAR(1 + wm);                               // AP rows of this pair done

        // ---- PV mma
        const uint32_t Vc = sb + VT + buf * 8192;
#pragma unroll
        for (int ks = 0; ks < 4; ++ks) {
            uint32_t a[4];
            {
                int r = wm * 16 + (l & 15);
                int c = 2 * ks + (l >> 4);
                ldsm_x4(a[0], a[1], a[2], a[3],
                        sb + AP + r * 128 + ((c ^ (r & 7)) << 4));
            }
            uint32_t bh[4][2];
#pragma unroll
            for (int j = 0; j < 2; ++j) {
                int n = wn * 32 + j * 16 + (l & 7) + ((l >> 4) << 3);
                int c = 2 * ks + ((l >> 3) & 1);
                uint32_t t0r, t1r, t2r, t3r;
                ldsm_x4(t0r, t1r, t2r, t3r, Vc + n * 128 + ((c ^ (n & 7)) << 4));
                bh[j*2][0] = t0r; bh[j*2][1] = t1r; bh[j*2+1][0] = t2r; bh[j*2+1][1] = t3r;
            }
#pragma unroll
            for (int nt = 0; nt < 4; ++nt)
                mma16816h(oacc[nt], a, bh[nt]);
        }
    }

    // epilogue
#pragma unroll
    for (int nt = 0; nt < 4; ++nt) {
        const int gc = wn * 32 + nt * 8 + 2 * (l & 3);
#pragma unroll
        for (int h = 0; h < 2; ++h) {
            const int gr = row0 + wm * 16 + (l >> 2) + h * 8;
            *(float2*)(out + ((size_t)(b * SEQ) + gr) * HD + gc) =
                make_float2(oacc[nt][h * 2 + 0], oacc[nt][h * 2 + 1]);
        }
    }
}

// ===========================================================================
extern "C" void kernel_launch(void* const* d_in, const int* in_sizes, int n_in,
                              void* d_out, int out_size)
{
    const float* q    = (const float*)d_in[0];
    const float* k    = (const float*)d_in[1];
    const float* v    = (const float*)d_in[2];
    const int*   mask = (const int*)d_in[3];

    float* out  = (float*)d_out;
    float* attn = out + (size_t)BATCH * SEQ * HD;

    cudaFuncSetAttribute(scores_mma_kernel,
                         cudaFuncAttributeMaxDynamicSharedMemorySize, 24576);
    cudaFuncSetAttribute(pv_mma_kernel,
                         cudaFuncAttributeMaxDynamicSharedMemorySize, 49408);

    prep_kernel<<<dim3(512, 3), 256>>>((const float4*)q, (const float4*)k, v, mask);

    scores_mma_kernel<<<dim3(32, 16, BATCH), 256, 24576>>>();
    pv_mma_kernel<<<dim3(32, BATCH), 256, 49408>>>(attn, out);
}